// round 1
// baseline (speedup 1.0000x reference)
#include <cuda_runtime.h>
#include <cuda_bf16.h>
#include <math.h>

// Problem constants
#define BATCH 4
#define SEQ   2048
#define DMODEL 1024
#define NHEAD 16
#define DK    64
#define DFF   4096
#define NTOK  (BATCH * SEQ)   // 8192

// ---------------- scratch (static device globals; no allocation) -----------
__device__ float g_x2  [NTOK * DMODEL];   // normed activations (reused twice)
__device__ float g_q   [NTOK * DMODEL];   // [B,H,S,DK]
__device__ float g_k   [NTOK * DMODEL];
__device__ float g_v   [NTOK * DMODEL];
__device__ float g_attn[NTOK * DMODEL];   // attention output, [B,S,H*DK]
__device__ float g_xr  [NTOK * DMODEL];   // residual after attention
__device__ float g_ff  [NTOK * DFF];      // FF hidden

// ---------------------------------------------------------------------------
// Tensor1DNorm: mean over last dim, UNBIASED std (ddof=1), eps added to std.
// One block per row of 1024, 256 threads, float4 per thread.
// ---------------------------------------------------------------------------
__global__ void __launch_bounds__(256) norm_kernel(
    const float* __restrict__ x, const float* __restrict__ alpha,
    const float* __restrict__ beta, float* __restrict__ y)
{
    __shared__ float red[16];
    __shared__ float stats[2];
    int row = blockIdx.x;
    int t = threadIdx.x;
    const float4* xr = (const float4*)(x + (size_t)row * DMODEL);
    float4 v = xr[t];
    float s  = v.x + v.y + v.z + v.w;
    float sq = v.x*v.x + v.y*v.y + v.z*v.z + v.w*v.w;
#pragma unroll
    for (int o = 16; o > 0; o >>= 1) {
        s  += __shfl_down_sync(0xffffffffu, s,  o);
        sq += __shfl_down_sync(0xffffffffu, sq, o);
    }
    int warp = t >> 5;
    if ((t & 31) == 0) { red[warp] = s; red[warp + 8] = sq; }
    __syncthreads();
    if (t == 0) {
        float S = 0.f, SQ = 0.f;
#pragma unroll
        for (int w = 0; w < 8; w++) { S += red[w]; SQ += red[w + 8]; }
        float mean = S * (1.0f / DMODEL);
        float var = (SQ - S * mean) * (1.0f / (DMODEL - 1));
        var = fmaxf(var, 0.0f);
        float inv = 1.0f / (sqrtf(var) + 1e-6f);
        stats[0] = mean; stats[1] = inv;
    }
    __syncthreads();
    float mean = stats[0], inv = stats[1];
    const float4* ar = (const float4*)alpha;
    const float4* br = (const float4*)beta;
    float4 a = ar[t], b = br[t];
    float4 o;
    o.x = a.x * (v.x - mean) * inv + b.x;
    o.y = a.y * (v.y - mean) * inv + b.y;
    o.z = a.z * (v.z - mean) * inv + b.z;
    o.w = a.w * (v.w - mean) * inv + b.w;
    ((float4*)(y + (size_t)row * DMODEL))[t] = o;
}

// ---------------------------------------------------------------------------
// Register-tiled SGEMM: C[M,N] = A[M,K] @ W[K,N] + bias, epilogue variants.
// BM=BN=128, BK=8, 256 threads, 8x8 per thread (four 4x4 quadrant sub-tiles).
// EPI: 0 plain, 1 relu, 2 residual add, 3 store into [B,H,S,DK] (QKV)
// M % 128 == 0, N % 128 == 0, K % 8 == 0 guaranteed by problem shapes.
// ---------------------------------------------------------------------------
#define BM 128
#define BN 128
#define BKK 8

template<int EPI>
__global__ void __launch_bounds__(256) sgemm_kernel(
    const float* __restrict__ A, const float* __restrict__ W,
    const float* __restrict__ bias, const float* __restrict__ resid,
    float* __restrict__ C, int M, int N, int K)
{
    __shared__ float As[BKK][BM];
    __shared__ float Bs[BKK][BN];
    int tid = threadIdx.x;
    int m0 = blockIdx.y * BM;
    int n0 = blockIdx.x * BN;

    int arow = tid >> 1;            // 0..127
    int acol = (tid & 1) << 2;      // 0 or 4
    int brow = tid >> 5;            // 0..7
    int bcol = (tid & 31) << 2;     // 0..124

    const float* Aptr = A + (size_t)(m0 + arow) * K + acol;
    const float* Wptr = W + (size_t)brow * N + n0 + bcol;

    int ty = tid >> 4, tx = tid & 15;

    float acc[8][8];
#pragma unroll
    for (int i = 0; i < 8; i++)
#pragma unroll
        for (int j = 0; j < 8; j++) acc[i][j] = 0.f;

    for (int k0 = 0; k0 < K; k0 += BKK) {
        float4 av = *(const float4*)(Aptr + k0);
        As[acol + 0][arow] = av.x;
        As[acol + 1][arow] = av.y;
        As[acol + 2][arow] = av.z;
        As[acol + 3][arow] = av.w;
        float4 bv = *(const float4*)(Wptr + (size_t)k0 * N);
        *(float4*)&Bs[brow][bcol] = bv;
        __syncthreads();
#pragma unroll
        for (int k = 0; k < BKK; k++) {
            float af[8], bf[8];
#pragma unroll
            for (int i = 0; i < 4; i++) {
                af[i]     = As[k][ty * 4 + i];
                af[i + 4] = As[k][64 + ty * 4 + i];
            }
#pragma unroll
            for (int j = 0; j < 4; j++) {
                bf[j]     = Bs[k][tx * 4 + j];
                bf[j + 4] = Bs[k][64 + tx * 4 + j];
            }
#pragma unroll
            for (int i = 0; i < 8; i++)
#pragma unroll
                for (int j = 0; j < 8; j++)
                    acc[i][j] = fmaf(af[i], bf[j], acc[i][j]);
        }
        __syncthreads();
    }

#pragma unroll
    for (int i = 0; i < 8; i++) {
        int r = m0 + ((i < 4) ? (ty * 4 + i) : (64 + ty * 4 + i - 4));
#pragma unroll
        for (int j = 0; j < 8; j++) {
            int c = n0 + ((j < 4) ? (tx * 4 + j) : (64 + tx * 4 + j - 4));
            float v = acc[i][j] + bias[c];
            if (EPI == 1) v = fmaxf(v, 0.f);
            if (EPI == 2) v += resid[(size_t)r * N + c];
            if (EPI == 3) {
                int b = r >> 11, s = r & 2047;
                int h = c >> 6,  d = c & 63;
                C[((((size_t)b << 4) + h) * SEQ + s) * DK + d] = v;
            } else {
                C[(size_t)r * N + c] = v;
            }
        }
    }
}

// ---------------------------------------------------------------------------
// Flash attention, fp32. One block per (64-query tile, b*h). 256 threads
// (16x16); each thread owns 4 score rows x 4 cols / 4 output dims.
// smem: Qs[64][68], B1[64][68] (K^T then P), B2[64][68] (V).
// ---------------------------------------------------------------------------
#define AST 68
#define ATT_SMEM (3 * 64 * AST * (int)sizeof(float))

__global__ void __launch_bounds__(256) attn_kernel(
    const float* __restrict__ Q, const float* __restrict__ Kg,
    const float* __restrict__ Vg, const int* __restrict__ mask,
    float* __restrict__ Out)
{
    extern __shared__ float sm[];
    float* Qs = sm;
    float* B1 = sm + 64 * AST;
    float* B2 = sm + 128 * AST;

    int tid = threadIdx.x;
    int ty = tid >> 4, tx = tid & 15;
    int bh = blockIdx.y;
    int b = bh >> 4, h = bh & 15;
    int q0 = blockIdx.x * 64;

    const float* Qp = Q + ((size_t)bh * SEQ + q0) * DK;
    const float* Kp = Kg + (size_t)bh * SEQ * DK;
    const float* Vp = Vg + (size_t)bh * SEQ * DK;
    const int*   mp = mask + b * SEQ;

    // load Q tile (64x64), padded stride
#pragma unroll
    for (int r = 0; r < 4; r++) {
        int idx = tid + r * 256;
        int i = idx >> 4;
        int dq = (idx & 15) << 2;
        float4 v = *(const float4*)(Qp + i * DK + dq);
        *(float4*)(Qs + i * AST + dq) = v;
    }

    float m[4], l[4], acc[4][4];
#pragma unroll
    for (int i = 0; i < 4; i++) {
        m[i] = -INFINITY; l[i] = 0.f;
#pragma unroll
        for (int j = 0; j < 4; j++) acc[i][j] = 0.f;
    }
    __syncthreads();

    for (int k0 = 0; k0 < SEQ; k0 += 64) {
        // load K tile transposed: B1[d][j] = K[k0+j][d]
#pragma unroll
        for (int r = 0; r < 4; r++) {
            int idx = tid + r * 256;
            int j = idx >> 4;
            int dq = (idx & 15) << 2;
            float4 v = *(const float4*)(Kp + (size_t)(k0 + j) * DK + dq);
            B1[(dq + 0) * AST + j] = v.x;
            B1[(dq + 1) * AST + j] = v.y;
            B1[(dq + 2) * AST + j] = v.z;
            B1[(dq + 3) * AST + j] = v.w;
        }
        __syncthreads();

        // scores S = Q @ K^T
        float s[4][4];
#pragma unroll
        for (int i = 0; i < 4; i++)
#pragma unroll
            for (int j = 0; j < 4; j++) s[i][j] = 0.f;
#pragma unroll 8
        for (int d = 0; d < 64; d++) {
            float a[4], bb[4];
#pragma unroll
            for (int i = 0; i < 4; i++) a[i] = Qs[(ty * 4 + i) * AST + d];
#pragma unroll
            for (int j = 0; j < 4; j++) bb[j] = B1[d * AST + tx * 4 + j];
#pragma unroll
            for (int i = 0; i < 4; i++)
#pragma unroll
                for (int j = 0; j < 4; j++)
                    s[i][j] = fmaf(a[i], bb[j], s[i][j]);
        }
        // scale + mask
#pragma unroll
        for (int j = 0; j < 4; j++) {
            int mv = mp[k0 + tx * 4 + j];
#pragma unroll
            for (int i = 0; i < 4; i++) {
                float v = s[i][j] * 0.125f;      // 1/sqrt(64)
                s[i][j] = (mv == 0) ? -1e9f : v;
            }
        }
        __syncthreads();   // everyone done reading K^T (B1)

        // online softmax (row groups = 16 lanes sharing ty)
#pragma unroll
        for (int i = 0; i < 4; i++) {
            float tm = fmaxf(fmaxf(s[i][0], s[i][1]), fmaxf(s[i][2], s[i][3]));
#pragma unroll
            for (int o = 8; o > 0; o >>= 1)
                tm = fmaxf(tm, __shfl_xor_sync(0xffffffffu, tm, o, 16));
            float mn = fmaxf(m[i], tm);
            float corr = __expf(m[i] - mn);
            float ps = 0.f;
#pragma unroll
            for (int j = 0; j < 4; j++) {
                float p = __expf(s[i][j] - mn);
                s[i][j] = p;
                ps += p;
            }
#pragma unroll
            for (int o = 8; o > 0; o >>= 1)
                ps += __shfl_xor_sync(0xffffffffu, ps, o, 16);
            l[i] = l[i] * corr + ps;
            m[i] = mn;
#pragma unroll
            for (int j = 0; j < 4; j++) acc[i][j] *= corr;
        }

        // write P into B1, load V tile into B2
#pragma unroll
        for (int i = 0; i < 4; i++)
#pragma unroll
            for (int j = 0; j < 4; j++)
                B1[(ty * 4 + i) * AST + tx * 4 + j] = s[i][j];
#pragma unroll
        for (int r = 0; r < 4; r++) {
            int idx = tid + r * 256;
            int j = idx >> 4;
            int dq = (idx & 15) << 2;
            *(float4*)(B2 + j * AST + dq) =
                *(const float4*)(Vp + (size_t)(k0 + j) * DK + dq);
        }
        __syncthreads();

        // acc += P @ V
#pragma unroll 8
        for (int j = 0; j < 64; j++) {
            float p[4], v[4];
#pragma unroll
            for (int i = 0; i < 4; i++) p[i] = B1[(ty * 4 + i) * AST + j];
#pragma unroll
            for (int c = 0; c < 4; c++) v[c] = B2[j * AST + tx * 4 + c];
#pragma unroll
            for (int i = 0; i < 4; i++)
#pragma unroll
                for (int c = 0; c < 4; c++)
                    acc[i][c] = fmaf(p[i], v[c], acc[i][c]);
        }
        __syncthreads();
    }

    // write output into [B,S,H*DK] layout for the O-projection GEMM
#pragma unroll
    for (int i = 0; i < 4; i++) {
        float invl = 1.0f / l[i];
        int rowg = b * SEQ + q0 + ty * 4 + i;
#pragma unroll
        for (int c = 0; c < 4; c++)
            Out[(size_t)rowg * DMODEL + h * DK + tx * 4 + c] = acc[i][c] * invl;
    }
}

// ---------------------------------------------------------------------------
extern "C" void kernel_launch(void* const* d_in, const int* in_sizes, int n_in,
                              void* d_out, int out_size)
{
    const float* x      = (const float*)d_in[0];
    const int*   mask   = (const int*)  d_in[1];
    const float* wq     = (const float*)d_in[2];
    const float* bq     = (const float*)d_in[3];
    const float* wk     = (const float*)d_in[4];
    const float* bk     = (const float*)d_in[5];
    const float* wv     = (const float*)d_in[6];
    const float* bv     = (const float*)d_in[7];
    const float* wo     = (const float*)d_in[8];
    const float* bo     = (const float*)d_in[9];
    const float* w1     = (const float*)d_in[10];
    const float* b1     = (const float*)d_in[11];
    const float* w2     = (const float*)d_in[12];
    const float* b2     = (const float*)d_in[13];
    const float* alpha1 = (const float*)d_in[14];
    const float* bias1  = (const float*)d_in[15];
    const float* alpha2 = (const float*)d_in[16];
    const float* bias2  = (const float*)d_in[17];
    float* out = (float*)d_out;

    float *px2, *pq, *pk, *pv, *pattn, *pxr, *pff;
    cudaGetSymbolAddress((void**)&px2,   g_x2);
    cudaGetSymbolAddress((void**)&pq,    g_q);
    cudaGetSymbolAddress((void**)&pk,    g_k);
    cudaGetSymbolAddress((void**)&pv,    g_v);
    cudaGetSymbolAddress((void**)&pattn, g_attn);
    cudaGetSymbolAddress((void**)&pxr,   g_xr);
    cudaGetSymbolAddress((void**)&pff,   g_ff);

    cudaFuncSetAttribute(attn_kernel,
                         cudaFuncAttributeMaxDynamicSharedMemorySize, ATT_SMEM);

    dim3 gD(DMODEL / BN, NTOK / BM);   // (8, 64)
    dim3 gF(DFF / BN,    NTOK / BM);   // (32, 64)

    // 1) pre-norm 1
    norm_kernel<<<NTOK, 256>>>(x, alpha1, bias1, px2);
    // 2) QKV projections (transpose-store into [B,H,S,DK])
    sgemm_kernel<3><<<gD, 256>>>(px2, wq, bq, nullptr, pq, NTOK, DMODEL, DMODEL);
    sgemm_kernel<3><<<gD, 256>>>(px2, wk, bk, nullptr, pk, NTOK, DMODEL, DMODEL);
    sgemm_kernel<3><<<gD, 256>>>(px2, wv, bv, nullptr, pv, NTOK, DMODEL, DMODEL);
    // 3) attention
    attn_kernel<<<dim3(SEQ / 64, BATCH * NHEAD), 256, ATT_SMEM>>>(
        pq, pk, pv, mask, pattn);
    // 4) output projection + residual
    sgemm_kernel<2><<<gD, 256>>>(pattn, wo, bo, x, pxr, NTOK, DMODEL, DMODEL);
    // 5) pre-norm 2
    norm_kernel<<<NTOK, 256>>>(pxr, alpha2, bias2, px2);
    // 6) FF1 + ReLU
    sgemm_kernel<1><<<gF, 256>>>(px2, w1, b1, nullptr, pff, NTOK, DFF, DMODEL);
    // 7) FF2 + residual -> output
    sgemm_kernel<2><<<gD, 256>>>(pff, w2, b2, pxr, out, NTOK, DMODEL, DFF);
}

// round 3
// speedup vs baseline: 1.7072x; 1.7072x over previous
#include <cuda_runtime.h>
#include <cuda_bf16.h>
#include <math.h>
#include <stdint.h>

// Problem constants
#define BATCH 4
#define SEQ   2048
#define DMODEL 1024
#define NHEAD 16
#define DK    64
#define DFF   4096
#define NTOK  (BATCH * SEQ)   // 8192

// ---------------- scratch (static device globals; no allocation) -----------
__device__ __nv_bfloat16 g_x2h [NTOK * DMODEL];
__device__ __nv_bfloat16 g_x2l [NTOK * DMODEL];
__device__ float         g_q   [NTOK * DMODEL];   // [B,H,S,DK]
__device__ float         g_k   [NTOK * DMODEL];
__device__ float         g_v   [NTOK * DMODEL];
__device__ __nv_bfloat16 g_ath [NTOK * DMODEL];   // attn out split, [B,S,H*DK]
__device__ __nv_bfloat16 g_atl [NTOK * DMODEL];
__device__ float         g_xr  [NTOK * DMODEL];   // residual after attention
__device__ __nv_bfloat16 g_ffh [NTOK * DFF];
__device__ __nv_bfloat16 g_ffl [NTOK * DFF];
// transposed split weights, [N, K] layout
__device__ __nv_bfloat16 g_wqh[DMODEL*DMODEL], g_wql[DMODEL*DMODEL];
__device__ __nv_bfloat16 g_wkh[DMODEL*DMODEL], g_wkl[DMODEL*DMODEL];
__device__ __nv_bfloat16 g_wvh[DMODEL*DMODEL], g_wvl[DMODEL*DMODEL];
__device__ __nv_bfloat16 g_woh[DMODEL*DMODEL], g_wol[DMODEL*DMODEL];
__device__ __nv_bfloat16 g_w1h[DMODEL*DFF],    g_w1l[DMODEL*DFF];
__device__ __nv_bfloat16 g_w2h[DFF*DMODEL],    g_w2l[DFF*DMODEL];

// ============================ PTX helpers (sm_80-level only) ================
__device__ __forceinline__ uint32_t s2u(const void* p) {
    uint32_t a;
    asm("{ .reg .u64 t; cvta.to.shared.u64 t, %1; cvt.u32.u64 %0, t; }"
        : "=r"(a) : "l"(p));
    return a;
}
__device__ __forceinline__ void cpa16(uint32_t s, const void* g) {
    asm volatile("cp.async.cg.shared.global [%0], [%1], 16;"
                 :: "r"(s), "l"(g) : "memory");
}
__device__ __forceinline__ void cp_commit() {
    asm volatile("cp.async.commit_group;" ::: "memory");
}
template<int N>
__device__ __forceinline__ void cp_wait() {
    asm volatile("cp.async.wait_group %0;" :: "n"(N) : "memory");
}
__device__ __forceinline__ void ldm4(uint32_t* r, uint32_t addr) {
    asm volatile("ldmatrix.sync.aligned.m8n8.x4.shared.b16 {%0,%1,%2,%3}, [%4];"
        : "=r"(r[0]), "=r"(r[1]), "=r"(r[2]), "=r"(r[3]) : "r"(addr));
}
__device__ __forceinline__ void mma16816(float* c, const uint32_t* a,
                                         uint32_t b0, uint32_t b1) {
    asm volatile(
        "mma.sync.aligned.m16n8k16.row.col.f32.bf16.bf16.f32 "
        "{%0,%1,%2,%3}, {%4,%5,%6,%7}, {%8,%9}, {%0,%1,%2,%3};"
        : "+f"(c[0]), "+f"(c[1]), "+f"(c[2]), "+f"(c[3])
        : "r"(a[0]), "r"(a[1]), "r"(a[2]), "r"(a[3]), "r"(b0), "r"(b1));
}

// ---------------------------------------------------------------------------
// Tensor1DNorm -> split-bf16 output (hi/lo).
// ---------------------------------------------------------------------------
__global__ void __launch_bounds__(256) norm_split_kernel(
    const float* __restrict__ x, const float* __restrict__ alpha,
    const float* __restrict__ beta,
    __nv_bfloat16* __restrict__ yh, __nv_bfloat16* __restrict__ yl)
{
    __shared__ float red[16];
    __shared__ float stats[2];
    int row = blockIdx.x;
    int t = threadIdx.x;
    const float4* xr = (const float4*)(x + (size_t)row * DMODEL);
    float4 v = xr[t];
    float s  = v.x + v.y + v.z + v.w;
    float sq = v.x*v.x + v.y*v.y + v.z*v.z + v.w*v.w;
#pragma unroll
    for (int o = 16; o > 0; o >>= 1) {
        s  += __shfl_down_sync(0xffffffffu, s,  o);
        sq += __shfl_down_sync(0xffffffffu, sq, o);
    }
    int warp = t >> 5;
    if ((t & 31) == 0) { red[warp] = s; red[warp + 8] = sq; }
    __syncthreads();
    if (t == 0) {
        float S = 0.f, SQ = 0.f;
#pragma unroll
        for (int w = 0; w < 8; w++) { S += red[w]; SQ += red[w + 8]; }
        float mean = S * (1.0f / DMODEL);
        float var = (SQ - S * mean) * (1.0f / (DMODEL - 1));
        var = fmaxf(var, 0.0f);
        stats[0] = mean; stats[1] = 1.0f / (sqrtf(var) + 1e-6f);
    }
    __syncthreads();
    float mean = stats[0], inv = stats[1];
    float4 a = ((const float4*)alpha)[t];
    float4 b = ((const float4*)beta)[t];
    float o[4];
    o[0] = a.x * (v.x - mean) * inv + b.x;
    o[1] = a.y * (v.y - mean) * inv + b.y;
    o[2] = a.z * (v.z - mean) * inv + b.z;
    o[3] = a.w * (v.w - mean) * inv + b.w;
    __nv_bfloat162 h2[2], l2[2];
#pragma unroll
    for (int q = 0; q < 2; q++) {
        __nv_bfloat16 h0 = __float2bfloat16(o[q*2]);
        __nv_bfloat16 h1 = __float2bfloat16(o[q*2+1]);
        h2[q].x = h0; h2[q].y = h1;
        l2[q].x = __float2bfloat16(o[q*2]   - __bfloat162float(h0));
        l2[q].y = __float2bfloat16(o[q*2+1] - __bfloat162float(h1));
    }
    __nv_bfloat162* ph = (__nv_bfloat162*)(yh + (size_t)row * DMODEL);
    __nv_bfloat162* pl = (__nv_bfloat162*)(yl + (size_t)row * DMODEL);
    ph[t*2] = h2[0]; ph[t*2+1] = h2[1];
    pl[t*2] = l2[0]; pl[t*2+1] = l2[1];
}

// ---------------------------------------------------------------------------
// Weight transpose + split: W[K,N] fp32 -> Wt_hi/lo [N,K] bf16. 32x32 tiles.
// ---------------------------------------------------------------------------
__global__ void __launch_bounds__(256) convw_kernel(
    const float* __restrict__ W,
    __nv_bfloat16* __restrict__ hi, __nv_bfloat16* __restrict__ lo,
    int K, int N)
{
    __shared__ float t[32][33];
    int tx = threadIdx.x, ty = threadIdx.y;
    int n0 = blockIdx.x * 32, k0 = blockIdx.y * 32;
#pragma unroll
    for (int i = 0; i < 4; i++)
        t[ty + 8*i][tx] = W[(size_t)(k0 + ty + 8*i) * N + n0 + tx];
    __syncthreads();
#pragma unroll
    for (int i = 0; i < 4; i++) {
        float v = t[tx][ty + 8*i];
        __nv_bfloat16 h = __float2bfloat16(v);
        size_t idx = (size_t)(n0 + ty + 8*i) * K + k0 + tx;
        hi[idx] = h;
        lo[idx] = __float2bfloat16(v - __bfloat162float(h));
    }
}

// ---------------------------------------------------------------------------
// Split-bf16 HMMA GEMM (mma.sync m16n8k16). CTA tile 128x128x64, 256 threads,
// 8 warps (2M x 4N), warp tile 64x32. Double-buffered cp.async staging with
// SW128 swizzle (conflict-free ldmatrix).
// D[M,N] = (Ah+Al)[M,K] @ (Bh+Bl)[N,K]^T  via 3 mma products, fp32 accum.
// EPI: 0 = +bias, store fp32 [B,H,S,DK] (QKV)
//      1 = +bias, relu, store split bf16 (FF1)
//      2 = +bias +resid, store fp32 (O-proj / FF2)
// ---------------------------------------------------------------------------
#define GBM 128
#define GBN 128
#define GBK 64
#define OFF_AH 0
#define OFF_AL 16384
#define OFF_BH 32768
#define OFF_BL 49152
#define STAGE_B 65536
#define GEMM_SMEM (2 * STAGE_B)

__device__ __forceinline__ void load_stage64(
    uint32_t sb, const __nv_bfloat16* Ah, const __nv_bfloat16* Al,
    const __nv_bfloat16* Bh, const __nv_bfloat16* Bl,
    int m0, int n0, int k0, int K, int tid)
{
#pragma unroll
    for (int r = 0; r < 4; r++) {
        int ci = tid + r * 256;            // 0..1023
        int row = ci >> 3, ch = ci & 7;
        uint32_t sw = (uint32_t)(row * 128 + ((ch ^ (row & 7)) << 4));
        size_t goA = (size_t)(m0 + row) * K + k0 + ch * 8;
        size_t goB = (size_t)(n0 + row) * K + k0 + ch * 8;
        cpa16(sb + OFF_AH + sw, Ah + goA);
        cpa16(sb + OFF_AL + sw, Al + goA);
        cpa16(sb + OFF_BH + sw, Bh + goB);
        cpa16(sb + OFF_BL + sw, Bl + goB);
    }
}

template<int EPI>
__global__ void __launch_bounds__(256)
mma_gemm(const __nv_bfloat16* __restrict__ Ah, const __nv_bfloat16* __restrict__ Al,
         const __nv_bfloat16* __restrict__ Bh, const __nv_bfloat16* __restrict__ Bl,
         const float* __restrict__ bias, const float* __restrict__ resid,
         float* __restrict__ C,
         __nv_bfloat16* __restrict__ Ch, __nv_bfloat16* __restrict__ Cl,
         int M, int N, int K)
{
    extern __shared__ __align__(1024) char dsm[];
    uint32_t dyn = s2u(dsm);

    int tid = threadIdx.x;
    int wid = tid >> 5, lane = tid & 31;
    int wm = wid & 1, wn = wid >> 1;      // 2 x 4 warp grid
    int m0 = blockIdx.y * GBM, n0 = blockIdx.x * GBN;

    float c[4][4][4];
#pragma unroll
    for (int i = 0; i < 4; i++)
#pragma unroll
        for (int j = 0; j < 4; j++)
#pragma unroll
            for (int q = 0; q < 4; q++) c[i][j][q] = 0.f;

    // per-thread ldmatrix row bases
    int aRow0 = wm * 64 + (lane & 7) + ((lane >> 3) & 1) * 8;
    int bRow0 = wn * 32 + (lane & 7) + ((lane >> 3) & 1) * 8;
    int cgrp = lane >> 4;                 // 0/1 -> k-chunk select

    int nsteps = K / GBK;
    load_stage64(dyn, Ah, Al, Bh, Bl, m0, n0, 0, K, tid);
    cp_commit();

    for (int step = 0; step < nsteps; step++) {
        uint32_t sb = dyn + (uint32_t)(step & 1) * STAGE_B;
        if (step + 1 < nsteps) {
            load_stage64(dyn + (uint32_t)((step + 1) & 1) * STAGE_B,
                         Ah, Al, Bh, Bl, m0, n0, (step + 1) * GBK, K, tid);
            cp_commit();
            cp_wait<1>();
        } else {
            cp_wait<0>();
        }
        __syncthreads();

#pragma unroll
        for (int s = 0; s < 4; s++) {
            int ch = 2 * s + cgrp;
            uint32_t ah[4][4], al[4][4];
#pragma unroll
            for (int i = 0; i < 4; i++) {
                int row = aRow0 + i * 16;
                uint32_t ad = sb + OFF_AH + row * 128 + ((ch ^ (row & 7)) << 4);
                ldm4(ah[i], ad);
                ldm4(al[i], ad + (OFF_AL - OFF_AH));
            }
            uint32_t bh[2][4], bl[2][4];
#pragma unroll
            for (int g = 0; g < 2; g++) {
                int row = bRow0 + g * 16;
                uint32_t bd = sb + OFF_BH + row * 128 + ((ch ^ (row & 7)) << 4);
                ldm4(bh[g], bd);
                ldm4(bl[g], bd + (OFF_BL - OFF_BH));
            }
#pragma unroll
            for (int i = 0; i < 4; i++) {
#pragma unroll
                for (int j = 0; j < 4; j++) {
                    int g = j >> 1, o = j & 1;
                    mma16816(c[i][j], ah[i], bh[g][o], bh[g][o + 2]);
                    mma16816(c[i][j], ah[i], bl[g][o], bl[g][o + 2]);
                    mma16816(c[i][j], al[i], bh[g][o], bh[g][o + 2]);
                }
            }
        }
        __syncthreads();
    }

    // ----------------- epilogue -----------------
    int rbase = m0 + wm * 64 + (lane >> 2);
    int cbase = n0 + wn * 32 + (lane & 3) * 2;
#pragma unroll
    for (int i = 0; i < 4; i++) {
#pragma unroll
        for (int j = 0; j < 4; j++) {
            int col = cbase + j * 8;
            float bs0 = bias[col], bs1 = bias[col + 1];
#pragma unroll
            for (int half = 0; half < 2; half++) {
                int r = rbase + i * 16 + half * 8;
                float v0 = c[i][j][half * 2]     + bs0;
                float v1 = c[i][j][half * 2 + 1] + bs1;
                if (EPI == 0) {
                    int b = r >> 11, sx = r & 2047;
                    int h = col >> 6, d = col & 63;
                    float2 o; o.x = v0; o.y = v1;
                    *(float2*)(C + ((((size_t)b * NHEAD + h) * SEQ + sx) * DK + d)) = o;
                } else if (EPI == 1) {
                    v0 = fmaxf(v0, 0.f);
                    v1 = fmaxf(v1, 0.f);
                    __nv_bfloat16 h0 = __float2bfloat16(v0);
                    __nv_bfloat16 h1 = __float2bfloat16(v1);
                    __nv_bfloat162 hv; hv.x = h0; hv.y = h1;
                    __nv_bfloat162 lv;
                    lv.x = __float2bfloat16(v0 - __bfloat162float(h0));
                    lv.y = __float2bfloat16(v1 - __bfloat162float(h1));
                    *(__nv_bfloat162*)(Ch + (size_t)r * N + col) = hv;
                    *(__nv_bfloat162*)(Cl + (size_t)r * N + col) = lv;
                } else {
                    float2 rr = *(const float2*)(resid + (size_t)r * N + col);
                    float2 o; o.x = v0 + rr.x; o.y = v1 + rr.y;
                    *(float2*)(C + (size_t)r * N + col) = o;
                }
            }
        }
    }
}

// ---------------------------------------------------------------------------
// Flash attention, fp32 FFMA; outputs split bf16 for the O-proj GEMM.
// ---------------------------------------------------------------------------
#define AST 68
#define ATT_SMEM (3 * 64 * AST * (int)sizeof(float))

__global__ void __launch_bounds__(256) attn_kernel(
    const float* __restrict__ Q, const float* __restrict__ Kg,
    const float* __restrict__ Vg, const int* __restrict__ mask,
    __nv_bfloat16* __restrict__ Oh, __nv_bfloat16* __restrict__ Ol)
{
    extern __shared__ float sm[];
    float* Qs = sm;
    float* B1 = sm + 64 * AST;
    float* B2 = sm + 128 * AST;

    int tid = threadIdx.x;
    int ty = tid >> 4, tx = tid & 15;
    int bh = blockIdx.y;
    int b = bh >> 4, hh = bh & 15;
    int q0 = blockIdx.x * 64;

    const float* Qp = Q + ((size_t)bh * SEQ + q0) * DK;
    const float* Kp = Kg + (size_t)bh * SEQ * DK;
    const float* Vp = Vg + (size_t)bh * SEQ * DK;
    const int*   mp = mask + b * SEQ;

#pragma unroll
    for (int r = 0; r < 4; r++) {
        int idx = tid + r * 256;
        int i = idx >> 4;
        int dq = (idx & 15) << 2;
        *(float4*)(Qs + i * AST + dq) = *(const float4*)(Qp + i * DK + dq);
    }

    float m[4], l[4], acc[4][4];
#pragma unroll
    for (int i = 0; i < 4; i++) {
        m[i] = -INFINITY; l[i] = 0.f;
#pragma unroll
        for (int j = 0; j < 4; j++) acc[i][j] = 0.f;
    }
    __syncthreads();

    for (int k0 = 0; k0 < SEQ; k0 += 64) {
#pragma unroll
        for (int r = 0; r < 4; r++) {
            int idx = tid + r * 256;
            int j = idx >> 4;
            int dq = (idx & 15) << 2;
            float4 v = *(const float4*)(Kp + (size_t)(k0 + j) * DK + dq);
            B1[(dq + 0) * AST + j] = v.x;
            B1[(dq + 1) * AST + j] = v.y;
            B1[(dq + 2) * AST + j] = v.z;
            B1[(dq + 3) * AST + j] = v.w;
        }
        __syncthreads();

        float s[4][4];
#pragma unroll
        for (int i = 0; i < 4; i++)
#pragma unroll
            for (int j = 0; j < 4; j++) s[i][j] = 0.f;
#pragma unroll 8
        for (int d = 0; d < 64; d++) {
            float a[4], bb[4];
#pragma unroll
            for (int i = 0; i < 4; i++) a[i] = Qs[(ty * 4 + i) * AST + d];
#pragma unroll
            for (int j = 0; j < 4; j++) bb[j] = B1[d * AST + tx * 4 + j];
#pragma unroll
            for (int i = 0; i < 4; i++)
#pragma unroll
                for (int j = 0; j < 4; j++)
                    s[i][j] = fmaf(a[i], bb[j], s[i][j]);
        }
#pragma unroll
        for (int j = 0; j < 4; j++) {
            int mv = mp[k0 + tx * 4 + j];
#pragma unroll
            for (int i = 0; i < 4; i++) {
                float v = s[i][j] * 0.125f;
                s[i][j] = (mv == 0) ? -1e9f : v;
            }
        }
        __syncthreads();

#pragma unroll
        for (int i = 0; i < 4; i++) {
            float tm = fmaxf(fmaxf(s[i][0], s[i][1]), fmaxf(s[i][2], s[i][3]));
#pragma unroll
            for (int o = 8; o > 0; o >>= 1)
                tm = fmaxf(tm, __shfl_xor_sync(0xffffffffu, tm, o, 16));
            float mn = fmaxf(m[i], tm);
            float corr = __expf(m[i] - mn);
            float ps = 0.f;
#pragma unroll
            for (int j = 0; j < 4; j++) {
                float p = __expf(s[i][j] - mn);
                s[i][j] = p;
                ps += p;
            }
#pragma unroll
            for (int o = 8; o > 0; o >>= 1)
                ps += __shfl_xor_sync(0xffffffffu, ps, o, 16);
            l[i] = l[i] * corr + ps;
            m[i] = mn;
#pragma unroll
            for (int j = 0; j < 4; j++) acc[i][j] *= corr;
        }

#pragma unroll
        for (int i = 0; i < 4; i++)
#pragma unroll
            for (int j = 0; j < 4; j++)
                B1[(ty * 4 + i) * AST + tx * 4 + j] = s[i][j];
#pragma unroll
        for (int r = 0; r < 4; r++) {
            int idx = tid + r * 256;
            int j = idx >> 4;
            int dq = (idx & 15) << 2;
            *(float4*)(B2 + j * AST + dq) =
                *(const float4*)(Vp + (size_t)(k0 + j) * DK + dq);
        }
        __syncthreads();

#pragma unroll 8
        for (int j = 0; j < 64; j++) {
            float p[4], v[4];
#pragma unroll
            for (int i = 0; i < 4; i++) p[i] = B1[(ty * 4 + i) * AST + j];
#pragma unroll
            for (int cc = 0; cc < 4; cc++) v[cc] = B2[j * AST + tx * 4 + cc];
#pragma unroll
            for (int i = 0; i < 4; i++)
#pragma unroll
                for (int cc = 0; cc < 4; cc++)
                    acc[i][cc] = fmaf(p[i], v[cc], acc[i][cc]);
        }
        __syncthreads();
    }

#pragma unroll
    for (int i = 0; i < 4; i++) {
        float invl = 1.0f / l[i];
        size_t rowg = (size_t)b * SEQ + q0 + ty * 4 + i;
        size_t base = rowg * DMODEL + hh * DK + tx * 4;
        __nv_bfloat162 h2[2], l2[2];
#pragma unroll
        for (int q = 0; q < 2; q++) {
            float v0 = acc[i][q*2]   * invl;
            float v1 = acc[i][q*2+1] * invl;
            __nv_bfloat16 h0 = __float2bfloat16(v0);
            __nv_bfloat16 h1 = __float2bfloat16(v1);
            h2[q].x = h0; h2[q].y = h1;
            l2[q].x = __float2bfloat16(v0 - __bfloat162float(h0));
            l2[q].y = __float2bfloat16(v1 - __bfloat162float(h1));
        }
        *(__nv_bfloat162*)(Oh + base)     = h2[0];
        *(__nv_bfloat162*)(Oh + base + 2) = h2[1];
        *(__nv_bfloat162*)(Ol + base)     = l2[0];
        *(__nv_bfloat162*)(Ol + base + 2) = l2[1];
    }
}

// ---------------------------------------------------------------------------
extern "C" void kernel_launch(void* const* d_in, const int* in_sizes, int n_in,
                              void* d_out, int out_size)
{
    const float* x      = (const float*)d_in[0];
    const int*   mask   = (const int*)  d_in[1];
    const float* wq     = (const float*)d_in[2];
    const float* bq     = (const float*)d_in[3];
    const float* wk     = (const float*)d_in[4];
    const float* bk     = (const float*)d_in[5];
    const float* wv     = (const float*)d_in[6];
    const float* bv     = (const float*)d_in[7];
    const float* wo     = (const float*)d_in[8];
    const float* bo     = (const float*)d_in[9];
    const float* w1     = (const float*)d_in[10];
    const float* b1     = (const float*)d_in[11];
    const float* w2     = (const float*)d_in[12];
    const float* b2     = (const float*)d_in[13];
    const float* alpha1 = (const float*)d_in[14];
    const float* bias1  = (const float*)d_in[15];
    const float* alpha2 = (const float*)d_in[16];
    const float* bias2  = (const float*)d_in[17];
    float* out = (float*)d_out;

    __nv_bfloat16 *x2h, *x2l, *ath, *atl, *ffh, *ffl;
    __nv_bfloat16 *wqh, *wql, *wkh, *wkl, *wvh, *wvl, *woh, *wol, *w1h, *w1l, *w2h, *w2l;
    float *pq, *pk, *pv, *pxr;
    cudaGetSymbolAddress((void**)&x2h, g_x2h);  cudaGetSymbolAddress((void**)&x2l, g_x2l);
    cudaGetSymbolAddress((void**)&ath, g_ath);  cudaGetSymbolAddress((void**)&atl, g_atl);
    cudaGetSymbolAddress((void**)&ffh, g_ffh);  cudaGetSymbolAddress((void**)&ffl, g_ffl);
    cudaGetSymbolAddress((void**)&wqh, g_wqh);  cudaGetSymbolAddress((void**)&wql, g_wql);
    cudaGetSymbolAddress((void**)&wkh, g_wkh);  cudaGetSymbolAddress((void**)&wkl, g_wkl);
    cudaGetSymbolAddress((void**)&wvh, g_wvh);  cudaGetSymbolAddress((void**)&wvl, g_wvl);
    cudaGetSymbolAddress((void**)&woh, g_woh);  cudaGetSymbolAddress((void**)&wol, g_wol);
    cudaGetSymbolAddress((void**)&w1h, g_w1h);  cudaGetSymbolAddress((void**)&w1l, g_w1l);
    cudaGetSymbolAddress((void**)&w2h, g_w2h);  cudaGetSymbolAddress((void**)&w2l, g_w2l);
    cudaGetSymbolAddress((void**)&pq, g_q);     cudaGetSymbolAddress((void**)&pk, g_k);
    cudaGetSymbolAddress((void**)&pv, g_v);     cudaGetSymbolAddress((void**)&pxr, g_xr);

    cudaFuncSetAttribute(attn_kernel,
                         cudaFuncAttributeMaxDynamicSharedMemorySize, ATT_SMEM);
    cudaFuncSetAttribute(mma_gemm<0>,
                         cudaFuncAttributeMaxDynamicSharedMemorySize, GEMM_SMEM);
    cudaFuncSetAttribute(mma_gemm<1>,
                         cudaFuncAttributeMaxDynamicSharedMemorySize, GEMM_SMEM);
    cudaFuncSetAttribute(mma_gemm<2>,
                         cudaFuncAttributeMaxDynamicSharedMemorySize, GEMM_SMEM);

    dim3 cb(32, 8);
    // weight transpose + split (runs every launch; same output every time)
    convw_kernel<<<dim3(DMODEL/32, DMODEL/32), cb>>>(wq, wqh, wql, DMODEL, DMODEL);
    convw_kernel<<<dim3(DMODEL/32, DMODEL/32), cb>>>(wk, wkh, wkl, DMODEL, DMODEL);
    convw_kernel<<<dim3(DMODEL/32, DMODEL/32), cb>>>(wv, wvh, wvl, DMODEL, DMODEL);
    convw_kernel<<<dim3(DMODEL/32, DMODEL/32), cb>>>(wo, woh, wol, DMODEL, DMODEL);
    convw_kernel<<<dim3(DFF/32,    DMODEL/32), cb>>>(w1, w1h, w1l, DMODEL, DFF);
    convw_kernel<<<dim3(DMODEL/32, DFF/32),    cb>>>(w2, w2h, w2l, DFF, DMODEL);

    dim3 gD(DMODEL / GBN, NTOK / GBM);   // (8, 64)
    dim3 gF(DFF / GBN,    NTOK / GBM);   // (32, 64)

    // 1) pre-norm 1 -> split bf16
    norm_split_kernel<<<NTOK, 256>>>(x, alpha1, bias1, x2h, x2l);
    // 2) QKV projections (HMMA), store fp32 [B,H,S,DK]
    mma_gemm<0><<<gD, 256, GEMM_SMEM>>>(x2h, x2l, wqh, wql, bq, nullptr,
                                        pq, nullptr, nullptr, NTOK, DMODEL, DMODEL);
    mma_gemm<0><<<gD, 256, GEMM_SMEM>>>(x2h, x2l, wkh, wkl, bk, nullptr,
                                        pk, nullptr, nullptr, NTOK, DMODEL, DMODEL);
    mma_gemm<0><<<gD, 256, GEMM_SMEM>>>(x2h, x2l, wvh, wvl, bv, nullptr,
                                        pv, nullptr, nullptr, NTOK, DMODEL, DMODEL);
    // 3) attention -> split bf16
    attn_kernel<<<dim3(SEQ / 64, BATCH * NHEAD), 256, ATT_SMEM>>>(
        pq, pk, pv, mask, ath, atl);
    // 4) output projection + residual (fp32)
    mma_gemm<2><<<gD, 256, GEMM_SMEM>>>(ath, atl, woh, wol, bo, x,
                                        pxr, nullptr, nullptr, NTOK, DMODEL, DMODEL);
    // 5) pre-norm 2 -> split bf16
    norm_split_kernel<<<NTOK, 256>>>(pxr, alpha2, bias2, x2h, x2l);
    // 6) FF1 + ReLU -> split bf16
    mma_gemm<1><<<gF, 256, GEMM_SMEM>>>(x2h, x2l, w1h, w1l, b1, nullptr,
                                        nullptr, ffh, ffl, NTOK, DFF, DMODEL);
    // 7) FF2 + residual -> fp32 out
    mma_gemm<2><<<gD, 256, GEMM_SMEM>>>(ffh, ffl, w2h, w2l, b2, pxr,
                                        out, nullptr, nullptr, NTOK, DMODEL, DFF);
}

// round 4
// speedup vs baseline: 2.4505x; 1.4354x over previous
#include <cuda_runtime.h>
#include <cuda_bf16.h>
#include <math.h>
#include <stdint.h>

// Problem constants
#define BATCH 4
#define SEQ   2048
#define DMODEL 1024
#define NHEAD 16
#define DK    64
#define DFF   4096
#define NTOK  (BATCH * SEQ)   // 8192

// ---------------- scratch (static device globals; no allocation) -----------
__device__ __nv_bfloat16 g_x2h [NTOK * DMODEL];
__device__ __nv_bfloat16 g_x2l [NTOK * DMODEL];
__device__ __nv_bfloat16 g_qh  [NTOK * DMODEL];   // [B,H,S,DK] split, pre-scaled 1/8
__device__ __nv_bfloat16 g_ql  [NTOK * DMODEL];
__device__ __nv_bfloat16 g_kh  [NTOK * DMODEL];
__device__ __nv_bfloat16 g_kl  [NTOK * DMODEL];
__device__ __nv_bfloat16 g_vh  [NTOK * DMODEL];
__device__ __nv_bfloat16 g_vl  [NTOK * DMODEL];
__device__ __nv_bfloat16 g_ath [NTOK * DMODEL];   // attn out split, [B,S,H*DK]
__device__ __nv_bfloat16 g_atl [NTOK * DMODEL];
__device__ float         g_xr  [NTOK * DMODEL];   // residual after attention
__device__ __nv_bfloat16 g_ffh [NTOK * DFF];
__device__ __nv_bfloat16 g_ffl [NTOK * DFF];
// transposed split weights, [N, K] layout
__device__ __nv_bfloat16 g_wqh[DMODEL*DMODEL], g_wql[DMODEL*DMODEL];
__device__ __nv_bfloat16 g_wkh[DMODEL*DMODEL], g_wkl[DMODEL*DMODEL];
__device__ __nv_bfloat16 g_wvh[DMODEL*DMODEL], g_wvl[DMODEL*DMODEL];
__device__ __nv_bfloat16 g_woh[DMODEL*DMODEL], g_wol[DMODEL*DMODEL];
__device__ __nv_bfloat16 g_w1h[DMODEL*DFF],    g_w1l[DMODEL*DFF];
__device__ __nv_bfloat16 g_w2h[DFF*DMODEL],    g_w2l[DFF*DMODEL];

// ============================ PTX helpers (sm_80-level only) ================
__device__ __forceinline__ uint32_t s2u(const void* p) {
    uint32_t a;
    asm("{ .reg .u64 t; cvta.to.shared.u64 t, %1; cvt.u32.u64 %0, t; }"
        : "=r"(a) : "l"(p));
    return a;
}
__device__ __forceinline__ void cpa16(uint32_t s, const void* g) {
    asm volatile("cp.async.cg.shared.global [%0], [%1], 16;"
                 :: "r"(s), "l"(g) : "memory");
}
__device__ __forceinline__ void cp_commit() {
    asm volatile("cp.async.commit_group;" ::: "memory");
}
template<int N>
__device__ __forceinline__ void cp_wait() {
    asm volatile("cp.async.wait_group %0;" :: "n"(N) : "memory");
}
__device__ __forceinline__ void ldm4(uint32_t* r, uint32_t addr) {
    asm volatile("ldmatrix.sync.aligned.m8n8.x4.shared.b16 {%0,%1,%2,%3}, [%4];"
        : "=r"(r[0]), "=r"(r[1]), "=r"(r[2]), "=r"(r[3]) : "r"(addr));
}
__device__ __forceinline__ void ldm4t(uint32_t* r, uint32_t addr) {
    asm volatile("ldmatrix.sync.aligned.m8n8.x4.trans.shared.b16 {%0,%1,%2,%3}, [%4];"
        : "=r"(r[0]), "=r"(r[1]), "=r"(r[2]), "=r"(r[3]) : "r"(addr));
}
__device__ __forceinline__ void mma16816(float* c, const uint32_t* a,
                                         uint32_t b0, uint32_t b1) {
    asm volatile(
        "mma.sync.aligned.m16n8k16.row.col.f32.bf16.bf16.f32 "
        "{%0,%1,%2,%3}, {%4,%5,%6,%7}, {%8,%9}, {%0,%1,%2,%3};"
        : "+f"(c[0]), "+f"(c[1]), "+f"(c[2]), "+f"(c[3])
        : "r"(a[0]), "r"(a[1]), "r"(a[2]), "r"(a[3]), "r"(b0), "r"(b1));
}
__device__ __forceinline__ uint32_t pk2(float a, float b) {
    __nv_bfloat162 h; h.x = __float2bfloat16(a); h.y = __float2bfloat16(b);
    return *(uint32_t*)&h;
}
__device__ __forceinline__ uint32_t pk2r(float a, float b, float& ra, float& rb) {
    __nv_bfloat162 h; h.x = __float2bfloat16(a); h.y = __float2bfloat16(b);
    ra = a - __bfloat162float(h.x); rb = b - __bfloat162float(h.y);
    return *(uint32_t*)&h;
}

// ---------------------------------------------------------------------------
// Tensor1DNorm -> split-bf16 output (hi/lo).
// ---------------------------------------------------------------------------
__global__ void __launch_bounds__(256) norm_split_kernel(
    const float* __restrict__ x, const float* __restrict__ alpha,
    const float* __restrict__ beta,
    __nv_bfloat16* __restrict__ yh, __nv_bfloat16* __restrict__ yl)
{
    __shared__ float red[16];
    __shared__ float stats[2];
    int row = blockIdx.x;
    int t = threadIdx.x;
    const float4* xr = (const float4*)(x + (size_t)row * DMODEL);
    float4 v = xr[t];
    float s  = v.x + v.y + v.z + v.w;
    float sq = v.x*v.x + v.y*v.y + v.z*v.z + v.w*v.w;
#pragma unroll
    for (int o = 16; o > 0; o >>= 1) {
        s  += __shfl_down_sync(0xffffffffu, s,  o);
        sq += __shfl_down_sync(0xffffffffu, sq, o);
    }
    int warp = t >> 5;
    if ((t & 31) == 0) { red[warp] = s; red[warp + 8] = sq; }
    __syncthreads();
    if (t == 0) {
        float S = 0.f, SQ = 0.f;
#pragma unroll
        for (int w = 0; w < 8; w++) { S += red[w]; SQ += red[w + 8]; }
        float mean = S * (1.0f / DMODEL);
        float var = (SQ - S * mean) * (1.0f / (DMODEL - 1));
        var = fmaxf(var, 0.0f);
        stats[0] = mean; stats[1] = 1.0f / (sqrtf(var) + 1e-6f);
    }
    __syncthreads();
    float mean = stats[0], inv = stats[1];
    float4 a = ((const float4*)alpha)[t];
    float4 b = ((const float4*)beta)[t];
    float o[4];
    o[0] = a.x * (v.x - mean) * inv + b.x;
    o[1] = a.y * (v.y - mean) * inv + b.y;
    o[2] = a.z * (v.z - mean) * inv + b.z;
    o[3] = a.w * (v.w - mean) * inv + b.w;
    __nv_bfloat162 h2[2], l2[2];
#pragma unroll
    for (int q = 0; q < 2; q++) {
        __nv_bfloat16 h0 = __float2bfloat16(o[q*2]);
        __nv_bfloat16 h1 = __float2bfloat16(o[q*2+1]);
        h2[q].x = h0; h2[q].y = h1;
        l2[q].x = __float2bfloat16(o[q*2]   - __bfloat162float(h0));
        l2[q].y = __float2bfloat16(o[q*2+1] - __bfloat162float(h1));
    }
    __nv_bfloat162* ph = (__nv_bfloat162*)(yh + (size_t)row * DMODEL);
    __nv_bfloat162* pl = (__nv_bfloat162*)(yl + (size_t)row * DMODEL);
    ph[t*2] = h2[0]; ph[t*2+1] = h2[1];
    pl[t*2] = l2[0]; pl[t*2+1] = l2[1];
}

// ---------------------------------------------------------------------------
// Fused weight transpose+split for ALL 6 weights in ONE launch.
// Block id ranges select the weight. 32x32 tiles.
// ---------------------------------------------------------------------------
__global__ void __launch_bounds__(256) convw_all(
    const float* __restrict__ wq, const float* __restrict__ wk,
    const float* __restrict__ wv, const float* __restrict__ wo,
    const float* __restrict__ w1, const float* __restrict__ w2,
    __nv_bfloat16* qh, __nv_bfloat16* ql,
    __nv_bfloat16* kh, __nv_bfloat16* kl,
    __nv_bfloat16* vh, __nv_bfloat16* vl,
    __nv_bfloat16* oh, __nv_bfloat16* ol,
    __nv_bfloat16* h1, __nv_bfloat16* l1,
    __nv_bfloat16* h2, __nv_bfloat16* l2)
{
    __shared__ float t[32][33];
    int bid = blockIdx.x;
    const float* W; __nv_bfloat16 *hi, *lo;
    int K, N, bx, by;
    if (bid < 4096) {
        int ws = bid >> 10, lt = bid & 1023;
        K = DMODEL; N = DMODEL; bx = lt & 31; by = lt >> 5;
        if (ws == 0)      { W = wq; hi = qh; lo = ql; }
        else if (ws == 1) { W = wk; hi = kh; lo = kl; }
        else if (ws == 2) { W = wv; hi = vh; lo = vl; }
        else              { W = wo; hi = oh; lo = ol; }
    } else if (bid < 8192) {
        int lt = bid - 4096;
        K = DMODEL; N = DFF; bx = lt & 127; by = lt >> 7;
        W = w1; hi = h1; lo = l1;
    } else {
        int lt = bid - 8192;
        K = DFF; N = DMODEL; bx = lt & 31; by = lt >> 5;
        W = w2; hi = h2; lo = l2;
    }
    int tx = threadIdx.x, ty = threadIdx.y;
    int n0 = bx * 32, k0 = by * 32;
#pragma unroll
    for (int i = 0; i < 4; i++)
        t[ty + 8*i][tx] = W[(size_t)(k0 + ty + 8*i) * N + n0 + tx];
    __syncthreads();
#pragma unroll
    for (int i = 0; i < 4; i++) {
        float v = t[tx][ty + 8*i];
        __nv_bfloat16 h = __float2bfloat16(v);
        size_t idx = (size_t)(n0 + ty + 8*i) * K + k0 + tx;
        hi[idx] = h;
        lo[idx] = __float2bfloat16(v - __bfloat162float(h));
    }
}

// ---------------------------------------------------------------------------
// Split-bf16 HMMA GEMM. CTA 128x128x64, 256 threads, 8 warps (2Mx4N).
// EPI: 1 = +bias, relu, store split bf16 (FF1)
//      2 = +bias +resid, store fp32 (O-proj / FF2)
//      3 = (+bias)*scale, store split bf16 [B,H,S,DK] (QKV)
// ---------------------------------------------------------------------------
#define GBM 128
#define GBN 128
#define GBK 64
#define OFF_AH 0
#define OFF_AL 16384
#define OFF_BH 32768
#define OFF_BL 49152
#define STAGE_B 65536
#define GEMM_SMEM (2 * STAGE_B)

__device__ __forceinline__ void load_stage64(
    uint32_t sb, const __nv_bfloat16* Ah, const __nv_bfloat16* Al,
    const __nv_bfloat16* Bh, const __nv_bfloat16* Bl,
    int m0, int n0, int k0, int K, int tid)
{
#pragma unroll
    for (int r = 0; r < 4; r++) {
        int ci = tid + r * 256;
        int row = ci >> 3, ch = ci & 7;
        uint32_t sw = (uint32_t)(row * 128 + ((ch ^ (row & 7)) << 4));
        size_t goA = (size_t)(m0 + row) * K + k0 + ch * 8;
        size_t goB = (size_t)(n0 + row) * K + k0 + ch * 8;
        cpa16(sb + OFF_AH + sw, Ah + goA);
        cpa16(sb + OFF_AL + sw, Al + goA);
        cpa16(sb + OFF_BH + sw, Bh + goB);
        cpa16(sb + OFF_BL + sw, Bl + goB);
    }
}

template<int EPI>
__global__ void __launch_bounds__(256)
mma_gemm(const __nv_bfloat16* __restrict__ Ah, const __nv_bfloat16* __restrict__ Al,
         const __nv_bfloat16* __restrict__ Bh, const __nv_bfloat16* __restrict__ Bl,
         const float* __restrict__ bias, const float* __restrict__ resid,
         float* __restrict__ C,
         __nv_bfloat16* __restrict__ Ch, __nv_bfloat16* __restrict__ Cl,
         int M, int N, int K, float scale)
{
    extern __shared__ __align__(1024) char dsm[];
    uint32_t dyn = s2u(dsm);

    int tid = threadIdx.x;
    int wid = tid >> 5, lane = tid & 31;
    int wm = wid & 1, wn = wid >> 1;
    int m0 = blockIdx.y * GBM, n0 = blockIdx.x * GBN;

    float c[4][4][4];
#pragma unroll
    for (int i = 0; i < 4; i++)
#pragma unroll
        for (int j = 0; j < 4; j++)
#pragma unroll
            for (int q = 0; q < 4; q++) c[i][j][q] = 0.f;

    int aRow0 = wm * 64 + (lane & 7) + ((lane >> 3) & 1) * 8;
    int bRow0 = wn * 32 + (lane & 7) + ((lane >> 3) & 1) * 8;
    int cgrp = lane >> 4;

    int nsteps = K / GBK;
    load_stage64(dyn, Ah, Al, Bh, Bl, m0, n0, 0, K, tid);
    cp_commit();

    for (int step = 0; step < nsteps; step++) {
        uint32_t sb = dyn + (uint32_t)(step & 1) * STAGE_B;
        if (step + 1 < nsteps) {
            load_stage64(dyn + (uint32_t)((step + 1) & 1) * STAGE_B,
                         Ah, Al, Bh, Bl, m0, n0, (step + 1) * GBK, K, tid);
            cp_commit();
            cp_wait<1>();
        } else {
            cp_wait<0>();
        }
        __syncthreads();

#pragma unroll
        for (int s = 0; s < 4; s++) {
            int ch = 2 * s + cgrp;
            uint32_t ah[4][4], al[4][4];
#pragma unroll
            for (int i = 0; i < 4; i++) {
                int row = aRow0 + i * 16;
                uint32_t ad = sb + OFF_AH + row * 128 + ((ch ^ (row & 7)) << 4);
                ldm4(ah[i], ad);
                ldm4(al[i], ad + (OFF_AL - OFF_AH));
            }
            uint32_t bh[2][4], bl[2][4];
#pragma unroll
            for (int g = 0; g < 2; g++) {
                int row = bRow0 + g * 16;
                uint32_t bd = sb + OFF_BH + row * 128 + ((ch ^ (row & 7)) << 4);
                ldm4(bh[g], bd);
                ldm4(bl[g], bd + (OFF_BL - OFF_BH));
            }
#pragma unroll
            for (int i = 0; i < 4; i++) {
#pragma unroll
                for (int j = 0; j < 4; j++) {
                    int g = j >> 1, o = j & 1;
                    mma16816(c[i][j], ah[i], bh[g][o], bh[g][o + 2]);
                    mma16816(c[i][j], ah[i], bl[g][o], bl[g][o + 2]);
                    mma16816(c[i][j], al[i], bh[g][o], bh[g][o + 2]);
                }
            }
        }
        __syncthreads();
    }

    // ----------------- epilogue -----------------
    int rbase = m0 + wm * 64 + (lane >> 2);
    int cbase = n0 + wn * 32 + (lane & 3) * 2;
#pragma unroll
    for (int i = 0; i < 4; i++) {
#pragma unroll
        for (int j = 0; j < 4; j++) {
            int col = cbase + j * 8;
            float bs0 = bias[col], bs1 = bias[col + 1];
#pragma unroll
            for (int half = 0; half < 2; half++) {
                int r = rbase + i * 16 + half * 8;
                float v0 = c[i][j][half * 2]     + bs0;
                float v1 = c[i][j][half * 2 + 1] + bs1;
                if (EPI == 1) {
                    v0 = fmaxf(v0, 0.f);
                    v1 = fmaxf(v1, 0.f);
                    __nv_bfloat162 hv, lv;
                    hv.x = __float2bfloat16(v0);
                    hv.y = __float2bfloat16(v1);
                    lv.x = __float2bfloat16(v0 - __bfloat162float(hv.x));
                    lv.y = __float2bfloat16(v1 - __bfloat162float(hv.y));
                    *(__nv_bfloat162*)(Ch + (size_t)r * N + col) = hv;
                    *(__nv_bfloat162*)(Cl + (size_t)r * N + col) = lv;
                } else if (EPI == 2) {
                    float2 rr = *(const float2*)(resid + (size_t)r * N + col);
                    float2 o; o.x = v0 + rr.x; o.y = v1 + rr.y;
                    *(float2*)(C + (size_t)r * N + col) = o;
                } else {  // EPI == 3: QKV split-bf16, scaled, [B,H,S,DK]
                    v0 *= scale; v1 *= scale;
                    int bb = r >> 11, sx = r & 2047;
                    int h = col >> 6, d = col & 63;
                    size_t idx = (((size_t)bb * NHEAD + h) * SEQ + sx) * DK + d;
                    __nv_bfloat162 hv, lv;
                    hv.x = __float2bfloat16(v0);
                    hv.y = __float2bfloat16(v1);
                    lv.x = __float2bfloat16(v0 - __bfloat162float(hv.x));
                    lv.y = __float2bfloat16(v1 - __bfloat162float(hv.y));
                    *(__nv_bfloat162*)(Ch + idx) = hv;
                    *(__nv_bfloat162*)(Cl + idx) = lv;
                }
            }
        }
    }
}

// ---------------------------------------------------------------------------
// HMMA flash attention, split-bf16 (3-product) for QK^T and PV.
// 128 q-rows/block, 8 warps (16 rows each), 64-key stages double-buffered.
// Q is pre-scaled by 1/8. Outputs split bf16 [B,S,H*DK].
// ---------------------------------------------------------------------------
#define AQH 0
#define AQL 16384
#define ASTG 32768
#define ASTRIDE 32768
#define AKH 0
#define AKL 8192
#define AVH 16384
#define AVL 24576
#define AMSK 98304
#define ATT_SMEM (98304 + 512)

__device__ __forceinline__ void attn_load_kv(
    uint32_t base, int buf, const __nv_bfloat16* Kph, const __nv_bfloat16* Klp,
    const __nv_bfloat16* Vph, const __nv_bfloat16* Vlp,
    const int* mp, int k0, int tid)
{
    uint32_t sb = base + ASTG + (uint32_t)buf * ASTRIDE;
#pragma unroll
    for (int r = 0; r < 2; r++) {
        int ci = tid + r * 256;
        int row = ci >> 3, ch = ci & 7;
        uint32_t sw = (uint32_t)(row * 128 + ((ch ^ (row & 7)) << 4));
        size_t go = (size_t)(k0 + row) * DK + ch * 8;
        cpa16(sb + AKH + sw, Kph + go);
        cpa16(sb + AKL + sw, Klp + go);
        cpa16(sb + AVH + sw, Vph + go);
        cpa16(sb + AVL + sw, Vlp + go);
    }
    if (tid < 16)
        cpa16(base + AMSK + (uint32_t)buf * 256 + tid * 16, mp + k0 + tid * 4);
}

__global__ void __launch_bounds__(256) attn_mma_kernel(
    const __nv_bfloat16* __restrict__ Qh, const __nv_bfloat16* __restrict__ Ql,
    const __nv_bfloat16* __restrict__ Kh, const __nv_bfloat16* __restrict__ Kl,
    const __nv_bfloat16* __restrict__ Vh, const __nv_bfloat16* __restrict__ Vl,
    const int* __restrict__ mask,
    __nv_bfloat16* __restrict__ Oh, __nv_bfloat16* __restrict__ Ol)
{
    extern __shared__ __align__(1024) char attsm[];
    uint32_t base = s2u(attsm);

    int tid = threadIdx.x;
    int wid = tid >> 5, lane = tid & 31;
    int bh = blockIdx.y;
    int b = bh >> 4, hh = bh & 15;
    int q0 = blockIdx.x * 128;

    const __nv_bfloat16* Qph = Qh + ((size_t)bh * SEQ + q0) * DK;
    const __nv_bfloat16* Qlp = Ql + ((size_t)bh * SEQ + q0) * DK;
    const __nv_bfloat16* Kph = Kh + (size_t)bh * SEQ * DK;
    const __nv_bfloat16* Klp = Kl + (size_t)bh * SEQ * DK;
    const __nv_bfloat16* Vph = Vh + (size_t)bh * SEQ * DK;
    const __nv_bfloat16* Vlp = Vl + (size_t)bh * SEQ * DK;
    const int* mp = mask + b * SEQ;

    // Q tile load (128x64 hi+lo)
#pragma unroll
    for (int r = 0; r < 4; r++) {
        int ci = tid + r * 256;
        int row = ci >> 3, ch = ci & 7;
        uint32_t sw = (uint32_t)(row * 128 + ((ch ^ (row & 7)) << 4));
        size_t go = (size_t)row * DK + ch * 8;
        cpa16(base + AQH + sw, Qph + go);
        cpa16(base + AQL + sw, Qlp + go);
    }
    attn_load_kv(base, 0, Kph, Klp, Vph, Vlp, mp, 0, tid);
    cp_commit();

    uint32_t qh[4][4], ql[4][4];
    float m0v = -INFINITY, m1v = -INFINITY, l0v = 0.f, l1v = 0.f;
    float o_[8][4];
#pragma unroll
    for (int j = 0; j < 8; j++)
#pragma unroll
        for (int q = 0; q < 4; q++) o_[j][q] = 0.f;

    const int NKB = SEQ / 64;   // 32
    for (int t = 0; t < NKB; t++) {
        if (t + 1 < NKB) {
            attn_load_kv(base, (t + 1) & 1, Kph, Klp, Vph, Vlp, mp,
                         (t + 1) * 64, tid);
            cp_commit();
            cp_wait<1>();
        } else {
            cp_wait<0>();
        }
        __syncthreads();

        if (t == 0) {
            // preload Q fragments (constant across key blocks)
#pragma unroll
            for (int c2 = 0; c2 < 4; c2++) {
                int row = wid * 16 + (lane & 15);
                int ch = 2 * c2 + (lane >> 4);
                uint32_t ad = base + AQH + row * 128 + ((ch ^ (row & 7)) << 4);
                ldm4(qh[c2], ad);
                ldm4(ql[c2], ad + (AQL - AQH));
            }
        }

        uint32_t sb = base + ASTG + (uint32_t)(t & 1) * ASTRIDE;

        // ---- scores: S[16 x 64] per warp, 3-product split ----
        float sc[8][4];
#pragma unroll
        for (int j = 0; j < 8; j++)
#pragma unroll
            for (int q = 0; q < 4; q++) sc[j][q] = 0.f;
#pragma unroll
        for (int c2 = 0; c2 < 4; c2++) {
            uint32_t kh[4][4], kl[4][4];
#pragma unroll
            for (int g = 0; g < 4; g++) {
                int row = g * 16 + (lane & 7) + ((lane >> 3) & 1) * 8;
                int ch = 2 * c2 + (lane >> 4);
                uint32_t ad = sb + AKH + row * 128 + ((ch ^ (row & 7)) << 4);
                ldm4(kh[g], ad);
                ldm4(kl[g], ad + (AKL - AKH));
            }
#pragma unroll
            for (int j = 0; j < 8; j++) {
                int g = j >> 1, o = j & 1;
                mma16816(sc[j], qh[c2], kh[g][o], kh[g][o + 2]);
                mma16816(sc[j], qh[c2], kl[g][o], kl[g][o + 2]);
                mma16816(sc[j], ql[c2], kh[g][o], kh[g][o + 2]);
            }
        }

        // ---- mask ----
        const int* msk = (const int*)(attsm + AMSK + (t & 1) * 256);
        int cc = (lane & 3) * 2;
#pragma unroll
        for (int j = 0; j < 8; j++) {
            int mv0 = msk[j * 8 + cc], mv1 = msk[j * 8 + cc + 1];
            if (mv0 == 0) { sc[j][0] = -1e9f; sc[j][2] = -1e9f; }
            if (mv1 == 0) { sc[j][1] = -1e9f; sc[j][3] = -1e9f; }
        }

        // ---- online softmax (rows r = lane>>2 and r+8) ----
        float mx0 = -INFINITY, mx1 = -INFINITY;
#pragma unroll
        for (int j = 0; j < 8; j++) {
            mx0 = fmaxf(mx0, fmaxf(sc[j][0], sc[j][1]));
            mx1 = fmaxf(mx1, fmaxf(sc[j][2], sc[j][3]));
        }
        mx0 = fmaxf(mx0, __shfl_xor_sync(0xffffffffu, mx0, 1));
        mx0 = fmaxf(mx0, __shfl_xor_sync(0xffffffffu, mx0, 2));
        mx1 = fmaxf(mx1, __shfl_xor_sync(0xffffffffu, mx1, 1));
        mx1 = fmaxf(mx1, __shfl_xor_sync(0xffffffffu, mx1, 2));
        float mn0 = fmaxf(m0v, mx0), mn1 = fmaxf(m1v, mx1);
        float cor0 = __expf(m0v - mn0), cor1 = __expf(m1v - mn1);

        float sum0 = 0.f, sum1 = 0.f;
        uint32_t ph0[8], ph1[8], pl0[8], pl1[8];
#pragma unroll
        for (int j = 0; j < 8; j++) {
            float p0 = __expf(sc[j][0] - mn0);
            float p1 = __expf(sc[j][1] - mn0);
            float p2 = __expf(sc[j][2] - mn1);
            float p3 = __expf(sc[j][3] - mn1);
            sum0 += p0 + p1; sum1 += p2 + p3;
            float r0, r1, r2, r3;
            ph0[j] = pk2r(p0, p1, r0, r1);
            ph1[j] = pk2r(p2, p3, r2, r3);
            pl0[j] = pk2(r0, r1);
            pl1[j] = pk2(r2, r3);
        }
        sum0 += __shfl_xor_sync(0xffffffffu, sum0, 1);
        sum0 += __shfl_xor_sync(0xffffffffu, sum0, 2);
        sum1 += __shfl_xor_sync(0xffffffffu, sum1, 1);
        sum1 += __shfl_xor_sync(0xffffffffu, sum1, 2);
        l0v = l0v * cor0 + sum0;
        l1v = l1v * cor1 + sum1;
        m0v = mn0; m1v = mn1;
#pragma unroll
        for (int j = 0; j < 8; j++) {
            o_[j][0] *= cor0; o_[j][1] *= cor0;
            o_[j][2] *= cor1; o_[j][3] *= cor1;
        }

        // ---- PV: O[16 x 64] += P[16 x 64] @ V[64 x 64] ----
#pragma unroll
        for (int t2 = 0; t2 < 4; t2++) {
            uint32_t pah[4] = { ph0[2*t2], ph1[2*t2], ph0[2*t2+1], ph1[2*t2+1] };
            uint32_t pal[4] = { pl0[2*t2], pl1[2*t2], pl0[2*t2+1], pl1[2*t2+1] };
            uint32_t vh[4][4], vl[4][4];
#pragma unroll
            for (int g = 0; g < 4; g++) {
                int row = t2 * 16 + (lane & 7) + ((lane >> 3) & 1) * 8;
                int ch = 2 * g + (lane >> 4);
                uint32_t ad = sb + AVH + row * 128 + ((ch ^ (row & 7)) << 4);
                ldm4t(vh[g], ad);
                ldm4t(vl[g], ad + (AVL - AVH));
            }
#pragma unroll
            for (int j = 0; j < 8; j++) {
                int g = j >> 1, h2 = j & 1;
                mma16816(o_[j], pah, vh[g][2*h2], vh[g][2*h2 + 1]);
                mma16816(o_[j], pah, vl[g][2*h2], vl[g][2*h2 + 1]);
                mma16816(o_[j], pal, vh[g][2*h2], vh[g][2*h2 + 1]);
            }
        }
        __syncthreads();
    }

    // ---- epilogue: O/l -> split bf16 [B,S,H*DK] ----
    float il0 = 1.0f / l0v, il1 = 1.0f / l1v;
    size_t row0 = (size_t)b * SEQ + q0 + wid * 16 + (lane >> 2);
    size_t row1 = row0 + 8;
    int cb = hh * DK + (lane & 3) * 2;
#pragma unroll
    for (int j = 0; j < 8; j++) {
        int col = cb + j * 8;
        float v0 = o_[j][0] * il0, v1 = o_[j][1] * il0;
        float v2 = o_[j][2] * il1, v3 = o_[j][3] * il1;
        __nv_bfloat162 hv, lv;
        hv.x = __float2bfloat16(v0); hv.y = __float2bfloat16(v1);
        lv.x = __float2bfloat16(v0 - __bfloat162float(hv.x));
        lv.y = __float2bfloat16(v1 - __bfloat162float(hv.y));
        *(__nv_bfloat162*)(Oh + row0 * DMODEL + col) = hv;
        *(__nv_bfloat162*)(Ol + row0 * DMODEL + col) = lv;
        hv.x = __float2bfloat16(v2); hv.y = __float2bfloat16(v3);
        lv.x = __float2bfloat16(v2 - __bfloat162float(hv.x));
        lv.y = __float2bfloat16(v3 - __bfloat162float(hv.y));
        *(__nv_bfloat162*)(Oh + row1 * DMODEL + col) = hv;
        *(__nv_bfloat162*)(Ol + row1 * DMODEL + col) = lv;
    }
}

// ---------------------------------------------------------------------------
extern "C" void kernel_launch(void* const* d_in, const int* in_sizes, int n_in,
                              void* d_out, int out_size)
{
    const float* x      = (const float*)d_in[0];
    const int*   mask   = (const int*)  d_in[1];
    const float* wq     = (const float*)d_in[2];
    const float* bq     = (const float*)d_in[3];
    const float* wk     = (const float*)d_in[4];
    const float* bk     = (const float*)d_in[5];
    const float* wv     = (const float*)d_in[6];
    const float* bv     = (const float*)d_in[7];
    const float* wo     = (const float*)d_in[8];
    const float* bo     = (const float*)d_in[9];
    const float* w1     = (const float*)d_in[10];
    const float* b1     = (const float*)d_in[11];
    const float* w2     = (const float*)d_in[12];
    const float* b2     = (const float*)d_in[13];
    const float* alpha1 = (const float*)d_in[14];
    const float* bias1  = (const float*)d_in[15];
    const float* alpha2 = (const float*)d_in[16];
    const float* bias2  = (const float*)d_in[17];
    float* out = (float*)d_out;

    __nv_bfloat16 *x2h, *x2l, *ath, *atl, *ffh, *ffl;
    __nv_bfloat16 *qh, *ql, *kh, *kl, *vh, *vl;
    __nv_bfloat16 *wqh, *wql, *wkh, *wkl, *wvh, *wvl, *woh, *wol, *w1h, *w1l, *w2h, *w2l;
    float *pxr;
    cudaGetSymbolAddress((void**)&x2h, g_x2h);  cudaGetSymbolAddress((void**)&x2l, g_x2l);
    cudaGetSymbolAddress((void**)&ath, g_ath);  cudaGetSymbolAddress((void**)&atl, g_atl);
    cudaGetSymbolAddress((void**)&ffh, g_ffh);  cudaGetSymbolAddress((void**)&ffl, g_ffl);
    cudaGetSymbolAddress((void**)&qh,  g_qh);   cudaGetSymbolAddress((void**)&ql,  g_ql);
    cudaGetSymbolAddress((void**)&kh,  g_kh);   cudaGetSymbolAddress((void**)&kl,  g_kl);
    cudaGetSymbolAddress((void**)&vh,  g_vh);   cudaGetSymbolAddress((void**)&vl,  g_vl);
    cudaGetSymbolAddress((void**)&wqh, g_wqh);  cudaGetSymbolAddress((void**)&wql, g_wql);
    cudaGetSymbolAddress((void**)&wkh, g_wkh);  cudaGetSymbolAddress((void**)&wkl, g_wkl);
    cudaGetSymbolAddress((void**)&wvh, g_wvh);  cudaGetSymbolAddress((void**)&wvl, g_wvl);
    cudaGetSymbolAddress((void**)&woh, g_woh);  cudaGetSymbolAddress((void**)&wol, g_wol);
    cudaGetSymbolAddress((void**)&w1h, g_w1h);  cudaGetSymbolAddress((void**)&w1l, g_w1l);
    cudaGetSymbolAddress((void**)&w2h, g_w2h);  cudaGetSymbolAddress((void**)&w2l, g_w2l);
    cudaGetSymbolAddress((void**)&pxr, g_xr);

    cudaFuncSetAttribute(attn_mma_kernel,
                         cudaFuncAttributeMaxDynamicSharedMemorySize, ATT_SMEM);
    cudaFuncSetAttribute(mma_gemm<1>,
                         cudaFuncAttributeMaxDynamicSharedMemorySize, GEMM_SMEM);
    cudaFuncSetAttribute(mma_gemm<2>,
                         cudaFuncAttributeMaxDynamicSharedMemorySize, GEMM_SMEM);
    cudaFuncSetAttribute(mma_gemm<3>,
                         cudaFuncAttributeMaxDynamicSharedMemorySize, GEMM_SMEM);

    dim3 gD(DMODEL / GBN, NTOK / GBM);   // (8, 64)
    dim3 gF(DFF / GBN,    NTOK / GBM);   // (32, 64)

    // 1) fused weight transpose + split (single launch)
    convw_all<<<12288, dim3(32, 8)>>>(wq, wk, wv, wo, w1, w2,
                                      wqh, wql, wkh, wkl, wvh, wvl,
                                      woh, wol, w1h, w1l, w2h, w2l);
    // 2) pre-norm 1 -> split bf16
    norm_split_kernel<<<NTOK, 256>>>(x, alpha1, bias1, x2h, x2l);
    // 3-5) QKV projections -> split bf16 [B,H,S,DK]; Q pre-scaled 1/8
    mma_gemm<3><<<gD, 256, GEMM_SMEM>>>(x2h, x2l, wqh, wql, bq, nullptr,
                                        nullptr, qh, ql, NTOK, DMODEL, DMODEL, 0.125f);
    mma_gemm<3><<<gD, 256, GEMM_SMEM>>>(x2h, x2l, wkh, wkl, bk, nullptr,
                                        nullptr, kh, kl, NTOK, DMODEL, DMODEL, 1.0f);
    mma_gemm<3><<<gD, 256, GEMM_SMEM>>>(x2h, x2l, wvh, wvl, bv, nullptr,
                                        nullptr, vh, vl, NTOK, DMODEL, DMODEL, 1.0f);
    // 6) HMMA flash attention -> split bf16
    attn_mma_kernel<<<dim3(SEQ / 128, BATCH * NHEAD), 256, ATT_SMEM>>>(
        qh, ql, kh, kl, vh, vl, mask, ath, atl);
    // 7) output projection + residual (fp32)
    mma_gemm<2><<<gD, 256, GEMM_SMEM>>>(ath, atl, woh, wol, bo, x,
                                        pxr, nullptr, nullptr, NTOK, DMODEL, DMODEL, 1.0f);
    // 8) pre-norm 2 -> split bf16
    norm_split_kernel<<<NTOK, 256>>>(pxr, alpha2, bias2, x2h, x2l);
    // 9) FF1 + ReLU -> split bf16
    mma_gemm<1><<<gF, 256, GEMM_SMEM>>>(x2h, x2l, w1h, w1l, b1, nullptr,
                                        nullptr, ffh, ffl, NTOK, DFF, DMODEL, 1.0f);
    // 10) FF2 + residual -> fp32 out
    mma_gemm<2><<<gD, 256, GEMM_SMEM>>>(ffh, ffl, w2h, w2l, b2, pxr,
                                        out, nullptr, nullptr, NTOK, DMODEL, DFF, 1.0f);
}

// round 5
// speedup vs baseline: 2.5386x; 1.0360x over previous
#include <cuda_runtime.h>
#include <cuda_bf16.h>
#include <math.h>
#include <stdint.h>

// Problem constants
#define BATCH 4
#define SEQ   2048
#define DMODEL 1024
#define NHEAD 16
#define DK    64
#define DFF   4096
#define NTOK  (BATCH * SEQ)   // 8192

// ---------------- scratch (static device globals; no allocation) -----------
__device__ __nv_bfloat16 g_x2h [NTOK * DMODEL];
__device__ __nv_bfloat16 g_x2l [NTOK * DMODEL];
__device__ __nv_bfloat16 g_qkvh[3 * NTOK * DMODEL];  // [3][B,H,S,DK] split
__device__ __nv_bfloat16 g_qkvl[3 * NTOK * DMODEL];
__device__ __nv_bfloat16 g_ath [NTOK * DMODEL];      // attn out split, [B,S,H*DK]
__device__ __nv_bfloat16 g_atl [NTOK * DMODEL];
__device__ float         g_xr  [NTOK * DMODEL];      // residual after attention
__device__ __nv_bfloat16 g_ffh [NTOK * DFF];
__device__ __nv_bfloat16 g_ffl [NTOK * DFF];
// transposed split weights, [N, K] layout; QKV fused to [3072, 1024]
__device__ __nv_bfloat16 g_wqkvh[3*DMODEL*DMODEL], g_wqkvl[3*DMODEL*DMODEL];
__device__ __nv_bfloat16 g_woh[DMODEL*DMODEL], g_wol[DMODEL*DMODEL];
__device__ __nv_bfloat16 g_w1h[DMODEL*DFF],    g_w1l[DMODEL*DFF];
__device__ __nv_bfloat16 g_w2h[DFF*DMODEL],    g_w2l[DFF*DMODEL];
__device__ float         g_bqkv[3*DMODEL];

// ============================ PTX helpers (sm_80-level only) ================
__device__ __forceinline__ uint32_t s2u(const void* p) {
    uint32_t a;
    asm("{ .reg .u64 t; cvta.to.shared.u64 t, %1; cvt.u32.u64 %0, t; }"
        : "=r"(a) : "l"(p));
    return a;
}
__device__ __forceinline__ void cpa16(uint32_t s, const void* g) {
    asm volatile("cp.async.cg.shared.global [%0], [%1], 16;"
                 :: "r"(s), "l"(g) : "memory");
}
__device__ __forceinline__ void cp_commit() {
    asm volatile("cp.async.commit_group;" ::: "memory");
}
template<int N>
__device__ __forceinline__ void cp_wait() {
    asm volatile("cp.async.wait_group %0;" :: "n"(N) : "memory");
}
__device__ __forceinline__ void ldm4(uint32_t* r, uint32_t addr) {
    asm volatile("ldmatrix.sync.aligned.m8n8.x4.shared.b16 {%0,%1,%2,%3}, [%4];"
        : "=r"(r[0]), "=r"(r[1]), "=r"(r[2]), "=r"(r[3]) : "r"(addr));
}
__device__ __forceinline__ void ldm4t(uint32_t* r, uint32_t addr) {
    asm volatile("ldmatrix.sync.aligned.m8n8.x4.trans.shared.b16 {%0,%1,%2,%3}, [%4];"
        : "=r"(r[0]), "=r"(r[1]), "=r"(r[2]), "=r"(r[3]) : "r"(addr));
}
__device__ __forceinline__ void mma16816(float* c, const uint32_t* a,
                                         uint32_t b0, uint32_t b1) {
    asm volatile(
        "mma.sync.aligned.m16n8k16.row.col.f32.bf16.bf16.f32 "
        "{%0,%1,%2,%3}, {%4,%5,%6,%7}, {%8,%9}, {%0,%1,%2,%3};"
        : "+f"(c[0]), "+f"(c[1]), "+f"(c[2]), "+f"(c[3])
        : "r"(a[0]), "r"(a[1]), "r"(a[2]), "r"(a[3]), "r"(b0), "r"(b1));
}
__device__ __forceinline__ uint32_t pk2(float a, float b) {
    __nv_bfloat162 h; h.x = __float2bfloat16(a); h.y = __float2bfloat16(b);
    return *(uint32_t*)&h;
}
__device__ __forceinline__ uint32_t pk2r(float a, float b, float& ra, float& rb) {
    __nv_bfloat162 h; h.x = __float2bfloat16(a); h.y = __float2bfloat16(b);
    ra = a - __bfloat162float(h.x); rb = b - __bfloat162float(h.y);
    return *(uint32_t*)&h;
}

// ---------------------------------------------------------------------------
// Tensor1DNorm -> split-bf16 output (hi/lo).
// ---------------------------------------------------------------------------
__global__ void __launch_bounds__(256) norm_split_kernel(
    const float* __restrict__ x, const float* __restrict__ alpha,
    const float* __restrict__ beta,
    __nv_bfloat16* __restrict__ yh, __nv_bfloat16* __restrict__ yl)
{
    __shared__ float red[16];
    __shared__ float stats[2];
    int row = blockIdx.x;
    int t = threadIdx.x;
    const float4* xr = (const float4*)(x + (size_t)row * DMODEL);
    float4 v = xr[t];
    float s  = v.x + v.y + v.z + v.w;
    float sq = v.x*v.x + v.y*v.y + v.z*v.z + v.w*v.w;
#pragma unroll
    for (int o = 16; o > 0; o >>= 1) {
        s  += __shfl_down_sync(0xffffffffu, s,  o);
        sq += __shfl_down_sync(0xffffffffu, sq, o);
    }
    int warp = t >> 5;
    if ((t & 31) == 0) { red[warp] = s; red[warp + 8] = sq; }
    __syncthreads();
    if (t == 0) {
        float S = 0.f, SQ = 0.f;
#pragma unroll
        for (int w = 0; w < 8; w++) { S += red[w]; SQ += red[w + 8]; }
        float mean = S * (1.0f / DMODEL);
        float var = (SQ - S * mean) * (1.0f / (DMODEL - 1));
        var = fmaxf(var, 0.0f);
        stats[0] = mean; stats[1] = 1.0f / (sqrtf(var) + 1e-6f);
    }
    __syncthreads();
    float mean = stats[0], inv = stats[1];
    float4 a = ((const float4*)alpha)[t];
    float4 b = ((const float4*)beta)[t];
    float o[4];
    o[0] = a.x * (v.x - mean) * inv + b.x;
    o[1] = a.y * (v.y - mean) * inv + b.y;
    o[2] = a.z * (v.z - mean) * inv + b.z;
    o[3] = a.w * (v.w - mean) * inv + b.w;
    __nv_bfloat162 h2[2], l2[2];
#pragma unroll
    for (int q = 0; q < 2; q++) {
        __nv_bfloat16 h0 = __float2bfloat16(o[q*2]);
        __nv_bfloat16 h1 = __float2bfloat16(o[q*2+1]);
        h2[q].x = h0; h2[q].y = h1;
        l2[q].x = __float2bfloat16(o[q*2]   - __bfloat162float(h0));
        l2[q].y = __float2bfloat16(o[q*2+1] - __bfloat162float(h1));
    }
    __nv_bfloat162* ph = (__nv_bfloat162*)(yh + (size_t)row * DMODEL);
    __nv_bfloat162* pl = (__nv_bfloat162*)(yl + (size_t)row * DMODEL);
    ph[t*2] = h2[0]; ph[t*2+1] = h2[1];
    pl[t*2] = l2[0]; pl[t*2+1] = l2[1];
}

// ---------------------------------------------------------------------------
// Fused weight transpose+split for ALL weights in ONE launch.
// QKV weights land in one fused [3072, 1024] buffer; also packs bias qkv.
// ---------------------------------------------------------------------------
__global__ void __launch_bounds__(256) convw_all(
    const float* __restrict__ wq, const float* __restrict__ wk,
    const float* __restrict__ wv, const float* __restrict__ wo,
    const float* __restrict__ w1, const float* __restrict__ w2,
    const float* __restrict__ bq, const float* __restrict__ bk,
    const float* __restrict__ bv,
    __nv_bfloat16* qkvh, __nv_bfloat16* qkvl,
    __nv_bfloat16* oh, __nv_bfloat16* ol,
    __nv_bfloat16* h1, __nv_bfloat16* l1,
    __nv_bfloat16* h2, __nv_bfloat16* l2,
    float* bqkv)
{
    __shared__ float t[32][33];
    int bid = blockIdx.x;
    const float* W; __nv_bfloat16 *hi, *lo;
    int K, N, bx, by;
    size_t nofs = 0;
    if (bid < 4096) {
        int ws = bid >> 10, lt = bid & 1023;
        K = DMODEL; N = DMODEL; bx = lt & 31; by = lt >> 5;
        if (ws == 0)      { W = wq; hi = qkvh; lo = qkvl; nofs = 0; }
        else if (ws == 1) { W = wk; hi = qkvh; lo = qkvl; nofs = DMODEL; }
        else if (ws == 2) { W = wv; hi = qkvh; lo = qkvl; nofs = 2*DMODEL; }
        else              { W = wo; hi = oh;   lo = ol; }
    } else if (bid < 8192) {
        int lt = bid - 4096;
        K = DMODEL; N = DFF; bx = lt & 127; by = lt >> 7;
        W = w1; hi = h1; lo = l1;
    } else {
        int lt = bid - 8192;
        K = DFF; N = DMODEL; bx = lt & 31; by = lt >> 5;
        W = w2; hi = h2; lo = l2;
    }
    int tx = threadIdx.x, ty = threadIdx.y;
    int n0 = bx * 32, k0 = by * 32;
#pragma unroll
    for (int i = 0; i < 4; i++)
        t[ty + 8*i][tx] = W[(size_t)(k0 + ty + 8*i) * N + n0 + tx];
    __syncthreads();
#pragma unroll
    for (int i = 0; i < 4; i++) {
        float v = t[tx][ty + 8*i];
        __nv_bfloat16 h = __float2bfloat16(v);
        size_t idx = (nofs + n0 + ty + 8*i) * K + k0 + tx;
        hi[idx] = h;
        lo[idx] = __float2bfloat16(v - __bfloat162float(h));
    }
    // pack qkv bias once
    if (bid == 0 && ty == 0) {
#pragma unroll
        for (int i = 0; i < DMODEL / 32; i++) {
            bqkv[i * 32 + tx]              = bq[i * 32 + tx];
            bqkv[DMODEL + i * 32 + tx]     = bk[i * 32 + tx];
            bqkv[2 * DMODEL + i * 32 + tx] = bv[i * 32 + tx];
        }
    }
}

// ---------------------------------------------------------------------------
// Split-bf16 HMMA GEMM. CTA 128x128, K-step 32, 3-stage cp.async pipeline,
// 256 threads (8 warps, 2Mx4N), 2 CTAs/SM (96KB smem, 128 regs).
// EPI: 1 = +bias, relu, store split bf16 (FF1)
//      2 = +bias +resid, store fp32 (O-proj / FF2)
//      3 = fused QKV: +bias, q-scale, store split bf16 [3][B,H,S,DK]
// ---------------------------------------------------------------------------
#define GBM 128
#define GBN 128
#define GBK 32
#define SOFF_AH 0
#define SOFF_AL 8192
#define SOFF_BH 16384
#define SOFF_BL 24576
#define STAGE_B 32768
#define GEMM_SMEM (3 * STAGE_B)

// SW64 swizzle for 64-byte rows: 16B chunk ch in row -> ch ^ ((row>>1)&3)
__device__ __forceinline__ void load_stage32(
    uint32_t sb, const __nv_bfloat16* Ah, const __nv_bfloat16* Al,
    const __nv_bfloat16* Bh, const __nv_bfloat16* Bl,
    int m0, int n0, int k0, int K, int tid)
{
#pragma unroll
    for (int r = 0; r < 2; r++) {
        int ci = tid + r * 256;            // 0..511
        int row = ci >> 2, ch = ci & 3;
        uint32_t sw = (uint32_t)(row * 64 + ((ch ^ ((row >> 1) & 3)) << 4));
        size_t goA = (size_t)(m0 + row) * K + k0 + ch * 8;
        size_t goB = (size_t)(n0 + row) * K + k0 + ch * 8;
        cpa16(sb + SOFF_AH + sw, Ah + goA);
        cpa16(sb + SOFF_AL + sw, Al + goA);
        cpa16(sb + SOFF_BH + sw, Bh + goB);
        cpa16(sb + SOFF_BL + sw, Bl + goB);
    }
}

template<int EPI>
__global__ void __launch_bounds__(256, 2)
mma_gemm(const __nv_bfloat16* __restrict__ Ah, const __nv_bfloat16* __restrict__ Al,
         const __nv_bfloat16* __restrict__ Bh, const __nv_bfloat16* __restrict__ Bl,
         const float* __restrict__ bias, const float* __restrict__ resid,
         float* __restrict__ C,
         __nv_bfloat16* __restrict__ Ch, __nv_bfloat16* __restrict__ Cl,
         int M, int N, int K)
{
    extern __shared__ __align__(1024) char dsm[];
    uint32_t dyn = s2u(dsm);

    int tid = threadIdx.x;
    int wid = tid >> 5, lane = tid & 31;
    int wm = wid & 1, wn = wid >> 1;
    int m0 = blockIdx.y * GBM, n0 = blockIdx.x * GBN;

    float c[4][4][4];
#pragma unroll
    for (int i = 0; i < 4; i++)
#pragma unroll
        for (int j = 0; j < 4; j++)
#pragma unroll
            for (int q = 0; q < 4; q++) c[i][j][q] = 0.f;

    int aRow0 = wm * 64 + (lane & 7) + ((lane >> 3) & 1) * 8;
    int bRow0 = wn * 32 + (lane & 7) + ((lane >> 3) & 1) * 8;
    int cgrp = lane >> 4;

    int nsteps = K / GBK;
    load_stage32(dyn, Ah, Al, Bh, Bl, m0, n0, 0, K, tid);
    cp_commit();
    load_stage32(dyn + STAGE_B, Ah, Al, Bh, Bl, m0, n0, GBK, K, tid);
    cp_commit();

    uint32_t sb = dyn;
    int buf = 0;
    for (int step = 0; step < nsteps; step++) {
        if (step < nsteps - 1) cp_wait<1>(); else cp_wait<0>();
        __syncthreads();
        if (step + 2 < nsteps) {
            int nb = buf + 2; if (nb >= 3) nb -= 3;
            load_stage32(dyn + (uint32_t)nb * STAGE_B, Ah, Al, Bh, Bl,
                         m0, n0, (step + 2) * GBK, K, tid);
            cp_commit();
        }

#pragma unroll
        for (int s = 0; s < 2; s++) {
            int ch = 2 * s + cgrp;
            uint32_t ah[4][4], al[4][4];
#pragma unroll
            for (int i = 0; i < 4; i++) {
                int row = aRow0 + i * 16;
                uint32_t ad = sb + SOFF_AH + row * 64 +
                              ((ch ^ ((row >> 1) & 3)) << 4);
                ldm4(ah[i], ad);
                ldm4(al[i], ad + (SOFF_AL - SOFF_AH));
            }
            uint32_t bh[2][4], bl[2][4];
#pragma unroll
            for (int g = 0; g < 2; g++) {
                int row = bRow0 + g * 16;
                uint32_t bd = sb + SOFF_BH + row * 64 +
                              ((ch ^ ((row >> 1) & 3)) << 4);
                ldm4(bh[g], bd);
                ldm4(bl[g], bd + (SOFF_BL - SOFF_BH));
            }
#pragma unroll
            for (int i = 0; i < 4; i++) {
#pragma unroll
                for (int j = 0; j < 4; j++) {
                    int g = j >> 1, o = j & 1;
                    mma16816(c[i][j], ah[i], bh[g][o], bh[g][o + 2]);
                    mma16816(c[i][j], ah[i], bl[g][o], bl[g][o + 2]);
                    mma16816(c[i][j], al[i], bh[g][o], bh[g][o + 2]);
                }
            }
        }
        buf++; if (buf >= 3) buf = 0;
        sb = dyn + (uint32_t)buf * STAGE_B;
        __syncthreads();
    }

    // ----------------- epilogue -----------------
    int rbase = m0 + wm * 64 + (lane >> 2);
    int cbase = n0 + wn * 32 + (lane & 3) * 2;
#pragma unroll
    for (int i = 0; i < 4; i++) {
#pragma unroll
        for (int j = 0; j < 4; j++) {
            int col = cbase + j * 8;
            float bs0 = bias[col], bs1 = bias[col + 1];
#pragma unroll
            for (int half = 0; half < 2; half++) {
                int r = rbase + i * 16 + half * 8;
                float v0 = c[i][j][half * 2]     + bs0;
                float v1 = c[i][j][half * 2 + 1] + bs1;
                if (EPI == 1) {
                    v0 = fmaxf(v0, 0.f);
                    v1 = fmaxf(v1, 0.f);
                    __nv_bfloat162 hv, lv;
                    hv.x = __float2bfloat16(v0);
                    hv.y = __float2bfloat16(v1);
                    lv.x = __float2bfloat16(v0 - __bfloat162float(hv.x));
                    lv.y = __float2bfloat16(v1 - __bfloat162float(hv.y));
                    *(__nv_bfloat162*)(Ch + (size_t)r * N + col) = hv;
                    *(__nv_bfloat162*)(Cl + (size_t)r * N + col) = lv;
                } else if (EPI == 2) {
                    float2 rr = *(const float2*)(resid + (size_t)r * N + col);
                    float2 o; o.x = v0 + rr.x; o.y = v1 + rr.y;
                    *(float2*)(C + (size_t)r * N + col) = o;
                } else {  // EPI == 3: fused QKV -> split bf16 [3][B,H,S,DK]
                    int t  = col >> 10;        // 0=q,1=k,2=v
                    int c2 = col & 1023;
                    int h = c2 >> 6, d = c2 & 63;
                    float sc = (t == 0) ? 0.125f : 1.0f;
                    v0 *= sc; v1 *= sc;
                    int bb = r >> 11, sx = r & 2047;
                    size_t idx = ((((size_t)t * BATCH + bb) * NHEAD + h) * SEQ + sx) * DK + d;
                    __nv_bfloat162 hv, lv;
                    hv.x = __float2bfloat16(v0);
                    hv.y = __float2bfloat16(v1);
                    lv.x = __float2bfloat16(v0 - __bfloat162float(hv.x));
                    lv.y = __float2bfloat16(v1 - __bfloat162float(hv.y));
                    *(__nv_bfloat162*)(Ch + idx) = hv;
                    *(__nv_bfloat162*)(Cl + idx) = lv;
                }
            }
        }
    }
}

// ---------------------------------------------------------------------------
// HMMA flash attention, split-bf16 (3-product) for QK^T and PV.
// 128 q-rows/block, 8 warps, 64-key stages double-buffered.
// Q pre-scaled by 1/8. Outputs split bf16 [B,S,H*DK].
// ---------------------------------------------------------------------------
#define AQH 0
#define AQL 16384
#define ASTG 32768
#define ASTRIDE 32768
#define AKH 0
#define AKL 8192
#define AVH 16384
#define AVL 24576
#define AMSK 98304
#define ATT_SMEM (98304 + 512)

__device__ __forceinline__ void attn_load_kv(
    uint32_t base, int buf, const __nv_bfloat16* Kph, const __nv_bfloat16* Klp,
    const __nv_bfloat16* Vph, const __nv_bfloat16* Vlp,
    const int* mp, int k0, int tid)
{
    uint32_t sb = base + ASTG + (uint32_t)buf * ASTRIDE;
#pragma unroll
    for (int r = 0; r < 2; r++) {
        int ci = tid + r * 256;
        int row = ci >> 3, ch = ci & 7;
        uint32_t sw = (uint32_t)(row * 128 + ((ch ^ (row & 7)) << 4));
        size_t go = (size_t)(k0 + row) * DK + ch * 8;
        cpa16(sb + AKH + sw, Kph + go);
        cpa16(sb + AKL + sw, Klp + go);
        cpa16(sb + AVH + sw, Vph + go);
        cpa16(sb + AVL + sw, Vlp + go);
    }
    if (tid < 16)
        cpa16(base + AMSK + (uint32_t)buf * 256 + tid * 16, mp + k0 + tid * 4);
}

__global__ void __launch_bounds__(256) attn_mma_kernel(
    const __nv_bfloat16* __restrict__ Qh, const __nv_bfloat16* __restrict__ Ql,
    const __nv_bfloat16* __restrict__ Kh, const __nv_bfloat16* __restrict__ Kl,
    const __nv_bfloat16* __restrict__ Vh, const __nv_bfloat16* __restrict__ Vl,
    const int* __restrict__ mask,
    __nv_bfloat16* __restrict__ Oh, __nv_bfloat16* __restrict__ Ol)
{
    extern __shared__ __align__(1024) char attsm[];
    uint32_t base = s2u(attsm);

    int tid = threadIdx.x;
    int wid = tid >> 5, lane = tid & 31;
    int bh = blockIdx.y;
    int b = bh >> 4, hh = bh & 15;
    int q0 = blockIdx.x * 128;

    const __nv_bfloat16* Qph = Qh + ((size_t)bh * SEQ + q0) * DK;
    const __nv_bfloat16* Qlp = Ql + ((size_t)bh * SEQ + q0) * DK;
    const __nv_bfloat16* Kph = Kh + (size_t)bh * SEQ * DK;
    const __nv_bfloat16* Klp = Kl + (size_t)bh * SEQ * DK;
    const __nv_bfloat16* Vph = Vh + (size_t)bh * SEQ * DK;
    const __nv_bfloat16* Vlp = Vl + (size_t)bh * SEQ * DK;
    const int* mp = mask + b * SEQ;

#pragma unroll
    for (int r = 0; r < 4; r++) {
        int ci = tid + r * 256;
        int row = ci >> 3, ch = ci & 7;
        uint32_t sw = (uint32_t)(row * 128 + ((ch ^ (row & 7)) << 4));
        size_t go = (size_t)row * DK + ch * 8;
        cpa16(base + AQH + sw, Qph + go);
        cpa16(base + AQL + sw, Qlp + go);
    }
    attn_load_kv(base, 0, Kph, Klp, Vph, Vlp, mp, 0, tid);
    cp_commit();

    uint32_t qh[4][4], ql[4][4];
    float m0v = -INFINITY, m1v = -INFINITY, l0v = 0.f, l1v = 0.f;
    float o_[8][4];
#pragma unroll
    for (int j = 0; j < 8; j++)
#pragma unroll
        for (int q = 0; q < 4; q++) o_[j][q] = 0.f;

    const int NKB = SEQ / 64;   // 32
    for (int t = 0; t < NKB; t++) {
        if (t + 1 < NKB) {
            attn_load_kv(base, (t + 1) & 1, Kph, Klp, Vph, Vlp, mp,
                         (t + 1) * 64, tid);
            cp_commit();
            cp_wait<1>();
        } else {
            cp_wait<0>();
        }
        __syncthreads();

        if (t == 0) {
#pragma unroll
            for (int c2 = 0; c2 < 4; c2++) {
                int row = wid * 16 + (lane & 15);
                int ch = 2 * c2 + (lane >> 4);
                uint32_t ad = base + AQH + row * 128 + ((ch ^ (row & 7)) << 4);
                ldm4(qh[c2], ad);
                ldm4(ql[c2], ad + (AQL - AQH));
            }
        }

        uint32_t sb = base + ASTG + (uint32_t)(t & 1) * ASTRIDE;

        float sc[8][4];
#pragma unroll
        for (int j = 0; j < 8; j++)
#pragma unroll
            for (int q = 0; q < 4; q++) sc[j][q] = 0.f;
#pragma unroll
        for (int c2 = 0; c2 < 4; c2++) {
            uint32_t kh[4][4], kl[4][4];
#pragma unroll
            for (int g = 0; g < 4; g++) {
                int row = g * 16 + (lane & 7) + ((lane >> 3) & 1) * 8;
                int ch = 2 * c2 + (lane >> 4);
                uint32_t ad = sb + AKH + row * 128 + ((ch ^ (row & 7)) << 4);
                ldm4(kh[g], ad);
                ldm4(kl[g], ad + (AKL - AKH));
            }
#pragma unroll
            for (int j = 0; j < 8; j++) {
                int g = j >> 1, o = j & 1;
                mma16816(sc[j], qh[c2], kh[g][o], kh[g][o + 2]);
                mma16816(sc[j], qh[c2], kl[g][o], kl[g][o + 2]);
                mma16816(sc[j], ql[c2], kh[g][o], kh[g][o + 2]);
            }
        }

        const int* msk = (const int*)(attsm + AMSK + (t & 1) * 256);
        int cc = (lane & 3) * 2;
#pragma unroll
        for (int j = 0; j < 8; j++) {
            int mv0 = msk[j * 8 + cc], mv1 = msk[j * 8 + cc + 1];
            if (mv0 == 0) { sc[j][0] = -1e9f; sc[j][2] = -1e9f; }
            if (mv1 == 0) { sc[j][1] = -1e9f; sc[j][3] = -1e9f; }
        }

        float mx0 = -INFINITY, mx1 = -INFINITY;
#pragma unroll
        for (int j = 0; j < 8; j++) {
            mx0 = fmaxf(mx0, fmaxf(sc[j][0], sc[j][1]));
            mx1 = fmaxf(mx1, fmaxf(sc[j][2], sc[j][3]));
        }
        mx0 = fmaxf(mx0, __shfl_xor_sync(0xffffffffu, mx0, 1));
        mx0 = fmaxf(mx0, __shfl_xor_sync(0xffffffffu, mx0, 2));
        mx1 = fmaxf(mx1, __shfl_xor_sync(0xffffffffu, mx1, 1));
        mx1 = fmaxf(mx1, __shfl_xor_sync(0xffffffffu, mx1, 2));
        float mn0 = fmaxf(m0v, mx0), mn1 = fmaxf(m1v, mx1);
        float cor0 = __expf(m0v - mn0), cor1 = __expf(m1v - mn1);

        float sum0 = 0.f, sum1 = 0.f;
        uint32_t ph0[8], ph1[8], pl0[8], pl1[8];
#pragma unroll
        for (int j = 0; j < 8; j++) {
            float p0 = __expf(sc[j][0] - mn0);
            float p1 = __expf(sc[j][1] - mn0);
            float p2 = __expf(sc[j][2] - mn1);
            float p3 = __expf(sc[j][3] - mn1);
            sum0 += p0 + p1; sum1 += p2 + p3;
            float r0, r1, r2, r3;
            ph0[j] = pk2r(p0, p1, r0, r1);
            ph1[j] = pk2r(p2, p3, r2, r3);
            pl0[j] = pk2(r0, r1);
            pl1[j] = pk2(r2, r3);
        }
        sum0 += __shfl_xor_sync(0xffffffffu, sum0, 1);
        sum0 += __shfl_xor_sync(0xffffffffu, sum0, 2);
        sum1 += __shfl_xor_sync(0xffffffffu, sum1, 1);
        sum1 += __shfl_xor_sync(0xffffffffu, sum1, 2);
        l0v = l0v * cor0 + sum0;
        l1v = l1v * cor1 + sum1;
        m0v = mn0; m1v = mn1;
#pragma unroll
        for (int j = 0; j < 8; j++) {
            o_[j][0] *= cor0; o_[j][1] *= cor0;
            o_[j][2] *= cor1; o_[j][3] *= cor1;
        }

#pragma unroll
        for (int t2 = 0; t2 < 4; t2++) {
            uint32_t pah[4] = { ph0[2*t2], ph1[2*t2], ph0[2*t2+1], ph1[2*t2+1] };
            uint32_t pal[4] = { pl0[2*t2], pl1[2*t2], pl0[2*t2+1], pl1[2*t2+1] };
            uint32_t vh[4][4], vl[4][4];
#pragma unroll
            for (int g = 0; g < 4; g++) {
                int row = t2 * 16 + (lane & 7) + ((lane >> 3) & 1) * 8;
                int ch = 2 * g + (lane >> 4);
                uint32_t ad = sb + AVH + row * 128 + ((ch ^ (row & 7)) << 4);
                ldm4t(vh[g], ad);
                ldm4t(vl[g], ad + (AVL - AVH));
            }
#pragma unroll
            for (int j = 0; j < 8; j++) {
                int g = j >> 1, h2 = j & 1;
                mma16816(o_[j], pah, vh[g][2*h2], vh[g][2*h2 + 1]);
                mma16816(o_[j], pah, vl[g][2*h2], vl[g][2*h2 + 1]);
                mma16816(o_[j], pal, vh[g][2*h2], vh[g][2*h2 + 1]);
            }
        }
        __syncthreads();
    }

    float il0 = 1.0f / l0v, il1 = 1.0f / l1v;
    size_t row0 = (size_t)b * SEQ + q0 + wid * 16 + (lane >> 2);
    size_t row1 = row0 + 8;
    int cb = hh * DK + (lane & 3) * 2;
#pragma unroll
    for (int j = 0; j < 8; j++) {
        int col = cb + j * 8;
        float v0 = o_[j][0] * il0, v1 = o_[j][1] * il0;
        float v2 = o_[j][2] * il1, v3 = o_[j][3] * il1;
        __nv_bfloat162 hv, lv;
        hv.x = __float2bfloat16(v0); hv.y = __float2bfloat16(v1);
        lv.x = __float2bfloat16(v0 - __bfloat162float(hv.x));
        lv.y = __float2bfloat16(v1 - __bfloat162float(hv.y));
        *(__nv_bfloat162*)(Oh + row0 * DMODEL + col) = hv;
        *(__nv_bfloat162*)(Ol + row0 * DMODEL + col) = lv;
        hv.x = __float2bfloat16(v2); hv.y = __float2bfloat16(v3);
        lv.x = __float2bfloat16(v2 - __bfloat162float(hv.x));
        lv.y = __float2bfloat16(v3 - __bfloat162float(hv.y));
        *(__nv_bfloat162*)(Oh + row1 * DMODEL + col) = hv;
        *(__nv_bfloat162*)(Ol + row1 * DMODEL + col) = lv;
    }
}

// ---------------------------------------------------------------------------
extern "C" void kernel_launch(void* const* d_in, const int* in_sizes, int n_in,
                              void* d_out, int out_size)
{
    const float* x      = (const float*)d_in[0];
    const int*   mask   = (const int*)  d_in[1];
    const float* wq     = (const float*)d_in[2];
    const float* bq     = (const float*)d_in[3];
    const float* wk     = (const float*)d_in[4];
    const float* bk     = (const float*)d_in[5];
    const float* wv     = (const float*)d_in[6];
    const float* bv     = (const float*)d_in[7];
    const float* wo     = (const float*)d_in[8];
    const float* bo     = (const float*)d_in[9];
    const float* w1     = (const float*)d_in[10];
    const float* b1     = (const float*)d_in[11];
    const float* w2     = (const float*)d_in[12];
    const float* b2     = (const float*)d_in[13];
    const float* alpha1 = (const float*)d_in[14];
    const float* bias1  = (const float*)d_in[15];
    const float* alpha2 = (const float*)d_in[16];
    const float* bias2  = (const float*)d_in[17];
    float* out = (float*)d_out;

    __nv_bfloat16 *x2h, *x2l, *ath, *atl, *ffh, *ffl, *qkvh, *qkvl;
    __nv_bfloat16 *wqkvh, *wqkvl, *woh, *wol, *w1h, *w1l, *w2h, *w2l;
    float *pxr, *bqkv;
    cudaGetSymbolAddress((void**)&x2h, g_x2h);    cudaGetSymbolAddress((void**)&x2l, g_x2l);
    cudaGetSymbolAddress((void**)&ath, g_ath);    cudaGetSymbolAddress((void**)&atl, g_atl);
    cudaGetSymbolAddress((void**)&ffh, g_ffh);    cudaGetSymbolAddress((void**)&ffl, g_ffl);
    cudaGetSymbolAddress((void**)&qkvh, g_qkvh);  cudaGetSymbolAddress((void**)&qkvl, g_qkvl);
    cudaGetSymbolAddress((void**)&wqkvh, g_wqkvh);cudaGetSymbolAddress((void**)&wqkvl, g_wqkvl);
    cudaGetSymbolAddress((void**)&woh, g_woh);    cudaGetSymbolAddress((void**)&wol, g_wol);
    cudaGetSymbolAddress((void**)&w1h, g_w1h);    cudaGetSymbolAddress((void**)&w1l, g_w1l);
    cudaGetSymbolAddress((void**)&w2h, g_w2h);    cudaGetSymbolAddress((void**)&w2l, g_w2l);
    cudaGetSymbolAddress((void**)&pxr, g_xr);     cudaGetSymbolAddress((void**)&bqkv, g_bqkv);

    cudaFuncSetAttribute(attn_mma_kernel,
                         cudaFuncAttributeMaxDynamicSharedMemorySize, ATT_SMEM);
    cudaFuncSetAttribute(mma_gemm<1>,
                         cudaFuncAttributeMaxDynamicSharedMemorySize, GEMM_SMEM);
    cudaFuncSetAttribute(mma_gemm<2>,
                         cudaFuncAttributeMaxDynamicSharedMemorySize, GEMM_SMEM);
    cudaFuncSetAttribute(mma_gemm<3>,
                         cudaFuncAttributeMaxDynamicSharedMemorySize, GEMM_SMEM);

    const size_t TENS = (size_t)NTOK * DMODEL;

    // 1) fused weight transpose + split (single launch)
    convw_all<<<12288, dim3(32, 8)>>>(wq, wk, wv, wo, w1, w2, bq, bk, bv,
                                      wqkvh, wqkvl, woh, wol,
                                      w1h, w1l, w2h, w2l, bqkv);
    // 2) pre-norm 1 -> split bf16
    norm_split_kernel<<<NTOK, 256>>>(x, alpha1, bias1, x2h, x2l);
    // 3) fused QKV projection -> split bf16 [3][B,H,S,DK] (q pre-scaled 1/8)
    mma_gemm<3><<<dim3(3 * DMODEL / GBN, NTOK / GBM), 256, GEMM_SMEM>>>(
        x2h, x2l, wqkvh, wqkvl, bqkv, nullptr,
        nullptr, qkvh, qkvl, NTOK, 3 * DMODEL, DMODEL);
    // 4) HMMA flash attention -> split bf16
    attn_mma_kernel<<<dim3(SEQ / 128, BATCH * NHEAD), 256, ATT_SMEM>>>(
        qkvh, qkvl, qkvh + TENS, qkvl + TENS, qkvh + 2 * TENS, qkvl + 2 * TENS,
        mask, ath, atl);
    // 5) output projection + residual (fp32)
    mma_gemm<2><<<dim3(DMODEL / GBN, NTOK / GBM), 256, GEMM_SMEM>>>(
        ath, atl, woh, wol, bo, x, pxr, nullptr, nullptr, NTOK, DMODEL, DMODEL);
    // 6) pre-norm 2 -> split bf16
    norm_split_kernel<<<NTOK, 256>>>(pxr, alpha2, bias2, x2h, x2l);
    // 7) FF1 + ReLU -> split bf16
    mma_gemm<1><<<dim3(DFF / GBN, NTOK / GBM), 256, GEMM_SMEM>>>(
        x2h, x2l, w1h, w1l, b1, nullptr, nullptr, ffh, ffl, NTOK, DFF, DMODEL);
    // 8) FF2 + residual -> fp32 out
    mma_gemm<2><<<dim3(DMODEL / GBN, NTOK / GBM), 256, GEMM_SMEM>>>(
        ffh, ffl, w2h, w2l, b2, pxr, out, nullptr, nullptr, NTOK, DMODEL, DFF);
}

// round 6
// speedup vs baseline: 2.7047x; 1.0654x over previous
#include <cuda_runtime.h>
#include <cuda_bf16.h>
#include <math.h>
#include <stdint.h>

// Problem constants
#define BATCH 4
#define SEQ   2048
#define DMODEL 1024
#define NHEAD 16
#define DK    64
#define DFF   4096
#define NTOK  (BATCH * SEQ)   // 8192

// ---------------- scratch (static device globals; no allocation) -----------
__device__ __nv_bfloat16 g_x2h [NTOK * DMODEL];
__device__ __nv_bfloat16 g_x2l [NTOK * DMODEL];
__device__ __nv_bfloat16 g_qkvh[3 * NTOK * DMODEL];  // [3][B,H,S,DK] split
__device__ __nv_bfloat16 g_qkvl[3 * NTOK * DMODEL];
__device__ __nv_bfloat16 g_ath [NTOK * DMODEL];      // attn out split, [B,S,H*DK]
__device__ __nv_bfloat16 g_atl [NTOK * DMODEL];
__device__ float         g_xr  [NTOK * DMODEL];      // residual after attention
__device__ __nv_bfloat16 g_ffh [NTOK * DFF];
__device__ __nv_bfloat16 g_ffl [NTOK * DFF];
// transposed split weights, [N, K] layout; QKV fused to [3072, 1024]
__device__ __nv_bfloat16 g_wqkvh[3*DMODEL*DMODEL], g_wqkvl[3*DMODEL*DMODEL];
__device__ __nv_bfloat16 g_woh[DMODEL*DMODEL], g_wol[DMODEL*DMODEL];
__device__ __nv_bfloat16 g_w1h[DMODEL*DFF],    g_w1l[DMODEL*DFF];
__device__ __nv_bfloat16 g_w2h[DFF*DMODEL],    g_w2l[DFF*DMODEL];
__device__ float         g_bqkv[3*DMODEL];

// ============================ PTX helpers (sm_80-level only) ================
__device__ __forceinline__ uint32_t s2u(const void* p) {
    uint32_t a;
    asm("{ .reg .u64 t; cvta.to.shared.u64 t, %1; cvt.u32.u64 %0, t; }"
        : "=r"(a) : "l"(p));
    return a;
}
__device__ __forceinline__ void cpa16(uint32_t s, const void* g) {
    asm volatile("cp.async.cg.shared.global [%0], [%1], 16;"
                 :: "r"(s), "l"(g) : "memory");
}
__device__ __forceinline__ void cp_commit() {
    asm volatile("cp.async.commit_group;" ::: "memory");
}
template<int N>
__device__ __forceinline__ void cp_wait() {
    asm volatile("cp.async.wait_group %0;" :: "n"(N) : "memory");
}
__device__ __forceinline__ void ldm4(uint32_t* r, uint32_t addr) {
    asm volatile("ldmatrix.sync.aligned.m8n8.x4.shared.b16 {%0,%1,%2,%3}, [%4];"
        : "=r"(r[0]), "=r"(r[1]), "=r"(r[2]), "=r"(r[3]) : "r"(addr));
}
__device__ __forceinline__ void ldm4t(uint32_t* r, uint32_t addr) {
    asm volatile("ldmatrix.sync.aligned.m8n8.x4.trans.shared.b16 {%0,%1,%2,%3}, [%4];"
        : "=r"(r[0]), "=r"(r[1]), "=r"(r[2]), "=r"(r[3]) : "r"(addr));
}
__device__ __forceinline__ void mma16816(float* c, const uint32_t* a,
                                         uint32_t b0, uint32_t b1) {
    asm volatile(
        "mma.sync.aligned.m16n8k16.row.col.f32.bf16.bf16.f32 "
        "{%0,%1,%2,%3}, {%4,%5,%6,%7}, {%8,%9}, {%0,%1,%2,%3};"
        : "+f"(c[0]), "+f"(c[1]), "+f"(c[2]), "+f"(c[3])
        : "r"(a[0]), "r"(a[1]), "r"(a[2]), "r"(a[3]), "r"(b0), "r"(b1));
}
__device__ __forceinline__ uint32_t pk2(float a, float b) {
    __nv_bfloat162 h; h.x = __float2bfloat16(a); h.y = __float2bfloat16(b);
    return *(uint32_t*)&h;
}
__device__ __forceinline__ uint32_t pk2r(float a, float b, float& ra, float& rb) {
    __nv_bfloat162 h; h.x = __float2bfloat16(a); h.y = __float2bfloat16(b);
    ra = a - __bfloat162float(h.x); rb = b - __bfloat162float(h.y);
    return *(uint32_t*)&h;
}

// ---------------------------------------------------------------------------
// Tensor1DNorm -> split-bf16 output (hi/lo).
// ---------------------------------------------------------------------------
__global__ void __launch_bounds__(256) norm_split_kernel(
    const float* __restrict__ x, const float* __restrict__ alpha,
    const float* __restrict__ beta,
    __nv_bfloat16* __restrict__ yh, __nv_bfloat16* __restrict__ yl)
{
    __shared__ float red[16];
    __shared__ float stats[2];
    int row = blockIdx.x;
    int t = threadIdx.x;
    const float4* xr = (const float4*)(x + (size_t)row * DMODEL);
    float4 v = xr[t];
    float s  = v.x + v.y + v.z + v.w;
    float sq = v.x*v.x + v.y*v.y + v.z*v.z + v.w*v.w;
#pragma unroll
    for (int o = 16; o > 0; o >>= 1) {
        s  += __shfl_down_sync(0xffffffffu, s,  o);
        sq += __shfl_down_sync(0xffffffffu, sq, o);
    }
    int warp = t >> 5;
    if ((t & 31) == 0) { red[warp] = s; red[warp + 8] = sq; }
    __syncthreads();
    if (t == 0) {
        float S = 0.f, SQ = 0.f;
#pragma unroll
        for (int w = 0; w < 8; w++) { S += red[w]; SQ += red[w + 8]; }
        float mean = S * (1.0f / DMODEL);
        float var = (SQ - S * mean) * (1.0f / (DMODEL - 1));
        var = fmaxf(var, 0.0f);
        stats[0] = mean; stats[1] = 1.0f / (sqrtf(var) + 1e-6f);
    }
    __syncthreads();
    float mean = stats[0], inv = stats[1];
    float4 a = ((const float4*)alpha)[t];
    float4 b = ((const float4*)beta)[t];
    float o[4];
    o[0] = a.x * (v.x - mean) * inv + b.x;
    o[1] = a.y * (v.y - mean) * inv + b.y;
    o[2] = a.z * (v.z - mean) * inv + b.z;
    o[3] = a.w * (v.w - mean) * inv + b.w;
    __nv_bfloat162 h2[2], l2[2];
#pragma unroll
    for (int q = 0; q < 2; q++) {
        __nv_bfloat16 h0 = __float2bfloat16(o[q*2]);
        __nv_bfloat16 h1 = __float2bfloat16(o[q*2+1]);
        h2[q].x = h0; h2[q].y = h1;
        l2[q].x = __float2bfloat16(o[q*2]   - __bfloat162float(h0));
        l2[q].y = __float2bfloat16(o[q*2+1] - __bfloat162float(h1));
    }
    __nv_bfloat162* ph = (__nv_bfloat162*)(yh + (size_t)row * DMODEL);
    __nv_bfloat162* pl = (__nv_bfloat162*)(yl + (size_t)row * DMODEL);
    ph[t*2] = h2[0]; ph[t*2+1] = h2[1];
    pl[t*2] = l2[0]; pl[t*2+1] = l2[1];
}

// ---------------------------------------------------------------------------
// Fused weight transpose+split for ALL weights in ONE launch.
// ---------------------------------------------------------------------------
__global__ void __launch_bounds__(256) convw_all(
    const float* __restrict__ wq, const float* __restrict__ wk,
    const float* __restrict__ wv, const float* __restrict__ wo,
    const float* __restrict__ w1, const float* __restrict__ w2,
    const float* __restrict__ bq, const float* __restrict__ bk,
    const float* __restrict__ bv,
    __nv_bfloat16* qkvh, __nv_bfloat16* qkvl,
    __nv_bfloat16* oh, __nv_bfloat16* ol,
    __nv_bfloat16* h1, __nv_bfloat16* l1,
    __nv_bfloat16* h2, __nv_bfloat16* l2,
    float* bqkv)
{
    __shared__ float t[32][33];
    int bid = blockIdx.x;
    const float* W; __nv_bfloat16 *hi, *lo;
    int K, N, bx, by;
    size_t nofs = 0;
    if (bid < 4096) {
        int ws = bid >> 10, lt = bid & 1023;
        K = DMODEL; N = DMODEL; bx = lt & 31; by = lt >> 5;
        if (ws == 0)      { W = wq; hi = qkvh; lo = qkvl; nofs = 0; }
        else if (ws == 1) { W = wk; hi = qkvh; lo = qkvl; nofs = DMODEL; }
        else if (ws == 2) { W = wv; hi = qkvh; lo = qkvl; nofs = 2*DMODEL; }
        else              { W = wo; hi = oh;   lo = ol; }
    } else if (bid < 8192) {
        int lt = bid - 4096;
        K = DMODEL; N = DFF; bx = lt & 127; by = lt >> 7;
        W = w1; hi = h1; lo = l1;
    } else {
        int lt = bid - 8192;
        K = DFF; N = DMODEL; bx = lt & 31; by = lt >> 5;
        W = w2; hi = h2; lo = l2;
    }
    int tx = threadIdx.x, ty = threadIdx.y;
    int n0 = bx * 32, k0 = by * 32;
#pragma unroll
    for (int i = 0; i < 4; i++)
        t[ty + 8*i][tx] = W[(size_t)(k0 + ty + 8*i) * N + n0 + tx];
    __syncthreads();
#pragma unroll
    for (int i = 0; i < 4; i++) {
        float v = t[tx][ty + 8*i];
        __nv_bfloat16 h = __float2bfloat16(v);
        size_t idx = (nofs + n0 + ty + 8*i) * K + k0 + tx;
        hi[idx] = h;
        lo[idx] = __float2bfloat16(v - __bfloat162float(h));
    }
    if (bid == 0 && ty == 0) {
#pragma unroll
        for (int i = 0; i < DMODEL / 32; i++) {
            bqkv[i * 32 + tx]              = bq[i * 32 + tx];
            bqkv[DMODEL + i * 32 + tx]     = bk[i * 32 + tx];
            bqkv[2 * DMODEL + i * 32 + tx] = bv[i * 32 + tx];
        }
    }
}

// ---------------------------------------------------------------------------
// Split-bf16 HMMA GEMM. CTA 128x128, K-step 32, 3-stage cp.async pipeline,
// 256 threads (8 warps, 2Mx4N), 2 CTAs/SM (96KB smem, 128 regs).
// ---------------------------------------------------------------------------
#define GBM 128
#define GBN 128
#define GBK 32
#define SOFF_AH 0
#define SOFF_AL 8192
#define SOFF_BH 16384
#define SOFF_BL 24576
#define STAGE_B 32768
#define GEMM_SMEM (3 * STAGE_B)

__device__ __forceinline__ void load_stage32(
    uint32_t sb, const __nv_bfloat16* Ah, const __nv_bfloat16* Al,
    const __nv_bfloat16* Bh, const __nv_bfloat16* Bl,
    int m0, int n0, int k0, int K, int tid)
{
#pragma unroll
    for (int r = 0; r < 2; r++) {
        int ci = tid + r * 256;
        int row = ci >> 2, ch = ci & 3;
        uint32_t sw = (uint32_t)(row * 64 + ((ch ^ ((row >> 1) & 3)) << 4));
        size_t goA = (size_t)(m0 + row) * K + k0 + ch * 8;
        size_t goB = (size_t)(n0 + row) * K + k0 + ch * 8;
        cpa16(sb + SOFF_AH + sw, Ah + goA);
        cpa16(sb + SOFF_AL + sw, Al + goA);
        cpa16(sb + SOFF_BH + sw, Bh + goB);
        cpa16(sb + SOFF_BL + sw, Bl + goB);
    }
}

template<int EPI>
__global__ void __launch_bounds__(256, 2)
mma_gemm(const __nv_bfloat16* __restrict__ Ah, const __nv_bfloat16* __restrict__ Al,
         const __nv_bfloat16* __restrict__ Bh, const __nv_bfloat16* __restrict__ Bl,
         const float* __restrict__ bias, const float* __restrict__ resid,
         float* __restrict__ C,
         __nv_bfloat16* __restrict__ Ch, __nv_bfloat16* __restrict__ Cl,
         int M, int N, int K)
{
    extern __shared__ __align__(1024) char dsm[];
    uint32_t dyn = s2u(dsm);

    int tid = threadIdx.x;
    int wid = tid >> 5, lane = tid & 31;
    int wm = wid & 1, wn = wid >> 1;
    int m0 = blockIdx.y * GBM, n0 = blockIdx.x * GBN;

    float c[4][4][4];
#pragma unroll
    for (int i = 0; i < 4; i++)
#pragma unroll
        for (int j = 0; j < 4; j++)
#pragma unroll
            for (int q = 0; q < 4; q++) c[i][j][q] = 0.f;

    int aRow0 = wm * 64 + (lane & 7) + ((lane >> 3) & 1) * 8;
    int bRow0 = wn * 32 + (lane & 7) + ((lane >> 3) & 1) * 8;
    int cgrp = lane >> 4;

    int nsteps = K / GBK;
    load_stage32(dyn, Ah, Al, Bh, Bl, m0, n0, 0, K, tid);
    cp_commit();
    load_stage32(dyn + STAGE_B, Ah, Al, Bh, Bl, m0, n0, GBK, K, tid);
    cp_commit();

    uint32_t sb = dyn;
    int buf = 0;
    for (int step = 0; step < nsteps; step++) {
        if (step < nsteps - 1) cp_wait<1>(); else cp_wait<0>();
        __syncthreads();
        if (step + 2 < nsteps) {
            int nb = buf + 2; if (nb >= 3) nb -= 3;
            load_stage32(dyn + (uint32_t)nb * STAGE_B, Ah, Al, Bh, Bl,
                         m0, n0, (step + 2) * GBK, K, tid);
            cp_commit();
        }

#pragma unroll
        for (int s = 0; s < 2; s++) {
            int ch = 2 * s + cgrp;
            uint32_t ah[4][4], al[4][4];
#pragma unroll
            for (int i = 0; i < 4; i++) {
                int row = aRow0 + i * 16;
                uint32_t ad = sb + SOFF_AH + row * 64 +
                              ((ch ^ ((row >> 1) & 3)) << 4);
                ldm4(ah[i], ad);
                ldm4(al[i], ad + (SOFF_AL - SOFF_AH));
            }
            uint32_t bh[2][4], bl[2][4];
#pragma unroll
            for (int g = 0; g < 2; g++) {
                int row = bRow0 + g * 16;
                uint32_t bd = sb + SOFF_BH + row * 64 +
                              ((ch ^ ((row >> 1) & 3)) << 4);
                ldm4(bh[g], bd);
                ldm4(bl[g], bd + (SOFF_BL - SOFF_BH));
            }
#pragma unroll
            for (int i = 0; i < 4; i++) {
#pragma unroll
                for (int j = 0; j < 4; j++) {
                    int g = j >> 1, o = j & 1;
                    mma16816(c[i][j], ah[i], bh[g][o], bh[g][o + 2]);
                    mma16816(c[i][j], ah[i], bl[g][o], bl[g][o + 2]);
                    mma16816(c[i][j], al[i], bh[g][o], bh[g][o + 2]);
                }
            }
        }
        buf++; if (buf >= 3) buf = 0;
        sb = dyn + (uint32_t)buf * STAGE_B;
        __syncthreads();
    }

    // ----------------- epilogue -----------------
    int rbase = m0 + wm * 64 + (lane >> 2);
    int cbase = n0 + wn * 32 + (lane & 3) * 2;
#pragma unroll
    for (int i = 0; i < 4; i++) {
#pragma unroll
        for (int j = 0; j < 4; j++) {
            int col = cbase + j * 8;
            float bs0 = bias[col], bs1 = bias[col + 1];
#pragma unroll
            for (int half = 0; half < 2; half++) {
                int r = rbase + i * 16 + half * 8;
                float v0 = c[i][j][half * 2]     + bs0;
                float v1 = c[i][j][half * 2 + 1] + bs1;
                if (EPI == 1) {
                    v0 = fmaxf(v0, 0.f);
                    v1 = fmaxf(v1, 0.f);
                    __nv_bfloat162 hv, lv;
                    hv.x = __float2bfloat16(v0);
                    hv.y = __float2bfloat16(v1);
                    lv.x = __float2bfloat16(v0 - __bfloat162float(hv.x));
                    lv.y = __float2bfloat16(v1 - __bfloat162float(hv.y));
                    *(__nv_bfloat162*)(Ch + (size_t)r * N + col) = hv;
                    *(__nv_bfloat162*)(Cl + (size_t)r * N + col) = lv;
                } else if (EPI == 2) {
                    float2 rr = *(const float2*)(resid + (size_t)r * N + col);
                    float2 o; o.x = v0 + rr.x; o.y = v1 + rr.y;
                    *(float2*)(C + (size_t)r * N + col) = o;
                } else {  // EPI == 3: fused QKV -> split bf16 [3][B,H,S,DK]
                    int t  = col >> 10;
                    int c2 = col & 1023;
                    int h = c2 >> 6, d = c2 & 63;
                    float sc = (t == 0) ? 0.125f : 1.0f;
                    v0 *= sc; v1 *= sc;
                    int bb = r >> 11, sx = r & 2047;
                    size_t idx = ((((size_t)t * BATCH + bb) * NHEAD + h) * SEQ + sx) * DK + d;
                    __nv_bfloat162 hv, lv;
                    hv.x = __float2bfloat16(v0);
                    hv.y = __float2bfloat16(v1);
                    lv.x = __float2bfloat16(v0 - __bfloat162float(hv.x));
                    lv.y = __float2bfloat16(v1 - __bfloat162float(hv.y));
                    *(__nv_bfloat162*)(Ch + idx) = hv;
                    *(__nv_bfloat162*)(Cl + idx) = lv;
                }
            }
        }
    }
}

// ---------------------------------------------------------------------------
// HMMA flash attention, split-bf16. 128 q-rows/block, 8 warps, 64-key stages
// double-buffered. Packed-P aliases the score registers (sc) to stay <=128
// regs -> 2 CTAs/SM.
// ---------------------------------------------------------------------------
#define AQH 0
#define AQL 16384
#define ASTG 32768
#define ASTRIDE 32768
#define AKH 0
#define AKL 8192
#define AVH 16384
#define AVL 24576
#define AMSK 98304
#define ATT_SMEM (98304 + 512)

__device__ __forceinline__ void attn_load_kv(
    uint32_t base, int buf, const __nv_bfloat16* Kph, const __nv_bfloat16* Klp,
    const __nv_bfloat16* Vph, const __nv_bfloat16* Vlp,
    const int* mp, int k0, int tid)
{
    uint32_t sb = base + ASTG + (uint32_t)buf * ASTRIDE;
#pragma unroll
    for (int r = 0; r < 2; r++) {
        int ci = tid + r * 256;
        int row = ci >> 3, ch = ci & 7;
        uint32_t sw = (uint32_t)(row * 128 + ((ch ^ (row & 7)) << 4));
        size_t go = (size_t)(k0 + row) * DK + ch * 8;
        cpa16(sb + AKH + sw, Kph + go);
        cpa16(sb + AKL + sw, Klp + go);
        cpa16(sb + AVH + sw, Vph + go);
        cpa16(sb + AVL + sw, Vlp + go);
    }
    if (tid < 16)
        cpa16(base + AMSK + (uint32_t)buf * 256 + tid * 16, mp + k0 + tid * 4);
}

__global__ void __launch_bounds__(256, 2) attn_mma_kernel(
    const __nv_bfloat16* __restrict__ Qh, const __nv_bfloat16* __restrict__ Ql,
    const __nv_bfloat16* __restrict__ Kh, const __nv_bfloat16* __restrict__ Kl,
    const __nv_bfloat16* __restrict__ Vh, const __nv_bfloat16* __restrict__ Vl,
    const int* __restrict__ mask,
    __nv_bfloat16* __restrict__ Oh, __nv_bfloat16* __restrict__ Ol)
{
    extern __shared__ __align__(1024) char attsm[];
    uint32_t base = s2u(attsm);

    int tid = threadIdx.x;
    int wid = tid >> 5, lane = tid & 31;
    int bh = blockIdx.y;
    int b = bh >> 4, hh = bh & 15;
    int q0 = blockIdx.x * 128;

    const __nv_bfloat16* Qph = Qh + ((size_t)bh * SEQ + q0) * DK;
    const __nv_bfloat16* Qlp = Ql + ((size_t)bh * SEQ + q0) * DK;
    const __nv_bfloat16* Kph = Kh + (size_t)bh * SEQ * DK;
    const __nv_bfloat16* Klp = Kl + (size_t)bh * SEQ * DK;
    const __nv_bfloat16* Vph = Vh + (size_t)bh * SEQ * DK;
    const __nv_bfloat16* Vlp = Vl + (size_t)bh * SEQ * DK;
    const int* mp = mask + b * SEQ;

#pragma unroll
    for (int r = 0; r < 4; r++) {
        int ci = tid + r * 256;
        int row = ci >> 3, ch = ci & 7;
        uint32_t sw = (uint32_t)(row * 128 + ((ch ^ (row & 7)) << 4));
        size_t go = (size_t)row * DK + ch * 8;
        cpa16(base + AQH + sw, Qph + go);
        cpa16(base + AQL + sw, Qlp + go);
    }
    attn_load_kv(base, 0, Kph, Klp, Vph, Vlp, mp, 0, tid);
    cp_commit();

    uint32_t qh[4][4], ql[4][4];
    float m0v = -INFINITY, m1v = -INFINITY, l0v = 0.f, l1v = 0.f;
    float o_[8][4];
#pragma unroll
    for (int j = 0; j < 8; j++)
#pragma unroll
        for (int q = 0; q < 4; q++) o_[j][q] = 0.f;

    const int NKB = SEQ / 64;   // 32
    for (int t = 0; t < NKB; t++) {
        if (t + 1 < NKB) {
            attn_load_kv(base, (t + 1) & 1, Kph, Klp, Vph, Vlp, mp,
                         (t + 1) * 64, tid);
            cp_commit();
            cp_wait<1>();
        } else {
            cp_wait<0>();
        }
        __syncthreads();

        if (t == 0) {
#pragma unroll
            for (int c2 = 0; c2 < 4; c2++) {
                int row = wid * 16 + (lane & 15);
                int ch = 2 * c2 + (lane >> 4);
                uint32_t ad = base + AQH + row * 128 + ((ch ^ (row & 7)) << 4);
                ldm4(qh[c2], ad);
                ldm4(ql[c2], ad + (AQL - AQH));
            }
        }

        uint32_t sb = base + ASTG + (uint32_t)(t & 1) * ASTRIDE;

        float sc[8][4];
#pragma unroll
        for (int j = 0; j < 8; j++)
#pragma unroll
            for (int q = 0; q < 4; q++) sc[j][q] = 0.f;
#pragma unroll
        for (int c2 = 0; c2 < 4; c2++) {
            uint32_t kh[4][4], kl[4][4];
#pragma unroll
            for (int g = 0; g < 4; g++) {
                int row = g * 16 + (lane & 7) + ((lane >> 3) & 1) * 8;
                int ch = 2 * c2 + (lane >> 4);
                uint32_t ad = sb + AKH + row * 128 + ((ch ^ (row & 7)) << 4);
                ldm4(kh[g], ad);
                ldm4(kl[g], ad + (AKL - AKH));
            }
#pragma unroll
            for (int j = 0; j < 8; j++) {
                int g = j >> 1, o = j & 1;
                mma16816(sc[j], qh[c2], kh[g][o], kh[g][o + 2]);
                mma16816(sc[j], qh[c2], kl[g][o], kl[g][o + 2]);
                mma16816(sc[j], ql[c2], kh[g][o], kh[g][o + 2]);
            }
        }

        const int* msk = (const int*)(attsm + AMSK + (t & 1) * 256);
        int cc = (lane & 3) * 2;
#pragma unroll
        for (int j = 0; j < 8; j++) {
            int mv0 = msk[j * 8 + cc], mv1 = msk[j * 8 + cc + 1];
            if (mv0 == 0) { sc[j][0] = -1e9f; sc[j][2] = -1e9f; }
            if (mv1 == 0) { sc[j][1] = -1e9f; sc[j][3] = -1e9f; }
        }

        float mx0 = -INFINITY, mx1 = -INFINITY;
#pragma unroll
        for (int j = 0; j < 8; j++) {
            mx0 = fmaxf(mx0, fmaxf(sc[j][0], sc[j][1]));
            mx1 = fmaxf(mx1, fmaxf(sc[j][2], sc[j][3]));
        }
        mx0 = fmaxf(mx0, __shfl_xor_sync(0xffffffffu, mx0, 1));
        mx0 = fmaxf(mx0, __shfl_xor_sync(0xffffffffu, mx0, 2));
        mx1 = fmaxf(mx1, __shfl_xor_sync(0xffffffffu, mx1, 1));
        mx1 = fmaxf(mx1, __shfl_xor_sync(0xffffffffu, mx1, 2));
        float mn0 = fmaxf(m0v, mx0), mn1 = fmaxf(m1v, mx1);
        float cor0 = __expf(m0v - mn0), cor1 = __expf(m1v - mn1);

        // packed P aliases sc's registers: sc[j] = {hi01, hi23, lo01, lo23}
        float sum0 = 0.f, sum1 = 0.f;
        uint32_t* pkd = (uint32_t*)sc;
#pragma unroll
        for (int j = 0; j < 8; j++) {
            float p0 = __expf(sc[j][0] - mn0);
            float p1 = __expf(sc[j][1] - mn0);
            float p2 = __expf(sc[j][2] - mn1);
            float p3 = __expf(sc[j][3] - mn1);
            sum0 += p0 + p1; sum1 += p2 + p3;
            float r0, r1, r2, r3;
            uint32_t h01 = pk2r(p0, p1, r0, r1);
            uint32_t h23 = pk2r(p2, p3, r2, r3);
            uint32_t l01 = pk2(r0, r1);
            uint32_t l23 = pk2(r2, r3);
            pkd[j * 4 + 0] = h01;
            pkd[j * 4 + 1] = h23;
            pkd[j * 4 + 2] = l01;
            pkd[j * 4 + 3] = l23;
        }
        sum0 += __shfl_xor_sync(0xffffffffu, sum0, 1);
        sum0 += __shfl_xor_sync(0xffffffffu, sum0, 2);
        sum1 += __shfl_xor_sync(0xffffffffu, sum1, 1);
        sum1 += __shfl_xor_sync(0xffffffffu, sum1, 2);
        l0v = l0v * cor0 + sum0;
        l1v = l1v * cor1 + sum1;
        m0v = mn0; m1v = mn1;
#pragma unroll
        for (int j = 0; j < 8; j++) {
            o_[j][0] *= cor0; o_[j][1] *= cor0;
            o_[j][2] *= cor1; o_[j][3] *= cor1;
        }

#pragma unroll
        for (int t2 = 0; t2 < 4; t2++) {
            uint32_t pah[4] = { pkd[(2*t2)*4 + 0], pkd[(2*t2)*4 + 1],
                                pkd[(2*t2+1)*4 + 0], pkd[(2*t2+1)*4 + 1] };
            uint32_t pal[4] = { pkd[(2*t2)*4 + 2], pkd[(2*t2)*4 + 3],
                                pkd[(2*t2+1)*4 + 2], pkd[(2*t2+1)*4 + 3] };
            uint32_t vh[4][4], vl[4][4];
#pragma unroll
            for (int g = 0; g < 4; g++) {
                int row = t2 * 16 + (lane & 7) + ((lane >> 3) & 1) * 8;
                int ch = 2 * g + (lane >> 4);
                uint32_t ad = sb + AVH + row * 128 + ((ch ^ (row & 7)) << 4);
                ldm4t(vh[g], ad);
                ldm4t(vl[g], ad + (AVL - AVH));
            }
#pragma unroll
            for (int j = 0; j < 8; j++) {
                int g = j >> 1, h2 = j & 1;
                mma16816(o_[j], pah, vh[g][2*h2], vh[g][2*h2 + 1]);
                mma16816(o_[j], pah, vl[g][2*h2], vl[g][2*h2 + 1]);
                mma16816(o_[j], pal, vh[g][2*h2], vh[g][2*h2 + 1]);
            }
        }
        __syncthreads();
    }

    float il0 = 1.0f / l0v, il1 = 1.0f / l1v;
    size_t row0 = (size_t)b * SEQ + q0 + wid * 16 + (lane >> 2);
    size_t row1 = row0 + 8;
    int cb = hh * DK + (lane & 3) * 2;
#pragma unroll
    for (int j = 0; j < 8; j++) {
        int col = cb + j * 8;
        float v0 = o_[j][0] * il0, v1 = o_[j][1] * il0;
        float v2 = o_[j][2] * il1, v3 = o_[j][3] * il1;
        __nv_bfloat162 hv, lv;
        hv.x = __float2bfloat16(v0); hv.y = __float2bfloat16(v1);
        lv.x = __float2bfloat16(v0 - __bfloat162float(hv.x));
        lv.y = __float2bfloat16(v1 - __bfloat162float(hv.y));
        *(__nv_bfloat162*)(Oh + row0 * DMODEL + col) = hv;
        *(__nv_bfloat162*)(Ol + row0 * DMODEL + col) = lv;
        hv.x = __float2bfloat16(v2); hv.y = __float2bfloat16(v3);
        lv.x = __float2bfloat16(v2 - __bfloat162float(hv.x));
        lv.y = __float2bfloat16(v3 - __bfloat162float(hv.y));
        *(__nv_bfloat162*)(Oh + row1 * DMODEL + col) = hv;
        *(__nv_bfloat162*)(Ol + row1 * DMODEL + col) = lv;
    }
}

// ---------------------------------------------------------------------------
extern "C" void kernel_launch(void* const* d_in, const int* in_sizes, int n_in,
                              void* d_out, int out_size)
{
    const float* x      = (const float*)d_in[0];
    const int*   mask   = (const int*)  d_in[1];
    const float* wq     = (const float*)d_in[2];
    const float* bq     = (const float*)d_in[3];
    const float* wk     = (const float*)d_in[4];
    const float* bk     = (const float*)d_in[5];
    const float* wv     = (const float*)d_in[6];
    const float* bv     = (const float*)d_in[7];
    const float* wo     = (const float*)d_in[8];
    const float* bo     = (const float*)d_in[9];
    const float* w1     = (const float*)d_in[10];
    const float* b1     = (const float*)d_in[11];
    const float* w2     = (const float*)d_in[12];
    const float* b2     = (const float*)d_in[13];
    const float* alpha1 = (const float*)d_in[14];
    const float* bias1  = (const float*)d_in[15];
    const float* alpha2 = (const float*)d_in[16];
    const float* bias2  = (const float*)d_in[17];
    float* out = (float*)d_out;

    __nv_bfloat16 *x2h, *x2l, *ath, *atl, *ffh, *ffl, *qkvh, *qkvl;
    __nv_bfloat16 *wqkvh, *wqkvl, *woh, *wol, *w1h, *w1l, *w2h, *w2l;
    float *pxr, *bqkv;
    cudaGetSymbolAddress((void**)&x2h, g_x2h);    cudaGetSymbolAddress((void**)&x2l, g_x2l);
    cudaGetSymbolAddress((void**)&ath, g_ath);    cudaGetSymbolAddress((void**)&atl, g_atl);
    cudaGetSymbolAddress((void**)&ffh, g_ffh);    cudaGetSymbolAddress((void**)&ffl, g_ffl);
    cudaGetSymbolAddress((void**)&qkvh, g_qkvh);  cudaGetSymbolAddress((void**)&qkvl, g_qkvl);
    cudaGetSymbolAddress((void**)&wqkvh, g_wqkvh);cudaGetSymbolAddress((void**)&wqkvl, g_wqkvl);
    cudaGetSymbolAddress((void**)&woh, g_woh);    cudaGetSymbolAddress((void**)&wol, g_wol);
    cudaGetSymbolAddress((void**)&w1h, g_w1h);    cudaGetSymbolAddress((void**)&w1l, g_w1l);
    cudaGetSymbolAddress((void**)&w2h, g_w2h);    cudaGetSymbolAddress((void**)&w2l, g_w2l);
    cudaGetSymbolAddress((void**)&pxr, g_xr);     cudaGetSymbolAddress((void**)&bqkv, g_bqkv);

    cudaFuncSetAttribute(attn_mma_kernel,
                         cudaFuncAttributeMaxDynamicSharedMemorySize, ATT_SMEM);
    cudaFuncSetAttribute(mma_gemm<1>,
                         cudaFuncAttributeMaxDynamicSharedMemorySize, GEMM_SMEM);
    cudaFuncSetAttribute(mma_gemm<2>,
                         cudaFuncAttributeMaxDynamicSharedMemorySize, GEMM_SMEM);
    cudaFuncSetAttribute(mma_gemm<3>,
                         cudaFuncAttributeMaxDynamicSharedMemorySize, GEMM_SMEM);

    const size_t TENS = (size_t)NTOK * DMODEL;

    convw_all<<<12288, dim3(32, 8)>>>(wq, wk, wv, wo, w1, w2, bq, bk, bv,
                                      wqkvh, wqkvl, woh, wol,
                                      w1h, w1l, w2h, w2l, bqkv);
    norm_split_kernel<<<NTOK, 256>>>(x, alpha1, bias1, x2h, x2l);
    mma_gemm<3><<<dim3(3 * DMODEL / GBN, NTOK / GBM), 256, GEMM_SMEM>>>(
        x2h, x2l, wqkvh, wqkvl, bqkv, nullptr,
        nullptr, qkvh, qkvl, NTOK, 3 * DMODEL, DMODEL);
    attn_mma_kernel<<<dim3(SEQ / 128, BATCH * NHEAD), 256, ATT_SMEM>>>(
        qkvh, qkvl, qkvh + TENS, qkvl + TENS, qkvh + 2 * TENS, qkvl + 2 * TENS,
        mask, ath, atl);
    mma_gemm<2><<<dim3(DMODEL / GBN, NTOK / GBM), 256, GEMM_SMEM>>>(
        ath, atl, woh, wol, bo, x, pxr, nullptr, nullptr, NTOK, DMODEL, DMODEL);
    norm_split_kernel<<<NTOK, 256>>>(pxr, alpha2, bias2, x2h, x2l);
    mma_gemm<1><<<dim3(DFF / GBN, NTOK / GBM), 256, GEMM_SMEM>>>(
        x2h, x2l, w1h, w1l, b1, nullptr, nullptr, ffh, ffl, NTOK, DFF, DMODEL);
    mma_gemm<2><<<dim3(DMODEL / GBN, NTOK / GBM), 256, GEMM_SMEM>>>(
        ffh, ffl, w2h, w2l, b2, pxr, out, nullptr, nullptr, NTOK, DMODEL, DFF);
}

// round 7
// speedup vs baseline: 3.7428x; 1.3838x over previous
#include <cuda_runtime.h>
#include <cuda_fp16.h>
#include <math.h>
#include <stdint.h>

// Problem constants
#define BATCH 4
#define SEQ   2048
#define DMODEL 1024
#define NHEAD 16
#define DK    64
#define DFF   4096
#define NTOK  (BATCH * SEQ)   // 8192

// ---------------- scratch (static device globals; no allocation) -----------
__device__ __half g_x2h [NTOK * DMODEL];
__device__ __half g_x2l [NTOK * DMODEL];
__device__ __half g_qhh [NTOK * DMODEL];   // Q split, pre-scaled 1/8, [B,H,S,DK]
__device__ __half g_qll [NTOK * DMODEL];
__device__ __half g_kk  [NTOK * DMODEL];   // K single fp16
__device__ __half g_vv  [NTOK * DMODEL];   // V single fp16
__device__ __half g_ath [NTOK * DMODEL];   // attn out split, [B,S,H*DK]
__device__ __half g_atl [NTOK * DMODEL];
__device__ float  g_xr  [NTOK * DMODEL];
__device__ __half g_ffh [NTOK * DFF];
__device__ __half g_ffl [NTOK * DFF];
// transposed single-fp16 weights, [N, K] layout; QKV fused to [3072, 1024]
__device__ __half g_wqkv[3*DMODEL*DMODEL];
__device__ __half g_wo[DMODEL*DMODEL];
__device__ __half g_w1[DMODEL*DFF];
__device__ __half g_w2[DFF*DMODEL];
__device__ float  g_bqkv[3*DMODEL];

// ============================ PTX helpers (sm_80-level only) ================
__device__ __forceinline__ uint32_t s2u(const void* p) {
    uint32_t a;
    asm("{ .reg .u64 t; cvta.to.shared.u64 t, %1; cvt.u32.u64 %0, t; }"
        : "=r"(a) : "l"(p));
    return a;
}
__device__ __forceinline__ void cpa16(uint32_t s, const void* g) {
    asm volatile("cp.async.cg.shared.global [%0], [%1], 16;"
                 :: "r"(s), "l"(g) : "memory");
}
__device__ __forceinline__ void cp_commit() {
    asm volatile("cp.async.commit_group;" ::: "memory");
}
template<int N>
__device__ __forceinline__ void cp_wait() {
    asm volatile("cp.async.wait_group %0;" :: "n"(N) : "memory");
}
__device__ __forceinline__ void ldm4(uint32_t* r, uint32_t addr) {
    asm volatile("ldmatrix.sync.aligned.m8n8.x4.shared.b16 {%0,%1,%2,%3}, [%4];"
        : "=r"(r[0]), "=r"(r[1]), "=r"(r[2]), "=r"(r[3]) : "r"(addr));
}
__device__ __forceinline__ void ldm4t(uint32_t* r, uint32_t addr) {
    asm volatile("ldmatrix.sync.aligned.m8n8.x4.trans.shared.b16 {%0,%1,%2,%3}, [%4];"
        : "=r"(r[0]), "=r"(r[1]), "=r"(r[2]), "=r"(r[3]) : "r"(addr));
}
__device__ __forceinline__ void mma16816(float* c, const uint32_t* a,
                                         uint32_t b0, uint32_t b1) {
    asm volatile(
        "mma.sync.aligned.m16n8k16.row.col.f32.f16.f16.f32 "
        "{%0,%1,%2,%3}, {%4,%5,%6,%7}, {%8,%9}, {%0,%1,%2,%3};"
        : "+f"(c[0]), "+f"(c[1]), "+f"(c[2]), "+f"(c[3])
        : "r"(a[0]), "r"(a[1]), "r"(a[2]), "r"(a[3]), "r"(b0), "r"(b1));
}
__device__ __forceinline__ uint32_t hpk2(float a, float b) {
    __half2 h; h.x = __float2half(a); h.y = __float2half(b);
    return *(uint32_t*)&h;
}
__device__ __forceinline__ uint32_t hpk2r(float a, float b, float& ra, float& rb) {
    __half2 h; h.x = __float2half(a); h.y = __float2half(b);
    ra = a - __half2float(h.x); rb = b - __half2float(h.y);
    return *(uint32_t*)&h;
}

// ---------------------------------------------------------------------------
// Tensor1DNorm -> split-fp16 output (hi/lo).
// ---------------------------------------------------------------------------
__global__ void __launch_bounds__(256) norm_split_kernel(
    const float* __restrict__ x, const float* __restrict__ alpha,
    const float* __restrict__ beta,
    __half* __restrict__ yh, __half* __restrict__ yl)
{
    __shared__ float red[16];
    __shared__ float stats[2];
    int row = blockIdx.x;
    int t = threadIdx.x;
    const float4* xr = (const float4*)(x + (size_t)row * DMODEL);
    float4 v = xr[t];
    float s  = v.x + v.y + v.z + v.w;
    float sq = v.x*v.x + v.y*v.y + v.z*v.z + v.w*v.w;
#pragma unroll
    for (int o = 16; o > 0; o >>= 1) {
        s  += __shfl_down_sync(0xffffffffu, s,  o);
        sq += __shfl_down_sync(0xffffffffu, sq, o);
    }
    int warp = t >> 5;
    if ((t & 31) == 0) { red[warp] = s; red[warp + 8] = sq; }
    __syncthreads();
    if (t == 0) {
        float S = 0.f, SQ = 0.f;
#pragma unroll
        for (int w = 0; w < 8; w++) { S += red[w]; SQ += red[w + 8]; }
        float mean = S * (1.0f / DMODEL);
        float var = (SQ - S * mean) * (1.0f / (DMODEL - 1));
        var = fmaxf(var, 0.0f);
        stats[0] = mean; stats[1] = 1.0f / (sqrtf(var) + 1e-6f);
    }
    __syncthreads();
    float mean = stats[0], inv = stats[1];
    float4 a = ((const float4*)alpha)[t];
    float4 b = ((const float4*)beta)[t];
    float o[4];
    o[0] = a.x * (v.x - mean) * inv + b.x;
    o[1] = a.y * (v.y - mean) * inv + b.y;
    o[2] = a.z * (v.z - mean) * inv + b.z;
    o[3] = a.w * (v.w - mean) * inv + b.w;
    uint32_t h[2], l[2];
#pragma unroll
    for (int q = 0; q < 2; q++) {
        float r0, r1;
        h[q] = hpk2r(o[q*2], o[q*2+1], r0, r1);
        l[q] = hpk2(r0, r1);
    }
    uint32_t* ph = (uint32_t*)(yh + (size_t)row * DMODEL) + t * 2;
    uint32_t* pl = (uint32_t*)(yl + (size_t)row * DMODEL) + t * 2;
    ph[0] = h[0]; ph[1] = h[1];
    pl[0] = l[0]; pl[1] = l[1];
}

// ---------------------------------------------------------------------------
// Fused weight transpose + fp16 convert for ALL weights in ONE launch.
// ---------------------------------------------------------------------------
__global__ void __launch_bounds__(256) convw_all(
    const float* __restrict__ wq, const float* __restrict__ wk,
    const float* __restrict__ wv, const float* __restrict__ wo,
    const float* __restrict__ w1, const float* __restrict__ w2,
    const float* __restrict__ bq, const float* __restrict__ bk,
    const float* __restrict__ bv,
    __half* qkv, __half* ow, __half* w1o, __half* w2o, float* bqkv)
{
    __shared__ float t[32][33];
    int bid = blockIdx.x;
    const float* W; __half* dst;
    int K, N, bx, by;
    size_t nofs = 0;
    if (bid < 4096) {
        int ws = bid >> 10, lt = bid & 1023;
        K = DMODEL; N = DMODEL; bx = lt & 31; by = lt >> 5;
        if (ws == 0)      { W = wq; dst = qkv; nofs = 0; }
        else if (ws == 1) { W = wk; dst = qkv; nofs = DMODEL; }
        else if (ws == 2) { W = wv; dst = qkv; nofs = 2*DMODEL; }
        else              { W = wo; dst = ow; }
    } else if (bid < 8192) {
        int lt = bid - 4096;
        K = DMODEL; N = DFF; bx = lt & 127; by = lt >> 7;
        W = w1; dst = w1o;
    } else {
        int lt = bid - 8192;
        K = DFF; N = DMODEL; bx = lt & 31; by = lt >> 5;
        W = w2; dst = w2o;
    }
    int tx = threadIdx.x, ty = threadIdx.y;
    int n0 = bx * 32, k0 = by * 32;
#pragma unroll
    for (int i = 0; i < 4; i++)
        t[ty + 8*i][tx] = W[(size_t)(k0 + ty + 8*i) * N + n0 + tx];
    __syncthreads();
#pragma unroll
    for (int i = 0; i < 4; i++) {
        float v = t[tx][ty + 8*i];
        dst[(nofs + n0 + ty + 8*i) * K + k0 + tx] = __float2half(v);
    }
    if (bid == 0 && ty == 0) {
#pragma unroll
        for (int i = 0; i < DMODEL / 32; i++) {
            bqkv[i * 32 + tx]              = bq[i * 32 + tx];
            bqkv[DMODEL + i * 32 + tx]     = bk[i * 32 + tx];
            bqkv[2 * DMODEL + i * 32 + tx] = bv[i * 32 + tx];
        }
    }
}

// ---------------------------------------------------------------------------
// Split-fp16 HMMA GEMM (2 products: Ah*B + Al*B). CTA 128x128, K-step 32,
// 3-stage cp.async pipeline, 256 threads (8 warps, 2Mx4N), 2 CTAs/SM.
// EPI: 1 = +bias, relu, split fp16 (FF1)
//      2 = +bias +resid, fp32 (O-proj / FF2)
//      3 = fused QKV: Q->split fp16 scaled 1/8, K/V->single fp16 [B,H,S,DK]
// ---------------------------------------------------------------------------
#define GBM 128
#define GBN 128
#define GBK 32
#define SOFF_AH 0
#define SOFF_AL 8192
#define SOFF_B  16384
#define STAGE_B 24576
#define GEMM_SMEM (3 * STAGE_B)

__device__ __forceinline__ void load_stage32(
    uint32_t sb, const __half* Ah, const __half* Al, const __half* B,
    int m0, int n0, int k0, int K, int tid)
{
#pragma unroll
    for (int r = 0; r < 2; r++) {
        int ci = tid + r * 256;
        int row = ci >> 2, ch = ci & 3;
        uint32_t sw = (uint32_t)(row * 64 + ((ch ^ ((row >> 1) & 3)) << 4));
        size_t goA = (size_t)(m0 + row) * K + k0 + ch * 8;
        size_t goB = (size_t)(n0 + row) * K + k0 + ch * 8;
        cpa16(sb + SOFF_AH + sw, Ah + goA);
        cpa16(sb + SOFF_AL + sw, Al + goA);
        cpa16(sb + SOFF_B  + sw, B  + goB);
    }
}

template<int EPI>
__global__ void __launch_bounds__(256, 2)
mma_gemm(const __half* __restrict__ Ah, const __half* __restrict__ Al,
         const __half* __restrict__ B,
         const float* __restrict__ bias, const float* __restrict__ resid,
         float* __restrict__ C,
         __half* __restrict__ Ch, __half* __restrict__ Cl,
         __half* __restrict__ Pk, __half* __restrict__ Pv,
         int M, int N, int K)
{
    extern __shared__ __align__(1024) char dsm[];
    uint32_t dyn = s2u(dsm);

    int tid = threadIdx.x;
    int wid = tid >> 5, lane = tid & 31;
    int wm = wid & 1, wn = wid >> 1;
    int m0 = blockIdx.y * GBM, n0 = blockIdx.x * GBN;

    float c[4][4][4];
#pragma unroll
    for (int i = 0; i < 4; i++)
#pragma unroll
        for (int j = 0; j < 4; j++)
#pragma unroll
            for (int q = 0; q < 4; q++) c[i][j][q] = 0.f;

    int aRow0 = wm * 64 + (lane & 7) + ((lane >> 3) & 1) * 8;
    int bRow0 = wn * 32 + (lane & 7) + ((lane >> 3) & 1) * 8;
    int cgrp = lane >> 4;

    int nsteps = K / GBK;
    load_stage32(dyn, Ah, Al, B, m0, n0, 0, K, tid);
    cp_commit();
    load_stage32(dyn + STAGE_B, Ah, Al, B, m0, n0, GBK, K, tid);
    cp_commit();

    uint32_t sb = dyn;
    int buf = 0;
    for (int step = 0; step < nsteps; step++) {
        if (step < nsteps - 1) cp_wait<1>(); else cp_wait<0>();
        __syncthreads();
        if (step + 2 < nsteps) {
            int nb = buf + 2; if (nb >= 3) nb -= 3;
            load_stage32(dyn + (uint32_t)nb * STAGE_B, Ah, Al, B,
                         m0, n0, (step + 2) * GBK, K, tid);
            cp_commit();
        }

#pragma unroll
        for (int s = 0; s < 2; s++) {
            int ch = 2 * s + cgrp;
            uint32_t ah[4][4], al[4][4];
#pragma unroll
            for (int i = 0; i < 4; i++) {
                int row = aRow0 + i * 16;
                uint32_t ad = sb + SOFF_AH + row * 64 +
                              ((ch ^ ((row >> 1) & 3)) << 4);
                ldm4(ah[i], ad);
                ldm4(al[i], ad + (SOFF_AL - SOFF_AH));
            }
            uint32_t bh[2][4];
#pragma unroll
            for (int g = 0; g < 2; g++) {
                int row = bRow0 + g * 16;
                uint32_t bd = sb + SOFF_B + row * 64 +
                              ((ch ^ ((row >> 1) & 3)) << 4);
                ldm4(bh[g], bd);
            }
#pragma unroll
            for (int i = 0; i < 4; i++) {
#pragma unroll
                for (int j = 0; j < 4; j++) {
                    int g = j >> 1, o = j & 1;
                    mma16816(c[i][j], ah[i], bh[g][o], bh[g][o + 2]);
                    mma16816(c[i][j], al[i], bh[g][o], bh[g][o + 2]);
                }
            }
        }
        buf++; if (buf >= 3) buf = 0;
        sb = dyn + (uint32_t)buf * STAGE_B;
        __syncthreads();
    }

    // ----------------- epilogue -----------------
    int rbase = m0 + wm * 64 + (lane >> 2);
    int cbase = n0 + wn * 32 + (lane & 3) * 2;
#pragma unroll
    for (int i = 0; i < 4; i++) {
#pragma unroll
        for (int j = 0; j < 4; j++) {
            int col = cbase + j * 8;
            float bs0 = bias[col], bs1 = bias[col + 1];
#pragma unroll
            for (int half = 0; half < 2; half++) {
                int r = rbase + i * 16 + half * 8;
                float v0 = c[i][j][half * 2]     + bs0;
                float v1 = c[i][j][half * 2 + 1] + bs1;
                if (EPI == 1) {
                    v0 = fmaxf(v0, 0.f);
                    v1 = fmaxf(v1, 0.f);
                    float r0, r1;
                    uint32_t hv = hpk2r(v0, v1, r0, r1);
                    uint32_t lv = hpk2(r0, r1);
                    *(uint32_t*)(Ch + (size_t)r * N + col) = hv;
                    *(uint32_t*)(Cl + (size_t)r * N + col) = lv;
                } else if (EPI == 2) {
                    float2 rr = *(const float2*)(resid + (size_t)r * N + col);
                    float2 o; o.x = v0 + rr.x; o.y = v1 + rr.y;
                    *(float2*)(C + (size_t)r * N + col) = o;
                } else {  // EPI == 3: fused QKV
                    int t  = col >> 10;        // 0=q,1=k,2=v
                    int c2 = col & 1023;
                    int h = c2 >> 6, d = c2 & 63;
                    int bb = r >> 11, sx = r & 2047;
                    size_t idx = (((size_t)bb * NHEAD + h) * SEQ + sx) * DK + d;
                    if (t == 0) {
                        v0 *= 0.125f; v1 *= 0.125f;
                        float r0, r1;
                        uint32_t hv = hpk2r(v0, v1, r0, r1);
                        uint32_t lv = hpk2(r0, r1);
                        *(uint32_t*)(Ch + idx) = hv;
                        *(uint32_t*)(Cl + idx) = lv;
                    } else if (t == 1) {
                        *(uint32_t*)(Pk + idx) = hpk2(v0, v1);
                    } else {
                        *(uint32_t*)(Pv + idx) = hpk2(v0, v1);
                    }
                }
            }
        }
    }
}

// ---------------------------------------------------------------------------
// HMMA flash attention, fp16. Q/P split (2 products), K/V single fp16.
// 128 q-rows/block, 8 warps, 64-key stages double-buffered, 2 CTAs/SM.
// ---------------------------------------------------------------------------
#define AQH 0
#define AQL 16384
#define ASTG 32768
#define ASTRIDE 16384
#define AK 0
#define AV 8192
#define AMSK 65536
#define ATT_SMEM (65536 + 512)

__device__ __forceinline__ void attn_load_kv(
    uint32_t base, int buf, const __half* Kp, const __half* Vp,
    const int* mp, int k0, int tid)
{
    uint32_t sb = base + ASTG + (uint32_t)buf * ASTRIDE;
#pragma unroll
    for (int r = 0; r < 2; r++) {
        int ci = tid + r * 256;
        int row = ci >> 3, ch = ci & 7;
        uint32_t sw = (uint32_t)(row * 128 + ((ch ^ (row & 7)) << 4));
        size_t go = (size_t)(k0 + row) * DK + ch * 8;
        cpa16(sb + AK + sw, Kp + go);
        cpa16(sb + AV + sw, Vp + go);
    }
    if (tid < 16)
        cpa16(base + AMSK + (uint32_t)buf * 256 + tid * 16, mp + k0 + tid * 4);
}

__global__ void __launch_bounds__(256, 2) attn_mma_kernel(
    const __half* __restrict__ Qh, const __half* __restrict__ Ql,
    const __half* __restrict__ Kg, const __half* __restrict__ Vg,
    const int* __restrict__ mask,
    __half* __restrict__ Oh, __half* __restrict__ Ol)
{
    extern __shared__ __align__(1024) char attsm[];
    uint32_t base = s2u(attsm);

    int tid = threadIdx.x;
    int wid = tid >> 5, lane = tid & 31;
    int bh = blockIdx.y;
    int b = bh >> 4, hh = bh & 15;
    int q0 = blockIdx.x * 128;

    const __half* Qph = Qh + ((size_t)bh * SEQ + q0) * DK;
    const __half* Qlp = Ql + ((size_t)bh * SEQ + q0) * DK;
    const __half* Kp  = Kg + (size_t)bh * SEQ * DK;
    const __half* Vp  = Vg + (size_t)bh * SEQ * DK;
    const int* mp = mask + b * SEQ;

#pragma unroll
    for (int r = 0; r < 4; r++) {
        int ci = tid + r * 256;
        int row = ci >> 3, ch = ci & 7;
        uint32_t sw = (uint32_t)(row * 128 + ((ch ^ (row & 7)) << 4));
        size_t go = (size_t)row * DK + ch * 8;
        cpa16(base + AQH + sw, Qph + go);
        cpa16(base + AQL + sw, Qlp + go);
    }
    attn_load_kv(base, 0, Kp, Vp, mp, 0, tid);
    cp_commit();

    uint32_t qh[4][4], ql[4][4];
    float m0v = -INFINITY, m1v = -INFINITY, l0v = 0.f, l1v = 0.f;
    float o_[8][4];
#pragma unroll
    for (int j = 0; j < 8; j++)
#pragma unroll
        for (int q = 0; q < 4; q++) o_[j][q] = 0.f;

    const int NKB = SEQ / 64;   // 32
    for (int t = 0; t < NKB; t++) {
        if (t + 1 < NKB) {
            attn_load_kv(base, (t + 1) & 1, Kp, Vp, mp, (t + 1) * 64, tid);
            cp_commit();
            cp_wait<1>();
        } else {
            cp_wait<0>();
        }
        __syncthreads();

        if (t == 0) {
#pragma unroll
            for (int c2 = 0; c2 < 4; c2++) {
                int row = wid * 16 + (lane & 15);
                int ch = 2 * c2 + (lane >> 4);
                uint32_t ad = base + AQH + row * 128 + ((ch ^ (row & 7)) << 4);
                ldm4(qh[c2], ad);
                ldm4(ql[c2], ad + (AQL - AQH));
            }
        }

        uint32_t sb = base + ASTG + (uint32_t)(t & 1) * ASTRIDE;

        float sc[8][4];
#pragma unroll
        for (int j = 0; j < 8; j++)
#pragma unroll
            for (int q = 0; q < 4; q++) sc[j][q] = 0.f;
#pragma unroll
        for (int c2 = 0; c2 < 4; c2++) {
            uint32_t kh[4][4];
#pragma unroll
            for (int g = 0; g < 4; g++) {
                int row = g * 16 + (lane & 7) + ((lane >> 3) & 1) * 8;
                int ch = 2 * c2 + (lane >> 4);
                ldm4(kh[g], sb + AK + row * 128 + ((ch ^ (row & 7)) << 4));
            }
#pragma unroll
            for (int j = 0; j < 8; j++) {
                int g = j >> 1, o = j & 1;
                mma16816(sc[j], qh[c2], kh[g][o], kh[g][o + 2]);
                mma16816(sc[j], ql[c2], kh[g][o], kh[g][o + 2]);
            }
        }

        const int* msk = (const int*)(attsm + AMSK + (t & 1) * 256);
        int cc = (lane & 3) * 2;
#pragma unroll
        for (int j = 0; j < 8; j++) {
            int mv0 = msk[j * 8 + cc], mv1 = msk[j * 8 + cc + 1];
            if (mv0 == 0) { sc[j][0] = -1e9f; sc[j][2] = -1e9f; }
            if (mv1 == 0) { sc[j][1] = -1e9f; sc[j][3] = -1e9f; }
        }

        float mx0 = -INFINITY, mx1 = -INFINITY;
#pragma unroll
        for (int j = 0; j < 8; j++) {
            mx0 = fmaxf(mx0, fmaxf(sc[j][0], sc[j][1]));
            mx1 = fmaxf(mx1, fmaxf(sc[j][2], sc[j][3]));
        }
        mx0 = fmaxf(mx0, __shfl_xor_sync(0xffffffffu, mx0, 1));
        mx0 = fmaxf(mx0, __shfl_xor_sync(0xffffffffu, mx0, 2));
        mx1 = fmaxf(mx1, __shfl_xor_sync(0xffffffffu, mx1, 1));
        mx1 = fmaxf(mx1, __shfl_xor_sync(0xffffffffu, mx1, 2));
        float mn0 = fmaxf(m0v, mx0), mn1 = fmaxf(m1v, mx1);
        float cor0 = __expf(m0v - mn0), cor1 = __expf(m1v - mn1);

        // packed P aliases sc's registers: sc[j] = {hi01, hi23, lo01, lo23}
        float sum0 = 0.f, sum1 = 0.f;
        uint32_t* pkd = (uint32_t*)sc;
#pragma unroll
        for (int j = 0; j < 8; j++) {
            float p0 = __expf(sc[j][0] - mn0);
            float p1 = __expf(sc[j][1] - mn0);
            float p2 = __expf(sc[j][2] - mn1);
            float p3 = __expf(sc[j][3] - mn1);
            sum0 += p0 + p1; sum1 += p2 + p3;
            float r0, r1, r2, r3;
            uint32_t h01 = hpk2r(p0, p1, r0, r1);
            uint32_t h23 = hpk2r(p2, p3, r2, r3);
            uint32_t l01 = hpk2(r0, r1);
            uint32_t l23 = hpk2(r2, r3);
            pkd[j * 4 + 0] = h01;
            pkd[j * 4 + 1] = h23;
            pkd[j * 4 + 2] = l01;
            pkd[j * 4 + 3] = l23;
        }
        sum0 += __shfl_xor_sync(0xffffffffu, sum0, 1);
        sum0 += __shfl_xor_sync(0xffffffffu, sum0, 2);
        sum1 += __shfl_xor_sync(0xffffffffu, sum1, 1);
        sum1 += __shfl_xor_sync(0xffffffffu, sum1, 2);
        l0v = l0v * cor0 + sum0;
        l1v = l1v * cor1 + sum1;
        m0v = mn0; m1v = mn1;
#pragma unroll
        for (int j = 0; j < 8; j++) {
            o_[j][0] *= cor0; o_[j][1] *= cor0;
            o_[j][2] *= cor1; o_[j][3] *= cor1;
        }

#pragma unroll
        for (int t2 = 0; t2 < 4; t2++) {
            uint32_t pah[4] = { pkd[(2*t2)*4 + 0], pkd[(2*t2)*4 + 1],
                                pkd[(2*t2+1)*4 + 0], pkd[(2*t2+1)*4 + 1] };
            uint32_t pal[4] = { pkd[(2*t2)*4 + 2], pkd[(2*t2)*4 + 3],
                                pkd[(2*t2+1)*4 + 2], pkd[(2*t2+1)*4 + 3] };
            uint32_t vh[4][4];
#pragma unroll
            for (int g = 0; g < 4; g++) {
                int row = t2 * 16 + (lane & 7) + ((lane >> 3) & 1) * 8;
                int ch = 2 * g + (lane >> 4);
                ldm4t(vh[g], sb + AV + row * 128 + ((ch ^ (row & 7)) << 4));
            }
#pragma unroll
            for (int j = 0; j < 8; j++) {
                int g = j >> 1, h2 = j & 1;
                mma16816(o_[j], pah, vh[g][2*h2], vh[g][2*h2 + 1]);
                mma16816(o_[j], pal, vh[g][2*h2], vh[g][2*h2 + 1]);
            }
        }
        __syncthreads();
    }

    float il0 = 1.0f / l0v, il1 = 1.0f / l1v;
    size_t row0 = (size_t)b * SEQ + q0 + wid * 16 + (lane >> 2);
    size_t row1 = row0 + 8;
    int cb = hh * DK + (lane & 3) * 2;
#pragma unroll
    for (int j = 0; j < 8; j++) {
        int col = cb + j * 8;
        float v0 = o_[j][0] * il0, v1 = o_[j][1] * il0;
        float v2 = o_[j][2] * il1, v3 = o_[j][3] * il1;
        float r0, r1;
        uint32_t hv = hpk2r(v0, v1, r0, r1);
        uint32_t lv = hpk2(r0, r1);
        *(uint32_t*)(Oh + row0 * DMODEL + col) = hv;
        *(uint32_t*)(Ol + row0 * DMODEL + col) = lv;
        hv = hpk2r(v2, v3, r0, r1);
        lv = hpk2(r0, r1);
        *(uint32_t*)(Oh + row1 * DMODEL + col) = hv;
        *(uint32_t*)(Ol + row1 * DMODEL + col) = lv;
    }
}

// ---------------------------------------------------------------------------
extern "C" void kernel_launch(void* const* d_in, const int* in_sizes, int n_in,
                              void* d_out, int out_size)
{
    const float* x      = (const float*)d_in[0];
    const int*   mask   = (const int*)  d_in[1];
    const float* wq     = (const float*)d_in[2];
    const float* bq     = (const float*)d_in[3];
    const float* wk     = (const float*)d_in[4];
    const float* bk     = (const float*)d_in[5];
    const float* wv     = (const float*)d_in[6];
    const float* bv     = (const float*)d_in[7];
    const float* wo     = (const float*)d_in[8];
    const float* bo     = (const float*)d_in[9];
    const float* w1     = (const float*)d_in[10];
    const float* b1     = (const float*)d_in[11];
    const float* w2     = (const float*)d_in[12];
    const float* b2     = (const float*)d_in[13];
    const float* alpha1 = (const float*)d_in[14];
    const float* bias1  = (const float*)d_in[15];
    const float* alpha2 = (const float*)d_in[16];
    const float* bias2  = (const float*)d_in[17];
    float* out = (float*)d_out;

    __half *x2h, *x2l, *ath, *atl, *ffh, *ffl, *qh, *ql, *kk, *vv;
    __half *wqkv, *wop, *w1p, *w2p;
    float *pxr, *bqkv;
    cudaGetSymbolAddress((void**)&x2h, g_x2h);   cudaGetSymbolAddress((void**)&x2l, g_x2l);
    cudaGetSymbolAddress((void**)&ath, g_ath);   cudaGetSymbolAddress((void**)&atl, g_atl);
    cudaGetSymbolAddress((void**)&ffh, g_ffh);   cudaGetSymbolAddress((void**)&ffl, g_ffl);
    cudaGetSymbolAddress((void**)&qh,  g_qhh);   cudaGetSymbolAddress((void**)&ql,  g_qll);
    cudaGetSymbolAddress((void**)&kk,  g_kk);    cudaGetSymbolAddress((void**)&vv,  g_vv);
    cudaGetSymbolAddress((void**)&wqkv, g_wqkv); cudaGetSymbolAddress((void**)&wop, g_wo);
    cudaGetSymbolAddress((void**)&w1p, g_w1);    cudaGetSymbolAddress((void**)&w2p, g_w2);
    cudaGetSymbolAddress((void**)&pxr, g_xr);    cudaGetSymbolAddress((void**)&bqkv, g_bqkv);

    cudaFuncSetAttribute(attn_mma_kernel,
                         cudaFuncAttributeMaxDynamicSharedMemorySize, ATT_SMEM);
    cudaFuncSetAttribute(mma_gemm<1>,
                         cudaFuncAttributeMaxDynamicSharedMemorySize, GEMM_SMEM);
    cudaFuncSetAttribute(mma_gemm<2>,
                         cudaFuncAttributeMaxDynamicSharedMemorySize, GEMM_SMEM);
    cudaFuncSetAttribute(mma_gemm<3>,
                         cudaFuncAttributeMaxDynamicSharedMemorySize, GEMM_SMEM);

    convw_all<<<12288, dim3(32, 8)>>>(wq, wk, wv, wo, w1, w2, bq, bk, bv,
                                      wqkv, wop, w1p, w2p, bqkv);
    norm_split_kernel<<<NTOK, 256>>>(x, alpha1, bias1, x2h, x2l);
    mma_gemm<3><<<dim3(3 * DMODEL / GBN, NTOK / GBM), 256, GEMM_SMEM>>>(
        x2h, x2l, wqkv, bqkv, nullptr, nullptr, qh, ql, kk, vv,
        NTOK, 3 * DMODEL, DMODEL);
    attn_mma_kernel<<<dim3(SEQ / 128, BATCH * NHEAD), 256, ATT_SMEM>>>(
        qh, ql, kk, vv, mask, ath, atl);
    mma_gemm<2><<<dim3(DMODEL / GBN, NTOK / GBM), 256, GEMM_SMEM>>>(
        ath, atl, wop, bo, x, pxr, nullptr, nullptr, nullptr, nullptr,
        NTOK, DMODEL, DMODEL);
    norm_split_kernel<<<NTOK, 256>>>(pxr, alpha2, bias2, x2h, x2l);
    mma_gemm<1><<<dim3(DFF / GBN, NTOK / GBM), 256, GEMM_SMEM>>>(
        x2h, x2l, w1p, b1, nullptr, nullptr, ffh, ffl, nullptr, nullptr,
        NTOK, DFF, DMODEL);
    mma_gemm<2><<<dim3(DMODEL / GBN, NTOK / GBM), 256, GEMM_SMEM>>>(
        ffh, ffl, w2p, b2, pxr, out, nullptr, nullptr, nullptr, nullptr,
        NTOK, DMODEL, DFF);
}

// round 8
// speedup vs baseline: 6.6727x; 1.7828x over previous
#include <cuda_runtime.h>
#include <cuda_fp16.h>
#include <math.h>
#include <stdint.h>

// Problem constants
#define BATCH 4
#define SEQ   2048
#define DMODEL 1024
#define NHEAD 16
#define DK    64
#define DFF   4096
#define NTOK  (BATCH * SEQ)   // 8192

// ---------------- scratch (static device globals; no allocation) -----------
__device__ __half g_x2  [NTOK * DMODEL];
__device__ __half g_q   [NTOK * DMODEL];   // pre-scaled 1/8, [B,H,S,DK]
__device__ __half g_k   [NTOK * DMODEL];
__device__ __half g_v   [NTOK * DMODEL];
__device__ __half g_at  [NTOK * DMODEL];   // attn out, [B,S,H*DK]
__device__ float  g_xr  [NTOK * DMODEL];
__device__ __half g_ff  [NTOK * DFF];
// transposed fp16 weights, [N, K] layout; QKV fused to [3072, 1024]
__device__ __half g_wqkv[3*DMODEL*DMODEL];
__device__ __half g_wo[DMODEL*DMODEL];
__device__ __half g_w1[DMODEL*DFF];
__device__ __half g_w2[DFF*DMODEL];
__device__ float  g_bqkv[3*DMODEL];

// ============================ PTX helpers (sm_80-level only) ================
__device__ __forceinline__ uint32_t s2u(const void* p) {
    uint32_t a;
    asm("{ .reg .u64 t; cvta.to.shared.u64 t, %1; cvt.u32.u64 %0, t; }"
        : "=r"(a) : "l"(p));
    return a;
}
__device__ __forceinline__ void cpa16(uint32_t s, const void* g) {
    asm volatile("cp.async.cg.shared.global [%0], [%1], 16;"
                 :: "r"(s), "l"(g) : "memory");
}
__device__ __forceinline__ void cp_commit() {
    asm volatile("cp.async.commit_group;" ::: "memory");
}
template<int N>
__device__ __forceinline__ void cp_wait() {
    asm volatile("cp.async.wait_group %0;" :: "n"(N) : "memory");
}
__device__ __forceinline__ void ldm4(uint32_t* r, uint32_t addr) {
    asm volatile("ldmatrix.sync.aligned.m8n8.x4.shared.b16 {%0,%1,%2,%3}, [%4];"
        : "=r"(r[0]), "=r"(r[1]), "=r"(r[2]), "=r"(r[3]) : "r"(addr));
}
__device__ __forceinline__ void ldm4t(uint32_t* r, uint32_t addr) {
    asm volatile("ldmatrix.sync.aligned.m8n8.x4.trans.shared.b16 {%0,%1,%2,%3}, [%4];"
        : "=r"(r[0]), "=r"(r[1]), "=r"(r[2]), "=r"(r[3]) : "r"(addr));
}
__device__ __forceinline__ void mma16816(float* c, const uint32_t* a,
                                         uint32_t b0, uint32_t b1) {
    asm volatile(
        "mma.sync.aligned.m16n8k16.row.col.f32.f16.f16.f32 "
        "{%0,%1,%2,%3}, {%4,%5,%6,%7}, {%8,%9}, {%0,%1,%2,%3};"
        : "+f"(c[0]), "+f"(c[1]), "+f"(c[2]), "+f"(c[3])
        : "r"(a[0]), "r"(a[1]), "r"(a[2]), "r"(a[3]), "r"(b0), "r"(b1));
}
__device__ __forceinline__ uint32_t hpk2(float a, float b) {
    __half2 h; h.x = __float2half(a); h.y = __float2half(b);
    return *(uint32_t*)&h;
}

// ---------------------------------------------------------------------------
// Tensor1DNorm -> fp16 output.
// ---------------------------------------------------------------------------
__global__ void __launch_bounds__(256) norm_h_kernel(
    const float* __restrict__ x, const float* __restrict__ alpha,
    const float* __restrict__ beta, __half* __restrict__ y)
{
    __shared__ float red[16];
    __shared__ float stats[2];
    int row = blockIdx.x;
    int t = threadIdx.x;
    const float4* xr = (const float4*)(x + (size_t)row * DMODEL);
    float4 v = xr[t];
    float s  = v.x + v.y + v.z + v.w;
    float sq = v.x*v.x + v.y*v.y + v.z*v.z + v.w*v.w;
#pragma unroll
    for (int o = 16; o > 0; o >>= 1) {
        s  += __shfl_down_sync(0xffffffffu, s,  o);
        sq += __shfl_down_sync(0xffffffffu, sq, o);
    }
    int warp = t >> 5;
    if ((t & 31) == 0) { red[warp] = s; red[warp + 8] = sq; }
    __syncthreads();
    if (t == 0) {
        float S = 0.f, SQ = 0.f;
#pragma unroll
        for (int w = 0; w < 8; w++) { S += red[w]; SQ += red[w + 8]; }
        float mean = S * (1.0f / DMODEL);
        float var = (SQ - S * mean) * (1.0f / (DMODEL - 1));
        var = fmaxf(var, 0.0f);
        stats[0] = mean; stats[1] = 1.0f / (sqrtf(var) + 1e-6f);
    }
    __syncthreads();
    float mean = stats[0], inv = stats[1];
    float4 a = ((const float4*)alpha)[t];
    float4 b = ((const float4*)beta)[t];
    uint32_t h0 = hpk2(a.x * (v.x - mean) * inv + b.x,
                       a.y * (v.y - mean) * inv + b.y);
    uint32_t h1 = hpk2(a.z * (v.z - mean) * inv + b.z,
                       a.w * (v.w - mean) * inv + b.w);
    uint32_t* ph = (uint32_t*)(y + (size_t)row * DMODEL) + t * 2;
    ph[0] = h0; ph[1] = h1;
}

// ---------------------------------------------------------------------------
// Fused weight transpose + fp16 convert for ALL weights in ONE launch.
// ---------------------------------------------------------------------------
__global__ void __launch_bounds__(256) convw_all(
    const float* __restrict__ wq, const float* __restrict__ wk,
    const float* __restrict__ wv, const float* __restrict__ wo,
    const float* __restrict__ w1, const float* __restrict__ w2,
    const float* __restrict__ bq, const float* __restrict__ bk,
    const float* __restrict__ bv,
    __half* qkv, __half* ow, __half* w1o, __half* w2o, float* bqkv)
{
    __shared__ float t[32][33];
    int bid = blockIdx.x;
    const float* W; __half* dst;
    int K, N, bx, by;
    size_t nofs = 0;
    if (bid < 4096) {
        int ws = bid >> 10, lt = bid & 1023;
        K = DMODEL; N = DMODEL; bx = lt & 31; by = lt >> 5;
        if (ws == 0)      { W = wq; dst = qkv; nofs = 0; }
        else if (ws == 1) { W = wk; dst = qkv; nofs = DMODEL; }
        else if (ws == 2) { W = wv; dst = qkv; nofs = 2*DMODEL; }
        else              { W = wo; dst = ow; }
    } else if (bid < 8192) {
        int lt = bid - 4096;
        K = DMODEL; N = DFF; bx = lt & 127; by = lt >> 7;
        W = w1; dst = w1o;
    } else {
        int lt = bid - 8192;
        K = DFF; N = DMODEL; bx = lt & 31; by = lt >> 5;
        W = w2; dst = w2o;
    }
    int tx = threadIdx.x, ty = threadIdx.y;
    int n0 = bx * 32, k0 = by * 32;
#pragma unroll
    for (int i = 0; i < 4; i++)
        t[ty + 8*i][tx] = W[(size_t)(k0 + ty + 8*i) * N + n0 + tx];
    __syncthreads();
#pragma unroll
    for (int i = 0; i < 4; i++) {
        float v = t[tx][ty + 8*i];
        dst[(nofs + n0 + ty + 8*i) * K + k0 + tx] = __float2half(v);
    }
    if (bid == 0 && ty == 0) {
#pragma unroll
        for (int i = 0; i < DMODEL / 32; i++) {
            bqkv[i * 32 + tx]              = bq[i * 32 + tx];
            bqkv[DMODEL + i * 32 + tx]     = bk[i * 32 + tx];
            bqkv[2 * DMODEL + i * 32 + tx] = bv[i * 32 + tx];
        }
    }
}

// ---------------------------------------------------------------------------
// fp16 HMMA GEMM. CTA 128x128, K-step 32, 3-stage cp.async pipeline,
// 256 threads (8 warps, 2Mx4N), 2 CTAs/SM (48KB smem).
// EPI: 1 = +bias, relu, fp16 (FF1)
//      2 = +bias +resid, fp32 (O-proj / FF2)
//      3 = fused QKV: Q scaled 1/8, K, V -> fp16 [B,H,S,DK]
// ---------------------------------------------------------------------------
#define GBM 128
#define GBN 128
#define GBK 32
#define SOFF_A 0
#define SOFF_B 8192
#define STAGE_B 16384
#define GEMM_SMEM (3 * STAGE_B)

__device__ __forceinline__ void load_stage32(
    uint32_t sb, const __half* A, const __half* B,
    int m0, int n0, int k0, int K, int tid)
{
#pragma unroll
    for (int r = 0; r < 2; r++) {
        int ci = tid + r * 256;
        int row = ci >> 2, ch = ci & 3;
        uint32_t sw = (uint32_t)(row * 64 + ((ch ^ ((row >> 1) & 3)) << 4));
        cpa16(sb + SOFF_A + sw, A + (size_t)(m0 + row) * K + k0 + ch * 8);
        cpa16(sb + SOFF_B + sw, B + (size_t)(n0 + row) * K + k0 + ch * 8);
    }
}

template<int EPI>
__global__ void __launch_bounds__(256, 2)
mma_gemm(const __half* __restrict__ A, const __half* __restrict__ B,
         const float* __restrict__ bias, const float* __restrict__ resid,
         float* __restrict__ C, __half* __restrict__ Ch,
         __half* __restrict__ Pk, __half* __restrict__ Pv,
         int M, int N, int K)
{
    extern __shared__ __align__(1024) char dsm[];
    uint32_t dyn = s2u(dsm);

    int tid = threadIdx.x;
    int wid = tid >> 5, lane = tid & 31;
    int wm = wid & 1, wn = wid >> 1;
    int m0 = blockIdx.y * GBM, n0 = blockIdx.x * GBN;

    float c[4][4][4];
#pragma unroll
    for (int i = 0; i < 4; i++)
#pragma unroll
        for (int j = 0; j < 4; j++)
#pragma unroll
            for (int q = 0; q < 4; q++) c[i][j][q] = 0.f;

    int aRow0 = wm * 64 + (lane & 7) + ((lane >> 3) & 1) * 8;
    int bRow0 = wn * 32 + (lane & 7) + ((lane >> 3) & 1) * 8;
    int cgrp = lane >> 4;

    int nsteps = K / GBK;
    load_stage32(dyn, A, B, m0, n0, 0, K, tid);
    cp_commit();
    load_stage32(dyn + STAGE_B, A, B, m0, n0, GBK, K, tid);
    cp_commit();

    uint32_t sb = dyn;
    int buf = 0;
    for (int step = 0; step < nsteps; step++) {
        if (step < nsteps - 1) cp_wait<1>(); else cp_wait<0>();
        __syncthreads();
        if (step + 2 < nsteps) {
            int nb = buf + 2; if (nb >= 3) nb -= 3;
            load_stage32(dyn + (uint32_t)nb * STAGE_B, A, B,
                         m0, n0, (step + 2) * GBK, K, tid);
            cp_commit();
        }

#pragma unroll
        for (int s = 0; s < 2; s++) {
            int ch = 2 * s + cgrp;
            uint32_t ah[4][4];
#pragma unroll
            for (int i = 0; i < 4; i++) {
                int row = aRow0 + i * 16;
                ldm4(ah[i], sb + SOFF_A + row * 64 +
                            ((ch ^ ((row >> 1) & 3)) << 4));
            }
            uint32_t bh[2][4];
#pragma unroll
            for (int g = 0; g < 2; g++) {
                int row = bRow0 + g * 16;
                ldm4(bh[g], sb + SOFF_B + row * 64 +
                            ((ch ^ ((row >> 1) & 3)) << 4));
            }
#pragma unroll
            for (int i = 0; i < 4; i++) {
#pragma unroll
                for (int j = 0; j < 4; j++) {
                    int g = j >> 1, o = j & 1;
                    mma16816(c[i][j], ah[i], bh[g][o], bh[g][o + 2]);
                }
            }
        }
        buf++; if (buf >= 3) buf = 0;
        sb = dyn + (uint32_t)buf * STAGE_B;
        __syncthreads();
    }

    // ----------------- epilogue -----------------
    int rbase = m0 + wm * 64 + (lane >> 2);
    int cbase = n0 + wn * 32 + (lane & 3) * 2;
#pragma unroll
    for (int i = 0; i < 4; i++) {
#pragma unroll
        for (int j = 0; j < 4; j++) {
            int col = cbase + j * 8;
            float bs0 = bias[col], bs1 = bias[col + 1];
#pragma unroll
            for (int half = 0; half < 2; half++) {
                int r = rbase + i * 16 + half * 8;
                float v0 = c[i][j][half * 2]     + bs0;
                float v1 = c[i][j][half * 2 + 1] + bs1;
                if (EPI == 1) {
                    v0 = fmaxf(v0, 0.f);
                    v1 = fmaxf(v1, 0.f);
                    *(uint32_t*)(Ch + (size_t)r * N + col) = hpk2(v0, v1);
                } else if (EPI == 2) {
                    float2 rr = *(const float2*)(resid + (size_t)r * N + col);
                    float2 o; o.x = v0 + rr.x; o.y = v1 + rr.y;
                    *(float2*)(C + (size_t)r * N + col) = o;
                } else {  // EPI == 3: fused QKV
                    int t  = col >> 10;        // 0=q,1=k,2=v
                    int c2 = col & 1023;
                    int h = c2 >> 6, d = c2 & 63;
                    int bb = r >> 11, sx = r & 2047;
                    size_t idx = (((size_t)bb * NHEAD + h) * SEQ + sx) * DK + d;
                    if (t == 0) {
                        *(uint32_t*)(Ch + idx) = hpk2(v0 * 0.125f, v1 * 0.125f);
                    } else if (t == 1) {
                        *(uint32_t*)(Pk + idx) = hpk2(v0, v1);
                    } else {
                        *(uint32_t*)(Pv + idx) = hpk2(v0, v1);
                    }
                }
            }
        }
    }
}

// ---------------------------------------------------------------------------
// HMMA flash attention, fp16 (single product). 128 q-rows/block, 8 warps,
// 64-key stages double-buffered, 2 CTAs/SM.
// ---------------------------------------------------------------------------
#define AQ 0
#define ASTG 16384
#define ASTRIDE 16384
#define AK 0
#define AV 8192
#define AMSK 49152
#define ATT_SMEM (49152 + 512)

__device__ __forceinline__ void attn_load_kv(
    uint32_t base, int buf, const __half* Kp, const __half* Vp,
    const int* mp, int k0, int tid)
{
    uint32_t sb = base + ASTG + (uint32_t)buf * ASTRIDE;
#pragma unroll
    for (int r = 0; r < 2; r++) {
        int ci = tid + r * 256;
        int row = ci >> 3, ch = ci & 7;
        uint32_t sw = (uint32_t)(row * 128 + ((ch ^ (row & 7)) << 4));
        size_t go = (size_t)(k0 + row) * DK + ch * 8;
        cpa16(sb + AK + sw, Kp + go);
        cpa16(sb + AV + sw, Vp + go);
    }
    if (tid < 16)
        cpa16(base + AMSK + (uint32_t)buf * 256 + tid * 16, mp + k0 + tid * 4);
}

__global__ void __launch_bounds__(256, 2) attn_mma_kernel(
    const __half* __restrict__ Qg, const __half* __restrict__ Kg,
    const __half* __restrict__ Vg, const int* __restrict__ mask,
    __half* __restrict__ O)
{
    extern __shared__ __align__(1024) char attsm[];
    uint32_t base = s2u(attsm);

    int tid = threadIdx.x;
    int wid = tid >> 5, lane = tid & 31;
    int bh = blockIdx.y;
    int b = bh >> 4, hh = bh & 15;
    int q0 = blockIdx.x * 128;

    const __half* Qp = Qg + ((size_t)bh * SEQ + q0) * DK;
    const __half* Kp = Kg + (size_t)bh * SEQ * DK;
    const __half* Vp = Vg + (size_t)bh * SEQ * DK;
    const int* mp = mask + b * SEQ;

#pragma unroll
    for (int r = 0; r < 4; r++) {
        int ci = tid + r * 256;
        int row = ci >> 3, ch = ci & 7;
        uint32_t sw = (uint32_t)(row * 128 + ((ch ^ (row & 7)) << 4));
        cpa16(base + AQ + sw, Qp + (size_t)row * DK + ch * 8);
    }
    attn_load_kv(base, 0, Kp, Vp, mp, 0, tid);
    cp_commit();

    uint32_t qh[4][4];
    float m0v = -INFINITY, m1v = -INFINITY, l0v = 0.f, l1v = 0.f;
    float o_[8][4];
#pragma unroll
    for (int j = 0; j < 8; j++)
#pragma unroll
        for (int q = 0; q < 4; q++) o_[j][q] = 0.f;

    const int NKB = SEQ / 64;   // 32
    for (int t = 0; t < NKB; t++) {
        if (t + 1 < NKB) {
            attn_load_kv(base, (t + 1) & 1, Kp, Vp, mp, (t + 1) * 64, tid);
            cp_commit();
            cp_wait<1>();
        } else {
            cp_wait<0>();
        }
        __syncthreads();

        if (t == 0) {
#pragma unroll
            for (int c2 = 0; c2 < 4; c2++) {
                int row = wid * 16 + (lane & 15);
                int ch = 2 * c2 + (lane >> 4);
                ldm4(qh[c2], base + AQ + row * 128 + ((ch ^ (row & 7)) << 4));
            }
        }

        uint32_t sb = base + ASTG + (uint32_t)(t & 1) * ASTRIDE;

        float sc[8][4];
#pragma unroll
        for (int j = 0; j < 8; j++)
#pragma unroll
            for (int q = 0; q < 4; q++) sc[j][q] = 0.f;
#pragma unroll
        for (int c2 = 0; c2 < 4; c2++) {
            uint32_t kh[4][4];
#pragma unroll
            for (int g = 0; g < 4; g++) {
                int row = g * 16 + (lane & 7) + ((lane >> 3) & 1) * 8;
                int ch = 2 * c2 + (lane >> 4);
                ldm4(kh[g], sb + AK + row * 128 + ((ch ^ (row & 7)) << 4));
            }
#pragma unroll
            for (int j = 0; j < 8; j++) {
                int g = j >> 1, o = j & 1;
                mma16816(sc[j], qh[c2], kh[g][o], kh[g][o + 2]);
            }
        }

        const int* msk = (const int*)(attsm + AMSK + (t & 1) * 256);
        int cc = (lane & 3) * 2;
#pragma unroll
        for (int j = 0; j < 8; j++) {
            int mv0 = msk[j * 8 + cc], mv1 = msk[j * 8 + cc + 1];
            if (mv0 == 0) { sc[j][0] = -1e9f; sc[j][2] = -1e9f; }
            if (mv1 == 0) { sc[j][1] = -1e9f; sc[j][3] = -1e9f; }
        }

        float mx0 = -INFINITY, mx1 = -INFINITY;
#pragma unroll
        for (int j = 0; j < 8; j++) {
            mx0 = fmaxf(mx0, fmaxf(sc[j][0], sc[j][1]));
            mx1 = fmaxf(mx1, fmaxf(sc[j][2], sc[j][3]));
        }
        mx0 = fmaxf(mx0, __shfl_xor_sync(0xffffffffu, mx0, 1));
        mx0 = fmaxf(mx0, __shfl_xor_sync(0xffffffffu, mx0, 2));
        mx1 = fmaxf(mx1, __shfl_xor_sync(0xffffffffu, mx1, 1));
        mx1 = fmaxf(mx1, __shfl_xor_sync(0xffffffffu, mx1, 2));
        float mn0 = fmaxf(m0v, mx0), mn1 = fmaxf(m1v, mx1);
        float cor0 = __expf(m0v - mn0), cor1 = __expf(m1v - mn1);

        // packed P aliases sc registers: pkd[j*2] = rows r, pkd[j*2+1] = rows r+8
        float sum0 = 0.f, sum1 = 0.f;
        uint32_t* pkd = (uint32_t*)sc;
#pragma unroll
        for (int j = 0; j < 8; j++) {
            float p0 = __expf(sc[j][0] - mn0);
            float p1 = __expf(sc[j][1] - mn0);
            float p2 = __expf(sc[j][2] - mn1);
            float p3 = __expf(sc[j][3] - mn1);
            sum0 += p0 + p1; sum1 += p2 + p3;
            uint32_t h01 = hpk2(p0, p1);
            uint32_t h23 = hpk2(p2, p3);
            pkd[j * 2 + 0] = h01;
            pkd[j * 2 + 1] = h23;
        }
        sum0 += __shfl_xor_sync(0xffffffffu, sum0, 1);
        sum0 += __shfl_xor_sync(0xffffffffu, sum0, 2);
        sum1 += __shfl_xor_sync(0xffffffffu, sum1, 1);
        sum1 += __shfl_xor_sync(0xffffffffu, sum1, 2);
        l0v = l0v * cor0 + sum0;
        l1v = l1v * cor1 + sum1;
        m0v = mn0; m1v = mn1;
#pragma unroll
        for (int j = 0; j < 8; j++) {
            o_[j][0] *= cor0; o_[j][1] *= cor0;
            o_[j][2] *= cor1; o_[j][3] *= cor1;
        }

#pragma unroll
        for (int t2 = 0; t2 < 4; t2++) {
            uint32_t pa[4] = { pkd[(2*t2)*2 + 0], pkd[(2*t2)*2 + 1],
                               pkd[(2*t2+1)*2 + 0], pkd[(2*t2+1)*2 + 1] };
            uint32_t vh[4][4];
#pragma unroll
            for (int g = 0; g < 4; g++) {
                int row = t2 * 16 + (lane & 7) + ((lane >> 3) & 1) * 8;
                int ch = 2 * g + (lane >> 4);
                ldm4t(vh[g], sb + AV + row * 128 + ((ch ^ (row & 7)) << 4));
            }
#pragma unroll
            for (int j = 0; j < 8; j++) {
                int g = j >> 1, h2 = j & 1;
                mma16816(o_[j], pa, vh[g][2*h2], vh[g][2*h2 + 1]);
            }
        }
        __syncthreads();
    }

    float il0 = 1.0f / l0v, il1 = 1.0f / l1v;
    size_t row0 = (size_t)b * SEQ + q0 + wid * 16 + (lane >> 2);
    size_t row1 = row0 + 8;
    int cb = hh * DK + (lane & 3) * 2;
#pragma unroll
    for (int j = 0; j < 8; j++) {
        int col = cb + j * 8;
        *(uint32_t*)(O + row0 * DMODEL + col) =
            hpk2(o_[j][0] * il0, o_[j][1] * il0);
        *(uint32_t*)(O + row1 * DMODEL + col) =
            hpk2(o_[j][2] * il1, o_[j][3] * il1);
    }
}

// ---------------------------------------------------------------------------
extern "C" void kernel_launch(void* const* d_in, const int* in_sizes, int n_in,
                              void* d_out, int out_size)
{
    const float* x      = (const float*)d_in[0];
    const int*   mask   = (const int*)  d_in[1];
    const float* wq     = (const float*)d_in[2];
    const float* bq     = (const float*)d_in[3];
    const float* wk     = (const float*)d_in[4];
    const float* bk     = (const float*)d_in[5];
    const float* wv     = (const float*)d_in[6];
    const float* bv     = (const float*)d_in[7];
    const float* wo     = (const float*)d_in[8];
    const float* bo     = (const float*)d_in[9];
    const float* w1     = (const float*)d_in[10];
    const float* b1     = (const float*)d_in[11];
    const float* w2     = (const float*)d_in[12];
    const float* b2     = (const float*)d_in[13];
    const float* alpha1 = (const float*)d_in[14];
    const float* bias1  = (const float*)d_in[15];
    const float* alpha2 = (const float*)d_in[16];
    const float* bias2  = (const float*)d_in[17];
    float* out = (float*)d_out;

    __half *x2, *at, *ff, *qq, *kk, *vv, *wqkv, *wop, *w1p, *w2p;
    float *pxr, *bqkv;
    cudaGetSymbolAddress((void**)&x2, g_x2);
    cudaGetSymbolAddress((void**)&at, g_at);
    cudaGetSymbolAddress((void**)&ff, g_ff);
    cudaGetSymbolAddress((void**)&qq, g_q);
    cudaGetSymbolAddress((void**)&kk, g_k);
    cudaGetSymbolAddress((void**)&vv, g_v);
    cudaGetSymbolAddress((void**)&wqkv, g_wqkv);
    cudaGetSymbolAddress((void**)&wop, g_wo);
    cudaGetSymbolAddress((void**)&w1p, g_w1);
    cudaGetSymbolAddress((void**)&w2p, g_w2);
    cudaGetSymbolAddress((void**)&pxr, g_xr);
    cudaGetSymbolAddress((void**)&bqkv, g_bqkv);

    cudaFuncSetAttribute(attn_mma_kernel,
                         cudaFuncAttributeMaxDynamicSharedMemorySize, ATT_SMEM);
    cudaFuncSetAttribute(mma_gemm<1>,
                         cudaFuncAttributeMaxDynamicSharedMemorySize, GEMM_SMEM);
    cudaFuncSetAttribute(mma_gemm<2>,
                         cudaFuncAttributeMaxDynamicSharedMemorySize, GEMM_SMEM);
    cudaFuncSetAttribute(mma_gemm<3>,
                         cudaFuncAttributeMaxDynamicSharedMemorySize, GEMM_SMEM);

    convw_all<<<12288, dim3(32, 8)>>>(wq, wk, wv, wo, w1, w2, bq, bk, bv,
                                      wqkv, wop, w1p, w2p, bqkv);
    norm_h_kernel<<<NTOK, 256>>>(x, alpha1, bias1, x2);
    mma_gemm<3><<<dim3(3 * DMODEL / GBN, NTOK / GBM), 256, GEMM_SMEM>>>(
        x2, wqkv, bqkv, nullptr, nullptr, qq, kk, vv, NTOK, 3 * DMODEL, DMODEL);
    attn_mma_kernel<<<dim3(SEQ / 128, BATCH * NHEAD), 256, ATT_SMEM>>>(
        qq, kk, vv, mask, at);
    mma_gemm<2><<<dim3(DMODEL / GBN, NTOK / GBM), 256, GEMM_SMEM>>>(
        at, wop, bo, x, pxr, nullptr, nullptr, nullptr, NTOK, DMODEL, DMODEL);
    norm_h_kernel<<<NTOK, 256>>>(pxr, alpha2, bias2, x2);
    mma_gemm<1><<<dim3(DFF / GBN, NTOK / GBM), 256, GEMM_SMEM>>>(
        x2, w1p, b1, nullptr, nullptr, ff, nullptr, nullptr, NTOK, DFF, DMODEL);
    mma_gemm<2><<<dim3(DMODEL / GBN, NTOK / GBM), 256, GEMM_SMEM>>>(
        ff, w2p, b2, pxr, out, nullptr, nullptr, nullptr, NTOK, DMODEL, DFF);
}

// round 9
// speedup vs baseline: 7.4445x; 1.1157x over previous
#include <cuda_runtime.h>
#include <cuda_fp16.h>
#include <math.h>
#include <stdint.h>

// Problem constants
#define BATCH 4
#define SEQ   2048
#define DMODEL 1024
#define NHEAD 16
#define DK    64
#define DFF   4096
#define NTOK  (BATCH * SEQ)   // 8192

// ---------------- scratch (static device globals; no allocation) -----------
__device__ __half g_x2  [NTOK * DMODEL];
__device__ __half g_q   [NTOK * DMODEL];   // pre-scaled 1/8, [B,H,S,DK]
__device__ __half g_k   [NTOK * DMODEL];
__device__ __half g_v   [NTOK * DMODEL];
__device__ __half g_at  [NTOK * DMODEL];   // attn out, [B,S,H*DK]
__device__ float  g_xr  [NTOK * DMODEL];
__device__ __half g_ff  [NTOK * DFF];
// transposed fp16 weights, [N, K] layout; QKV fused to [3072, 1024]
__device__ __half g_wqkv[3*DMODEL*DMODEL];
__device__ __half g_wo[DMODEL*DMODEL];
__device__ __half g_w1[DMODEL*DFF];
__device__ __half g_w2[DFF*DMODEL];
__device__ float  g_bqkv[3*DMODEL];

// ============================ PTX helpers (sm_80-level only) ================
__device__ __forceinline__ uint32_t s2u(const void* p) {
    uint32_t a;
    asm("{ .reg .u64 t; cvta.to.shared.u64 t, %1; cvt.u32.u64 %0, t; }"
        : "=r"(a) : "l"(p));
    return a;
}
__device__ __forceinline__ void cpa16(uint32_t s, const void* g) {
    asm volatile("cp.async.cg.shared.global [%0], [%1], 16;"
                 :: "r"(s), "l"(g) : "memory");
}
__device__ __forceinline__ void cp_commit() {
    asm volatile("cp.async.commit_group;" ::: "memory");
}
template<int N>
__device__ __forceinline__ void cp_wait() {
    asm volatile("cp.async.wait_group %0;" :: "n"(N) : "memory");
}
__device__ __forceinline__ void ldm4(uint32_t* r, uint32_t addr) {
    asm volatile("ldmatrix.sync.aligned.m8n8.x4.shared.b16 {%0,%1,%2,%3}, [%4];"
        : "=r"(r[0]), "=r"(r[1]), "=r"(r[2]), "=r"(r[3]) : "r"(addr));
}
__device__ __forceinline__ void ldm4t(uint32_t* r, uint32_t addr) {
    asm volatile("ldmatrix.sync.aligned.m8n8.x4.trans.shared.b16 {%0,%1,%2,%3}, [%4];"
        : "=r"(r[0]), "=r"(r[1]), "=r"(r[2]), "=r"(r[3]) : "r"(addr));
}
__device__ __forceinline__ void mma16816(float* c, const uint32_t* a,
                                         uint32_t b0, uint32_t b1) {
    asm volatile(
        "mma.sync.aligned.m16n8k16.row.col.f32.f16.f16.f32 "
        "{%0,%1,%2,%3}, {%4,%5,%6,%7}, {%8,%9}, {%0,%1,%2,%3};"
        : "+f"(c[0]), "+f"(c[1]), "+f"(c[2]), "+f"(c[3])
        : "r"(a[0]), "r"(a[1]), "r"(a[2]), "r"(a[3]), "r"(b0), "r"(b1));
}
__device__ __forceinline__ uint32_t hpk2(float a, float b) {
    __half2 h; h.x = __float2half(a); h.y = __float2half(b);
    return *(uint32_t*)&h;
}

// ---------------------------------------------------------------------------
// Tensor1DNorm -> fp16 output.
// ---------------------------------------------------------------------------
__global__ void __launch_bounds__(256) norm_h_kernel(
    const float* __restrict__ x, const float* __restrict__ alpha,
    const float* __restrict__ beta, __half* __restrict__ y)
{
    __shared__ float red[16];
    __shared__ float stats[2];
    int row = blockIdx.x;
    int t = threadIdx.x;
    const float4* xr = (const float4*)(x + (size_t)row * DMODEL);
    float4 v = xr[t];
    float s  = v.x + v.y + v.z + v.w;
    float sq = v.x*v.x + v.y*v.y + v.z*v.z + v.w*v.w;
#pragma unroll
    for (int o = 16; o > 0; o >>= 1) {
        s  += __shfl_down_sync(0xffffffffu, s,  o);
        sq += __shfl_down_sync(0xffffffffu, sq, o);
    }
    int warp = t >> 5;
    if ((t & 31) == 0) { red[warp] = s; red[warp + 8] = sq; }
    __syncthreads();
    if (t == 0) {
        float S = 0.f, SQ = 0.f;
#pragma unroll
        for (int w = 0; w < 8; w++) { S += red[w]; SQ += red[w + 8]; }
        float mean = S * (1.0f / DMODEL);
        float var = (SQ - S * mean) * (1.0f / (DMODEL - 1));
        var = fmaxf(var, 0.0f);
        stats[0] = mean; stats[1] = 1.0f / (sqrtf(var) + 1e-6f);
    }
    __syncthreads();
    float mean = stats[0], inv = stats[1];
    float4 a = ((const float4*)alpha)[t];
    float4 b = ((const float4*)beta)[t];
    uint32_t h0 = hpk2(a.x * (v.x - mean) * inv + b.x,
                       a.y * (v.y - mean) * inv + b.y);
    uint32_t h1 = hpk2(a.z * (v.z - mean) * inv + b.z,
                       a.w * (v.w - mean) * inv + b.w);
    uint32_t* ph = (uint32_t*)(y + (size_t)row * DMODEL) + t * 2;
    ph[0] = h0; ph[1] = h1;
}

// ---------------------------------------------------------------------------
// Fused weight transpose + fp16 convert for ALL weights in ONE launch.
// ---------------------------------------------------------------------------
__global__ void __launch_bounds__(256) convw_all(
    const float* __restrict__ wq, const float* __restrict__ wk,
    const float* __restrict__ wv, const float* __restrict__ wo,
    const float* __restrict__ w1, const float* __restrict__ w2,
    const float* __restrict__ bq, const float* __restrict__ bk,
    const float* __restrict__ bv,
    __half* qkv, __half* ow, __half* w1o, __half* w2o, float* bqkv)
{
    __shared__ float t[32][33];
    int bid = blockIdx.x;
    const float* W; __half* dst;
    int K, N, bx, by;
    size_t nofs = 0;
    if (bid < 4096) {
        int ws = bid >> 10, lt = bid & 1023;
        K = DMODEL; N = DMODEL; bx = lt & 31; by = lt >> 5;
        if (ws == 0)      { W = wq; dst = qkv; nofs = 0; }
        else if (ws == 1) { W = wk; dst = qkv; nofs = DMODEL; }
        else if (ws == 2) { W = wv; dst = qkv; nofs = 2*DMODEL; }
        else              { W = wo; dst = ow; }
    } else if (bid < 8192) {
        int lt = bid - 4096;
        K = DMODEL; N = DFF; bx = lt & 127; by = lt >> 7;
        W = w1; dst = w1o;
    } else {
        int lt = bid - 8192;
        K = DFF; N = DMODEL; bx = lt & 31; by = lt >> 5;
        W = w2; dst = w2o;
    }
    int tx = threadIdx.x, ty = threadIdx.y;
    int n0 = bx * 32, k0 = by * 32;
#pragma unroll
    for (int i = 0; i < 4; i++)
        t[ty + 8*i][tx] = W[(size_t)(k0 + ty + 8*i) * N + n0 + tx];
    __syncthreads();
#pragma unroll
    for (int i = 0; i < 4; i++) {
        float v = t[tx][ty + 8*i];
        dst[(nofs + n0 + ty + 8*i) * K + k0 + tx] = __float2half(v);
    }
    if (bid == 0 && ty == 0) {
#pragma unroll
        for (int i = 0; i < DMODEL / 32; i++) {
            bqkv[i * 32 + tx]              = bq[i * 32 + tx];
            bqkv[DMODEL + i * 32 + tx]     = bk[i * 32 + tx];
            bqkv[2 * DMODEL + i * 32 + tx] = bv[i * 32 + tx];
        }
    }
}

// ---------------------------------------------------------------------------
// fp16 HMMA GEMM. CTA 128x128, K-step 64, 3-stage cp.async pipeline,
// ONE barrier per step, 256 threads (8 warps, 2Mx4N), 2 CTAs/SM (96KB smem).
// EPI: 1 = +bias, relu, fp16 (FF1)
//      2 = +bias +resid, fp32 (O-proj / FF2)
//      3 = fused QKV: Q scaled 1/8, K, V -> fp16 [B,H,S,DK]
// ---------------------------------------------------------------------------
#define GBM 128
#define GBN 128
#define GBK 64
#define SOFF_A 0
#define SOFF_B 16384
#define STAGE_B 32768
#define GEMM_SMEM (3 * STAGE_B)

__device__ __forceinline__ void load_stage64(
    uint32_t sb, const __half* A, const __half* B,
    int m0, int n0, int k0, int K, int tid)
{
#pragma unroll
    for (int r = 0; r < 4; r++) {
        int ci = tid + r * 256;            // 0..1023
        int row = ci >> 3, ch = ci & 7;
        uint32_t sw = (uint32_t)(row * 128 + ((ch ^ (row & 7)) << 4));
        cpa16(sb + SOFF_A + sw, A + (size_t)(m0 + row) * K + k0 + ch * 8);
        cpa16(sb + SOFF_B + sw, B + (size_t)(n0 + row) * K + k0 + ch * 8);
    }
}

template<int EPI>
__global__ void __launch_bounds__(256, 2)
mma_gemm(const __half* __restrict__ A, const __half* __restrict__ B,
         const float* __restrict__ bias, const float* __restrict__ resid,
         float* __restrict__ C, __half* __restrict__ Ch,
         __half* __restrict__ Pk, __half* __restrict__ Pv,
         int M, int N, int K)
{
    extern __shared__ __align__(1024) char dsm[];
    uint32_t dyn = s2u(dsm);

    int tid = threadIdx.x;
    int wid = tid >> 5, lane = tid & 31;
    int wm = wid & 1, wn = wid >> 1;
    int m0 = blockIdx.y * GBM, n0 = blockIdx.x * GBN;

    float c[4][4][4];
#pragma unroll
    for (int i = 0; i < 4; i++)
#pragma unroll
        for (int j = 0; j < 4; j++)
#pragma unroll
            for (int q = 0; q < 4; q++) c[i][j][q] = 0.f;

    int aRow0 = wm * 64 + (lane & 7) + ((lane >> 3) & 1) * 8;
    int bRow0 = wn * 32 + (lane & 7) + ((lane >> 3) & 1) * 8;
    int cgrp = lane >> 4;

    int nsteps = K / GBK;
    load_stage64(dyn, A, B, m0, n0, 0, K, tid);
    cp_commit();
    load_stage64(dyn + STAGE_B, A, B, m0, n0, GBK, K, tid);
    cp_commit();

    int buf = 0;
    for (int step = 0; step < nsteps; step++) {
        if (step < nsteps - 1) cp_wait<1>(); else cp_wait<0>();
        __syncthreads();
        if (step + 2 < nsteps) {
            int nb = buf + 2; if (nb >= 3) nb -= 3;
            load_stage64(dyn + (uint32_t)nb * STAGE_B, A, B,
                         m0, n0, (step + 2) * GBK, K, tid);
            cp_commit();
        }
        uint32_t sb = dyn + (uint32_t)buf * STAGE_B;

#pragma unroll
        for (int s = 0; s < 4; s++) {
            int ch = 2 * s + cgrp;
            uint32_t ah[4][4];
#pragma unroll
            for (int i = 0; i < 4; i++) {
                int row = aRow0 + i * 16;
                ldm4(ah[i], sb + SOFF_A + row * 128 + ((ch ^ (row & 7)) << 4));
            }
            uint32_t bh[2][4];
#pragma unroll
            for (int g = 0; g < 2; g++) {
                int row = bRow0 + g * 16;
                ldm4(bh[g], sb + SOFF_B + row * 128 + ((ch ^ (row & 7)) << 4));
            }
#pragma unroll
            for (int i = 0; i < 4; i++) {
#pragma unroll
                for (int j = 0; j < 4; j++) {
                    int g = j >> 1, o = j & 1;
                    mma16816(c[i][j], ah[i], bh[g][o], bh[g][o + 2]);
                }
            }
        }
        buf++; if (buf >= 3) buf = 0;
    }

    // ----------------- epilogue -----------------
    int rbase = m0 + wm * 64 + (lane >> 2);
    int cbase = n0 + wn * 32 + (lane & 3) * 2;
#pragma unroll
    for (int i = 0; i < 4; i++) {
#pragma unroll
        for (int j = 0; j < 4; j++) {
            int col = cbase + j * 8;
            float bs0 = bias[col], bs1 = bias[col + 1];
#pragma unroll
            for (int half = 0; half < 2; half++) {
                int r = rbase + i * 16 + half * 8;
                float v0 = c[i][j][half * 2]     + bs0;
                float v1 = c[i][j][half * 2 + 1] + bs1;
                if (EPI == 1) {
                    v0 = fmaxf(v0, 0.f);
                    v1 = fmaxf(v1, 0.f);
                    *(uint32_t*)(Ch + (size_t)r * N + col) = hpk2(v0, v1);
                } else if (EPI == 2) {
                    float2 rr = *(const float2*)(resid + (size_t)r * N + col);
                    float2 o; o.x = v0 + rr.x; o.y = v1 + rr.y;
                    *(float2*)(C + (size_t)r * N + col) = o;
                } else {  // EPI == 3: fused QKV
                    int t  = col >> 10;        // 0=q,1=k,2=v
                    int c2 = col & 1023;
                    int h = c2 >> 6, d = c2 & 63;
                    int bb = r >> 11, sx = r & 2047;
                    size_t idx = (((size_t)bb * NHEAD + h) * SEQ + sx) * DK + d;
                    if (t == 0) {
                        *(uint32_t*)(Ch + idx) = hpk2(v0 * 0.125f, v1 * 0.125f);
                    } else if (t == 1) {
                        *(uint32_t*)(Pk + idx) = hpk2(v0, v1);
                    } else {
                        *(uint32_t*)(Pv + idx) = hpk2(v0, v1);
                    }
                }
            }
        }
    }
}

// ---------------------------------------------------------------------------
// HMMA flash attention, fp16. 128 q-rows/block, 8 warps, 64-key stages,
// 3-stage cp.async pipeline, ONE barrier per iteration, 2 CTAs/SM.
// ---------------------------------------------------------------------------
#define AQ 0
#define ASTG 16384
#define ASTRIDE 16384
#define AK 0
#define AV 8192
#define AMSK (16384 + 3 * 16384)
#define ATT_SMEM (AMSK + 3 * 256 + 256)

__device__ __forceinline__ void attn_load_kv(
    uint32_t base, int buf, const __half* Kp, const __half* Vp,
    const int* mp, int k0, int tid)
{
    uint32_t sb = base + ASTG + (uint32_t)buf * ASTRIDE;
#pragma unroll
    for (int r = 0; r < 2; r++) {
        int ci = tid + r * 256;
        int row = ci >> 3, ch = ci & 7;
        uint32_t sw = (uint32_t)(row * 128 + ((ch ^ (row & 7)) << 4));
        size_t go = (size_t)(k0 + row) * DK + ch * 8;
        cpa16(sb + AK + sw, Kp + go);
        cpa16(sb + AV + sw, Vp + go);
    }
    if (tid < 16)
        cpa16(base + AMSK + (uint32_t)buf * 256 + tid * 16, mp + k0 + tid * 4);
}

__global__ void __launch_bounds__(256, 2) attn_mma_kernel(
    const __half* __restrict__ Qg, const __half* __restrict__ Kg,
    const __half* __restrict__ Vg, const int* __restrict__ mask,
    __half* __restrict__ O)
{
    extern __shared__ __align__(1024) char attsm[];
    uint32_t base = s2u(attsm);

    int tid = threadIdx.x;
    int wid = tid >> 5, lane = tid & 31;
    int bh = blockIdx.y;
    int b = bh >> 4, hh = bh & 15;
    int q0 = blockIdx.x * 128;

    const __half* Qp = Qg + ((size_t)bh * SEQ + q0) * DK;
    const __half* Kp = Kg + (size_t)bh * SEQ * DK;
    const __half* Vp = Vg + (size_t)bh * SEQ * DK;
    const int* mp = mask + b * SEQ;

#pragma unroll
    for (int r = 0; r < 4; r++) {
        int ci = tid + r * 256;
        int row = ci >> 3, ch = ci & 7;
        uint32_t sw = (uint32_t)(row * 128 + ((ch ^ (row & 7)) << 4));
        cpa16(base + AQ + sw, Qp + (size_t)row * DK + ch * 8);
    }
    attn_load_kv(base, 0, Kp, Vp, mp, 0, tid);
    cp_commit();
    attn_load_kv(base, 1, Kp, Vp, mp, 64, tid);
    cp_commit();

    uint32_t qh[4][4];
    float m0v = -INFINITY, m1v = -INFINITY, l0v = 0.f, l1v = 0.f;
    float o_[8][4];
#pragma unroll
    for (int j = 0; j < 8; j++)
#pragma unroll
        for (int q = 0; q < 4; q++) o_[j][q] = 0.f;

    const int NKB = SEQ / 64;   // 32
    int buf = 0;
    for (int t = 0; t < NKB; t++) {
        if (t < NKB - 1) cp_wait<1>(); else cp_wait<0>();
        __syncthreads();
        if (t + 2 < NKB) {
            int nb = buf + 2; if (nb >= 3) nb -= 3;
            attn_load_kv(base, nb, Kp, Vp, mp, (t + 2) * 64, tid);
            cp_commit();
        }

        if (t == 0) {
#pragma unroll
            for (int c2 = 0; c2 < 4; c2++) {
                int row = wid * 16 + (lane & 15);
                int ch = 2 * c2 + (lane >> 4);
                ldm4(qh[c2], base + AQ + row * 128 + ((ch ^ (row & 7)) << 4));
            }
        }

        uint32_t sb = base + ASTG + (uint32_t)buf * ASTRIDE;

        float sc[8][4];
#pragma unroll
        for (int j = 0; j < 8; j++)
#pragma unroll
            for (int q = 0; q < 4; q++) sc[j][q] = 0.f;
#pragma unroll
        for (int c2 = 0; c2 < 4; c2++) {
            uint32_t kh[4][4];
#pragma unroll
            for (int g = 0; g < 4; g++) {
                int row = g * 16 + (lane & 7) + ((lane >> 3) & 1) * 8;
                int ch = 2 * c2 + (lane >> 4);
                ldm4(kh[g], sb + AK + row * 128 + ((ch ^ (row & 7)) << 4));
            }
#pragma unroll
            for (int j = 0; j < 8; j++) {
                int g = j >> 1, o = j & 1;
                mma16816(sc[j], qh[c2], kh[g][o], kh[g][o + 2]);
            }
        }

        const int* msk = (const int*)(attsm + AMSK - s2u(attsm) + base) +
                         (buf * 64);
        // (attsm + AMSK offset) — use direct smem pointer arithmetic:
        msk = (const int*)(attsm + (AMSK - 0) + buf * 256);
        int cc = (lane & 3) * 2;
#pragma unroll
        for (int j = 0; j < 8; j++) {
            int mv0 = msk[j * 8 + cc], mv1 = msk[j * 8 + cc + 1];
            if (mv0 == 0) { sc[j][0] = -1e9f; sc[j][2] = -1e9f; }
            if (mv1 == 0) { sc[j][1] = -1e9f; sc[j][3] = -1e9f; }
        }

        float mx0 = -INFINITY, mx1 = -INFINITY;
#pragma unroll
        for (int j = 0; j < 8; j++) {
            mx0 = fmaxf(mx0, fmaxf(sc[j][0], sc[j][1]));
            mx1 = fmaxf(mx1, fmaxf(sc[j][2], sc[j][3]));
        }
        mx0 = fmaxf(mx0, __shfl_xor_sync(0xffffffffu, mx0, 1));
        mx0 = fmaxf(mx0, __shfl_xor_sync(0xffffffffu, mx0, 2));
        mx1 = fmaxf(mx1, __shfl_xor_sync(0xffffffffu, mx1, 1));
        mx1 = fmaxf(mx1, __shfl_xor_sync(0xffffffffu, mx1, 2));
        float mn0 = fmaxf(m0v, mx0), mn1 = fmaxf(m1v, mx1);
        float cor0 = __expf(m0v - mn0), cor1 = __expf(m1v - mn1);

        // packed P aliases sc registers
        float sum0 = 0.f, sum1 = 0.f;
        uint32_t* pkd = (uint32_t*)sc;
#pragma unroll
        for (int j = 0; j < 8; j++) {
            float p0 = __expf(sc[j][0] - mn0);
            float p1 = __expf(sc[j][1] - mn0);
            float p2 = __expf(sc[j][2] - mn1);
            float p3 = __expf(sc[j][3] - mn1);
            sum0 += p0 + p1; sum1 += p2 + p3;
            uint32_t h01 = hpk2(p0, p1);
            uint32_t h23 = hpk2(p2, p3);
            pkd[j * 2 + 0] = h01;
            pkd[j * 2 + 1] = h23;
        }
        sum0 += __shfl_xor_sync(0xffffffffu, sum0, 1);
        sum0 += __shfl_xor_sync(0xffffffffu, sum0, 2);
        sum1 += __shfl_xor_sync(0xffffffffu, sum1, 1);
        sum1 += __shfl_xor_sync(0xffffffffu, sum1, 2);
        l0v = l0v * cor0 + sum0;
        l1v = l1v * cor1 + sum1;
        m0v = mn0; m1v = mn1;
#pragma unroll
        for (int j = 0; j < 8; j++) {
            o_[j][0] *= cor0; o_[j][1] *= cor0;
            o_[j][2] *= cor1; o_[j][3] *= cor1;
        }

#pragma unroll
        for (int t2 = 0; t2 < 4; t2++) {
            uint32_t pa[4] = { pkd[(2*t2)*2 + 0], pkd[(2*t2)*2 + 1],
                               pkd[(2*t2+1)*2 + 0], pkd[(2*t2+1)*2 + 1] };
            uint32_t vh[4][4];
#pragma unroll
            for (int g = 0; g < 4; g++) {
                int row = t2 * 16 + (lane & 7) + ((lane >> 3) & 1) * 8;
                int ch = 2 * g + (lane >> 4);
                ldm4t(vh[g], sb + AV + row * 128 + ((ch ^ (row & 7)) << 4));
            }
#pragma unroll
            for (int j = 0; j < 8; j++) {
                int g = j >> 1, h2 = j & 1;
                mma16816(o_[j], pa, vh[g][2*h2], vh[g][2*h2 + 1]);
            }
        }
        buf++; if (buf >= 3) buf = 0;
    }

    float il0 = 1.0f / l0v, il1 = 1.0f / l1v;
    size_t row0 = (size_t)b * SEQ + q0 + wid * 16 + (lane >> 2);
    size_t row1 = row0 + 8;
    int cb = hh * DK + (lane & 3) * 2;
#pragma unroll
    for (int j = 0; j < 8; j++) {
        int col = cb + j * 8;
        *(uint32_t*)(O + row0 * DMODEL + col) =
            hpk2(o_[j][0] * il0, o_[j][1] * il0);
        *(uint32_t*)(O + row1 * DMODEL + col) =
            hpk2(o_[j][2] * il1, o_[j][3] * il1);
    }
}

// ---------------------------------------------------------------------------
extern "C" void kernel_launch(void* const* d_in, const int* in_sizes, int n_in,
                              void* d_out, int out_size)
{
    const float* x      = (const float*)d_in[0];
    const int*   mask   = (const int*)  d_in[1];
    const float* wq     = (const float*)d_in[2];
    const float* bq     = (const float*)d_in[3];
    const float* wk     = (const float*)d_in[4];
    const float* bk     = (const float*)d_in[5];
    const float* wv     = (const float*)d_in[6];
    const float* bv     = (const float*)d_in[7];
    const float* wo     = (const float*)d_in[8];
    const float* bo     = (const float*)d_in[9];
    const float* w1     = (const float*)d_in[10];
    const float* b1     = (const float*)d_in[11];
    const float* w2     = (const float*)d_in[12];
    const float* b2     = (const float*)d_in[13];
    const float* alpha1 = (const float*)d_in[14];
    const float* bias1  = (const float*)d_in[15];
    const float* alpha2 = (const float*)d_in[16];
    const float* bias2  = (const float*)d_in[17];
    float* out = (float*)d_out;

    __half *x2, *at, *ff, *qq, *kk, *vv, *wqkv, *wop, *w1p, *w2p;
    float *pxr, *bqkv;
    cudaGetSymbolAddress((void**)&x2, g_x2);
    cudaGetSymbolAddress((void**)&at, g_at);
    cudaGetSymbolAddress((void**)&ff, g_ff);
    cudaGetSymbolAddress((void**)&qq, g_q);
    cudaGetSymbolAddress((void**)&kk, g_k);
    cudaGetSymbolAddress((void**)&vv, g_v);
    cudaGetSymbolAddress((void**)&wqkv, g_wqkv);
    cudaGetSymbolAddress((void**)&wop, g_wo);
    cudaGetSymbolAddress((void**)&w1p, g_w1);
    cudaGetSymbolAddress((void**)&w2p, g_w2);
    cudaGetSymbolAddress((void**)&pxr, g_xr);
    cudaGetSymbolAddress((void**)&bqkv, g_bqkv);

    cudaFuncSetAttribute(attn_mma_kernel,
                         cudaFuncAttributeMaxDynamicSharedMemorySize, ATT_SMEM);
    cudaFuncSetAttribute(mma_gemm<1>,
                         cudaFuncAttributeMaxDynamicSharedMemorySize, GEMM_SMEM);
    cudaFuncSetAttribute(mma_gemm<2>,
                         cudaFuncAttributeMaxDynamicSharedMemorySize, GEMM_SMEM);
    cudaFuncSetAttribute(mma_gemm<3>,
                         cudaFuncAttributeMaxDynamicSharedMemorySize, GEMM_SMEM);

    convw_all<<<12288, dim3(32, 8)>>>(wq, wk, wv, wo, w1, w2, bq, bk, bv,
                                      wqkv, wop, w1p, w2p, bqkv);
    norm_h_kernel<<<NTOK, 256>>>(x, alpha1, bias1, x2);
    mma_gemm<3><<<dim3(3 * DMODEL / GBN, NTOK / GBM), 256, GEMM_SMEM>>>(
        x2, wqkv, bqkv, nullptr, nullptr, qq, kk, vv, NTOK, 3 * DMODEL, DMODEL);
    attn_mma_kernel<<<dim3(SEQ / 128, BATCH * NHEAD), 256, ATT_SMEM>>>(
        qq, kk, vv, mask, at);
    mma_gemm<2><<<dim3(DMODEL / GBN, NTOK / GBM), 256, GEMM_SMEM>>>(
        at, wop, bo, x, pxr, nullptr, nullptr, nullptr, NTOK, DMODEL, DMODEL);
    norm_h_kernel<<<NTOK, 256>>>(pxr, alpha2, bias2, x2);
    mma_gemm<1><<<dim3(DFF / GBN, NTOK / GBM), 256, GEMM_SMEM>>>(
        x2, w1p, b1, nullptr, nullptr, ff, nullptr, nullptr, NTOK, DFF, DMODEL);
    mma_gemm<2><<<dim3(DMODEL / GBN, NTOK / GBM), 256, GEMM_SMEM>>>(
        ff, w2p, b2, pxr, out, nullptr, nullptr, nullptr, NTOK, DMODEL, DFF);
}